// round 5
// baseline (speedup 1.0000x reference)
#include <cuda_runtime.h>
#include <cuda_bf16.h>
#include <math.h>
#include <stdint.h>

// ---------------------------------------------------------------------------
// MoE top-2/8: router -> permuted expert segments -> two tf32 mma.sync GEMMs.
// Pre-rounded K-major-N weight scratch; 3-stage cp.async pipeline, 1 sync/chunk.
// ---------------------------------------------------------------------------

#define BATCH      8192
#define D_MODEL    1024
#define HIDDEN     4096
#define NUM_CLS    1000
#define N2PAD      1024
#define NUM_EXP    8
#define TOPK       2
#define NPAIR      (BATCH * TOPK)
#define MAX_TILES  136
#define CAP        (MAX_TILES * 128)

// ---------------- scratch ---------------------------------------------------
__device__ float g_h[(size_t)CAP * HIDDEN];                    // tf32-rounded
__device__ float g_xR[(size_t)BATCH * D_MODEL];                // tf32-rounded x
__device__ float g_W1R[(size_t)NUM_EXP * D_MODEL * HIDDEN];    // tf32 [e][k][n]
__device__ float g_W2R[(size_t)NUM_EXP * HIDDEN * N2PAD];      // tf32 padded
__device__ float g_gates[BATCH * NUM_EXP];
__device__ int   g_topi[BATCH * TOPK];
__device__ int   g_pairExpert[NPAIR];
__device__ float g_pairGate[NPAIR];
__device__ int   g_counts[NUM_EXP];
__device__ int   g_segbase[NUM_EXP + 1];
__device__ int   g_cursor[NUM_EXP];
__device__ int   g_permToken[CAP];
__device__ int   g_permPair[CAP];
__device__ float g_permGate[CAP];

__device__ __forceinline__ float tf32r(float x) {
    uint32_t o; asm("cvt.rna.tf32.f32 %0, %1;" : "=r"(o) : "f"(x));
    return __uint_as_float(o);
}
__device__ __forceinline__ float gelu_exact(float v) {
    return 0.5f * v * (1.0f + erff(v * 0.70710678118654752f));
}
__device__ __forceinline__ uint32_t smem_u32(const void* p) {
    uint32_t a;
    asm("{ .reg .u64 t; cvta.to.shared.u64 t, %1; cvt.u32.u64 %0, t; }" : "=r"(a) : "l"(p));
    return a;
}

#define CPA16(dst, src)        asm volatile("cp.async.ca.shared.global [%0], [%1], 16;" :: "r"(dst), "l"(src))
#define CPA16_SZ(dst, src, sz) asm volatile("cp.async.ca.shared.global [%0], [%1], 16, %2;" :: "r"(dst), "l"(src), "r"(sz))
#define CPA_COMMIT()           asm volatile("cp.async.commit_group;" ::: "memory")
#define CPA_WAIT1()            asm volatile("cp.async.wait_group 1;" ::: "memory")
#define CPA_WAIT0()            asm volatile("cp.async.wait_group 0;" ::: "memory")

__device__ __forceinline__ void mma_tf32(float* c, const uint32_t* a, const uint32_t* b) {
    asm volatile("mma.sync.aligned.m16n8k8.row.col.f32.tf32.tf32.f32 "
                 "{%0,%1,%2,%3}, {%4,%5,%6,%7}, {%8,%9}, {%0,%1,%2,%3};"
                 : "+f"(c[0]), "+f"(c[1]), "+f"(c[2]), "+f"(c[3])
                 : "r"(a[0]), "r"(a[1]), "r"(a[2]), "r"(a[3]), "r"(b[0]), "r"(b[1]));
}

// ---------------- prep: tf32 rounding ---------------------------------------
__global__ void round_x(const float* __restrict__ x) {
    size_t n4 = (size_t)BATCH * D_MODEL / 4;
    for (size_t i = blockIdx.x * blockDim.x + threadIdx.x; i < n4; i += (size_t)gridDim.x * blockDim.x) {
        float4 v = ((const float4*)x)[i];
        v.x = tf32r(v.x); v.y = tf32r(v.y); v.z = tf32r(v.z); v.w = tf32r(v.w);
        ((float4*)g_xR)[i] = v;
    }
}
__global__ void round_w1(const float* __restrict__ W1) {
    size_t n4 = (size_t)NUM_EXP * D_MODEL * HIDDEN / 4;
    for (size_t i = blockIdx.x * blockDim.x + threadIdx.x; i < n4; i += (size_t)gridDim.x * blockDim.x) {
        float4 v = ((const float4*)W1)[i];
        v.x = tf32r(v.x); v.y = tf32r(v.y); v.z = tf32r(v.z); v.w = tf32r(v.w);
        ((float4*)g_W1R)[i] = v;
    }
}
__global__ void round_w2(const float* __restrict__ W2) {
    size_t rows = (size_t)NUM_EXP * HIDDEN;
    for (size_t i = blockIdx.x * blockDim.x + threadIdx.x; i < rows * N2PAD; i += (size_t)gridDim.x * blockDim.x) {
        size_t r = i / N2PAD; int n = (int)(i % N2PAD);
        g_W2R[i] = (n < NUM_CLS) ? tf32r(W2[r * NUM_CLS + n]) : 0.f;
    }
}

// ---------------- routing ----------------------------------------------------
__global__ void init_kernel() {
    int i = blockIdx.x * blockDim.x + threadIdx.x;
    if (i < CAP) { g_permToken[i] = -1; g_permPair[i] = -1; }
    if (i < NUM_EXP) g_counts[i] = 0;
}

__global__ void router_kernel(const float* __restrict__ x,
                              const float* __restrict__ Wg,
                              const float* __restrict__ bg) {
    int gwarp = (blockIdx.x * blockDim.x + threadIdx.x) >> 5;
    int lane  = threadIdx.x & 31;
    if (gwarp >= BATCH) return;
    const float* xr = x + (size_t)gwarp * D_MODEL;
    float acc[NUM_EXP];
#pragma unroll
    for (int e = 0; e < NUM_EXP; e++) acc[e] = 0.f;
    for (int k0 = lane * 4; k0 < D_MODEL; k0 += 128) {
        float4 xv = *(const float4*)(xr + k0);
        const float* xs = (const float*)&xv;
#pragma unroll
        for (int kk = 0; kk < 4; kk++) {
            const float4* wg = (const float4*)(Wg + (size_t)(k0 + kk) * NUM_EXP);
            float4 w0 = wg[0], w1 = wg[1];
            float xk = xs[kk];
            acc[0] += xk * w0.x; acc[1] += xk * w0.y;
            acc[2] += xk * w0.z; acc[3] += xk * w0.w;
            acc[4] += xk * w1.x; acc[5] += xk * w1.y;
            acc[6] += xk * w1.z; acc[7] += xk * w1.w;
        }
    }
#pragma unroll
    for (int off = 16; off; off >>= 1)
#pragma unroll
        for (int e = 0; e < NUM_EXP; e++)
            acc[e] += __shfl_xor_sync(0xFFFFFFFFu, acc[e], off);
    if (lane == 0) {
        float v[NUM_EXP];
#pragma unroll
        for (int e = 0; e < NUM_EXP; e++) v[e] = acc[e] + bg[e];
        int i1 = 0;
#pragma unroll
        for (int e = 1; e < NUM_EXP; e++) if (v[e] > v[i1]) i1 = e;
        int i2 = -1;
#pragma unroll
        for (int e = 0; e < NUM_EXP; e++)
            if (e != i1 && (i2 < 0 || v[e] > v[i2])) i2 = e;
        float e2 = expf(v[i2] - v[i1]);
        float g1 = 1.f / (1.f + e2), g2 = e2 / (1.f + e2);
#pragma unroll
        for (int e = 0; e < NUM_EXP; e++) g_gates[gwarp * NUM_EXP + e] = 0.f;
        g_gates[gwarp * NUM_EXP + i1] = g1;
        g_gates[gwarp * NUM_EXP + i2] = g2;
        g_topi[gwarp * TOPK + 0] = i1;
        g_topi[gwarp * TOPK + 1] = i2;
        g_pairExpert[gwarp * TOPK + 0] = i1;
        g_pairExpert[gwarp * TOPK + 1] = i2;
        g_pairGate[gwarp * TOPK + 0] = g1;
        g_pairGate[gwarp * TOPK + 1] = g2;
        atomicAdd(&g_counts[i1], 1);
        atomicAdd(&g_counts[i2], 1);
    }
}

__global__ void scan_kernel() {
    int base = 0;
#pragma unroll
    for (int e = 0; e < NUM_EXP; e++) {
        g_segbase[e] = base;
        g_cursor[e]  = base;
        base += ((g_counts[e] + 127) >> 7) << 7;
    }
    g_segbase[NUM_EXP] = base;
}

__global__ void scatter_kernel() {
    int p = blockIdx.x * blockDim.x + threadIdx.x;
    if (p >= NPAIR) return;
    int e = g_pairExpert[p];
    int pos = atomicAdd(&g_cursor[e], 1);
    g_permToken[pos] = p >> 1;
    g_permPair[pos]  = p;
    g_permGate[pos]  = g_pairGate[p];
}

// ---------------- tf32 mma GEMMs --------------------------------------------
// CTA: 256 thr (8 warps 2Mx4N), tile 128x128, BK=32, 3-stage, one sync/chunk.
#define AS_STRIDE 36
#define BS_STRIDE 136
#define AS_BYTES  (128 * AS_STRIDE * 4)            // 18432
#define BS_BYTES  (32 * BS_STRIDE * 4)             // 17408
#define STAGE_B   (AS_BYTES + BS_BYTES)            // 35840
#define NSTAGE    3
#define SMEM_TOT  (NSTAGE * STAGE_B)               // 107520

__device__ __forceinline__ void issue_chunk(uint32_t aDst, uint32_t bDst,
                                            const float* aSrc, const float* bSrc,
                                            int bStrideN, uint32_t aSz, int kt) {
#pragma unroll
    for (int j = 0; j < 4; j++)
        CPA16_SZ(aDst + j * 16, aSrc + kt + j * 4, aSz);
#pragma unroll
    for (int j = 0; j < 4; j++)
        CPA16(bDst + j * 16, bSrc + (size_t)kt * bStrideN + j * 4);
    CPA_COMMIT();
}

__device__ __forceinline__ void mma_tile(const float* As, const float* Bs,
                                         int wr, int wc, int gid, int tig,
                                         float c[4][4][4]) {
#pragma unroll
    for (int ks = 0; ks < 4; ks++) {
        uint32_t b[4][2];
#pragma unroll
        for (int ni = 0; ni < 4; ni++) {
            int col = wc + ni * 8 + gid;
            b[ni][0] = __float_as_uint(Bs[(ks * 8 + tig) * BS_STRIDE + col]);
            b[ni][1] = __float_as_uint(Bs[(ks * 8 + tig + 4) * BS_STRIDE + col]);
        }
#pragma unroll
        for (int mi = 0; mi < 4; mi++) {
            int r0 = wr + mi * 16 + gid;
            uint32_t a[4];
            a[0] = __float_as_uint(As[r0 * AS_STRIDE + ks * 8 + tig]);
            a[1] = __float_as_uint(As[(r0 + 8) * AS_STRIDE + ks * 8 + tig]);
            a[2] = __float_as_uint(As[r0 * AS_STRIDE + ks * 8 + tig + 4]);
            a[3] = __float_as_uint(As[(r0 + 8) * AS_STRIDE + ks * 8 + tig + 4]);
#pragma unroll
            for (int ni = 0; ni < 4; ni++) mma_tf32(c[mi][ni], a, b[ni]);
        }
    }
}

// 3-stage mainloop: one __syncthreads per chunk.
__device__ __forceinline__ void gemm_mainloop(uint32_t aDst0, uint32_t bDst0,
                                              const float* aSrc, const float* bSrc,
                                              int bStrideN, uint32_t aSz,
                                              char* smem, int NIT,
                                              int wr, int wc, int gid, int tig,
                                              float c[4][4][4]) {
    issue_chunk(aDst0,           bDst0,           aSrc, bSrc, bStrideN, aSz, 0);
    issue_chunk(aDst0 + STAGE_B, bDst0 + STAGE_B, aSrc, bSrc, bStrideN, aSz, 32);
    int buf = 0, nxt = 2;
    for (int it = 0; it < NIT; ++it) {
        if (it + 1 < NIT) CPA_WAIT1(); else CPA_WAIT0();
        __syncthreads();
        if (it + 2 < NIT)
            issue_chunk(aDst0 + nxt * STAGE_B, bDst0 + nxt * STAGE_B,
                        aSrc, bSrc, bStrideN, aSz, (it + 2) * 32);
        mma_tile((const float*)(smem + buf * STAGE_B),
                 (const float*)(smem + buf * STAGE_B + AS_BYTES),
                 wr, wc, gid, tig, c);
        buf = (buf == NSTAGE - 1) ? 0 : buf + 1;
        nxt = (nxt == NSTAGE - 1) ? 0 : nxt + 1;
    }
}

__global__ __launch_bounds__(256, 2)
void gemm1_mma(const float* __restrict__ b1) {
    extern __shared__ __align__(16) char smem[];
    const int tid = threadIdx.x, wid = tid >> 5, lane = tid & 31;
    const int rowBase = blockIdx.x * 128, nBase = blockIdx.y * 128;
    if (rowBase >= g_segbase[NUM_EXP]) return;
    int expert = 0;
#pragma unroll
    for (int i = 1; i < NUM_EXP; i++) if (g_segbase[i] <= rowBase) expert = i;

    uint32_t sb = smem_u32(smem);
    const int am = tid >> 1, ak = (tid & 1) * 16;
    const int bk = tid >> 3, bn = (tid & 7) * 16;
    uint32_t aDst0 = sb + (am * AS_STRIDE + ak) * 4;
    uint32_t bDst0 = sb + AS_BYTES + (bk * BS_STRIDE + bn) * 4;

    const int tok = g_permToken[rowBase + am];
    const float* aSrc = g_xR + (size_t)(tok < 0 ? 0 : tok) * D_MODEL + ak;
    uint32_t aSz = tok < 0 ? 0u : 16u;
    const float* bSrc = g_W1R + (size_t)expert * D_MODEL * HIDDEN + (size_t)bk * HIDDEN + nBase + bn;

    const int gid = lane >> 2, tig = lane & 3;
    const int wr = (wid >> 2) * 64, wc = (wid & 3) * 32;
    float c[4][4][4];
#pragma unroll
    for (int mi = 0; mi < 4; mi++)
#pragma unroll
        for (int ni = 0; ni < 4; ni++)
#pragma unroll
            for (int q = 0; q < 4; q++) c[mi][ni][q] = 0.f;

    gemm_mainloop(aDst0, bDst0, aSrc, bSrc, HIDDEN, aSz, smem, D_MODEL / 32,
                  wr, wc, gid, tig, c);

    const float* bb = b1 + (size_t)expert * HIDDEN + nBase;
#pragma unroll
    for (int mi = 0; mi < 4; mi++) {
        int r0 = rowBase + wr + mi * 16 + gid;
#pragma unroll
        for (int ni = 0; ni < 4; ni++) {
            int col = wc + ni * 8 + tig * 2;
            float bias0 = __ldg(bb + col), bias1 = __ldg(bb + col + 1);
            float2 v0, v1;
            v0.x = tf32r(gelu_exact(c[mi][ni][0] + bias0));
            v0.y = tf32r(gelu_exact(c[mi][ni][1] + bias1));
            v1.x = tf32r(gelu_exact(c[mi][ni][2] + bias0));
            v1.y = tf32r(gelu_exact(c[mi][ni][3] + bias1));
            *(float2*)(g_h + (size_t)r0 * HIDDEN + nBase + col) = v0;
            *(float2*)(g_h + (size_t)(r0 + 8) * HIDDEN + nBase + col) = v1;
        }
    }
}

__global__ __launch_bounds__(256, 2)
void gemm2_mma(const float* __restrict__ b2, float* __restrict__ out) {
    extern __shared__ __align__(16) char smem[];
    const int tid = threadIdx.x, wid = tid >> 5, lane = tid & 31;
    const int rowBase = blockIdx.x * 128, nBase = blockIdx.y * 128;
    if (rowBase >= g_segbase[NUM_EXP]) return;
    int expert = 0;
#pragma unroll
    for (int i = 1; i < NUM_EXP; i++) if (g_segbase[i] <= rowBase) expert = i;

    uint32_t sb = smem_u32(smem);
    const int am = tid >> 1, ak = (tid & 1) * 16;
    const int bk = tid >> 3, bn = (tid & 7) * 16;
    uint32_t aDst0 = sb + (am * AS_STRIDE + ak) * 4;
    uint32_t bDst0 = sb + AS_BYTES + (bk * BS_STRIDE + bn) * 4;

    const float* aSrc = g_h + (size_t)(rowBase + am) * HIDDEN + ak;
    const float* bSrc = g_W2R + (size_t)expert * HIDDEN * N2PAD + (size_t)bk * N2PAD + nBase + bn;

    const int gid = lane >> 2, tig = lane & 3;
    const int wr = (wid >> 2) * 64, wc = (wid & 3) * 32;
    float c[4][4][4];
#pragma unroll
    for (int mi = 0; mi < 4; mi++)
#pragma unroll
        for (int ni = 0; ni < 4; ni++)
#pragma unroll
            for (int q = 0; q < 4; q++) c[mi][ni][q] = 0.f;

    gemm_mainloop(aDst0, bDst0, aSrc, bSrc, N2PAD, 16u, smem, HIDDEN / 32,
                  wr, wc, gid, tig, c);

    const float* bb = b2 + (size_t)expert * NUM_CLS;
#pragma unroll
    for (int mi = 0; mi < 4; mi++) {
        int r0 = rowBase + wr + mi * 16 + gid;
#pragma unroll
        for (int half = 0; half < 2; half++) {
            int r = r0 + half * 8;
            int pair = g_permPair[r];
            if (pair < 0) continue;
            float gate = g_permGate[r];
            float* orow = out + (size_t)(pair >> 1) * NUM_CLS;
#pragma unroll
            for (int ni = 0; ni < 4; ni++) {
                int col = nBase + wc + ni * 8 + tig * 2;
                if (col < NUM_CLS)
                    atomicAdd(orow + col, gate * (c[mi][ni][half * 2 + 0] + __ldg(bb + col)));
                if (col + 1 < NUM_CLS)
                    atomicAdd(orow + col + 1, gate * (c[mi][ni][half * 2 + 1] + __ldg(bb + col + 1)));
            }
        }
    }
}

// ---------------- tail -------------------------------------------------------
__global__ void tail_kernel(float* __restrict__ out, int out_size) {
    int i = blockIdx.x * blockDim.x + threadIdx.x;
    const int OUT0 = BATCH * NUM_CLS;
    if (out_size >= OUT0 + BATCH * NUM_EXP) {
        if (i < BATCH * NUM_EXP)
            out[OUT0 + i] = g_gates[i];
        if (out_size >= OUT0 + BATCH * NUM_EXP + BATCH * TOPK && i < BATCH * TOPK)
            out[OUT0 + BATCH * NUM_EXP + i] = (float)g_topi[i];
    }
}

// ---------------------------------------------------------------------------
extern "C" void kernel_launch(void* const* d_in, const int* in_sizes, int n_in,
                              void* d_out, int out_size) {
    const float* x  = (const float*)d_in[0];
    const float* Wg = (const float*)d_in[1];
    const float* bg = (const float*)d_in[2];
    const float* W1 = (const float*)d_in[3];
    const float* b1 = (const float*)d_in[4];
    const float* W2 = (const float*)d_in[5];
    const float* b2 = (const float*)d_in[6];
    float* out = (float*)d_out;

    cudaFuncSetAttribute(gemm1_mma, cudaFuncAttributeMaxDynamicSharedMemorySize, SMEM_TOT);
    cudaFuncSetAttribute(gemm2_mma, cudaFuncAttributeMaxDynamicSharedMemorySize, SMEM_TOT);

    cudaMemsetAsync(d_out, 0, (size_t)out_size * sizeof(float));
    init_kernel<<<(CAP + 255) / 256, 256>>>();
    round_x<<<512, 256>>>(x);
    round_w1<<<2048, 256>>>(W1);
    round_w2<<<2048, 256>>>(W2);
    router_kernel<<<BATCH / 8, 256>>>(x, Wg, bg);
    scan_kernel<<<1, 1>>>();
    scatter_kernel<<<(NPAIR + 255) / 256, 256>>>();
    gemm1_mma<<<dim3(MAX_TILES, HIDDEN / 128), 256, SMEM_TOT>>>(b1);
    gemm2_mma<<<dim3(MAX_TILES, N2PAD / 128), 256, SMEM_TOT>>>(b2, out);
    tail_kernel<<<(BATCH * NUM_EXP + 255) / 256, 256>>>(out, out_size);
}

// round 6
// speedup vs baseline: 1.1345x; 1.1345x over previous
#include <cuda_runtime.h>
#include <cuda_bf16.h>
#include <math.h>
#include <stdint.h>

// ---------------------------------------------------------------------------
// MoE top-2/8: router -> permuted expert segments -> two tf32 mma.sync GEMMs.
// R3-proven 2-stage mainloop; preamble fused so gemm1 is ncu's captured launch.
// ---------------------------------------------------------------------------

#define BATCH      8192
#define D_MODEL    1024
#define HIDDEN     4096
#define NUM_CLS    1000
#define N2PAD      1024
#define NUM_EXP    8
#define TOPK       2
#define NPAIR      (BATCH * TOPK)
#define MAX_TILES  136
#define CAP        (MAX_TILES * 128)

// ---------------- scratch ---------------------------------------------------
__device__ float g_h[(size_t)CAP * HIDDEN];
__device__ float g_xR[(size_t)BATCH * D_MODEL];
__device__ float g_W1R[(size_t)NUM_EXP * D_MODEL * HIDDEN];
__device__ float g_W2R[(size_t)NUM_EXP * HIDDEN * N2PAD];
__device__ float g_gates[BATCH * NUM_EXP];
__device__ int   g_topi[BATCH * TOPK];
__device__ int   g_pairExpert[NPAIR];
__device__ float g_pairGate[NPAIR];
__device__ int   g_counts[NUM_EXP];
__device__ int   g_segbase[NUM_EXP + 1];
__device__ int   g_cursor[NUM_EXP];
__device__ int   g_permToken[CAP];
__device__ int   g_permPair[CAP];
__device__ float g_permGate[CAP];
__device__ unsigned g_done;

__device__ __forceinline__ float tf32r(float x) {
    uint32_t o; asm("cvt.rna.tf32.f32 %0, %1;" : "=r"(o) : "f"(x));
    return __uint_as_float(o);
}
__device__ __forceinline__ float gelu_exact(float v) {
    return 0.5f * v * (1.0f + erff(v * 0.70710678118654752f));
}
__device__ __forceinline__ uint32_t smem_u32(const void* p) {
    uint32_t a;
    asm("{ .reg .u64 t; cvta.to.shared.u64 t, %1; cvt.u32.u64 %0, t; }" : "=r"(a) : "l"(p));
    return a;
}

#define CPA16(dst, src)        asm volatile("cp.async.ca.shared.global [%0], [%1], 16;" :: "r"(dst), "l"(src))
#define CPA16_SZ(dst, src, sz) asm volatile("cp.async.ca.shared.global [%0], [%1], 16, %2;" :: "r"(dst), "l"(src), "r"(sz))
#define CPA_COMMIT()           asm volatile("cp.async.commit_group;" ::: "memory")
#define CPA_WAIT1()            asm volatile("cp.async.wait_group 1;" ::: "memory")
#define CPA_WAIT0()            asm volatile("cp.async.wait_group 0;" ::: "memory")

__device__ __forceinline__ void mma_tf32(float* c, const uint32_t* a, const uint32_t* b) {
    asm volatile("mma.sync.aligned.m16n8k8.row.col.f32.tf32.tf32.f32 "
                 "{%0,%1,%2,%3}, {%4,%5,%6,%7}, {%8,%9}, {%0,%1,%2,%3};"
                 : "+f"(c[0]), "+f"(c[1]), "+f"(c[2]), "+f"(c[3])
                 : "r"(a[0]), "r"(a[1]), "r"(a[2]), "r"(a[3]), "r"(b[0]), "r"(b[1]));
}

// ---------------- L1: fused prep (init + tf32 rounding) ---------------------
__global__ void prep_kernel(const float* __restrict__ x,
                            const float* __restrict__ W1,
                            const float* __restrict__ W2) {
    size_t tid0 = blockIdx.x * blockDim.x + threadIdx.x;
    size_t nthr = (size_t)gridDim.x * blockDim.x;

    if (tid0 < CAP) { g_permToken[tid0] = -1; g_permPair[tid0] = -1; }
    if (tid0 < NUM_EXP) g_counts[tid0] = 0;
    if (tid0 == 0) g_done = 0;

    for (size_t i = tid0; i < (size_t)BATCH * D_MODEL / 4; i += nthr) {
        float4 v = ((const float4*)x)[i];
        v.x = tf32r(v.x); v.y = tf32r(v.y); v.z = tf32r(v.z); v.w = tf32r(v.w);
        ((float4*)g_xR)[i] = v;
    }
    for (size_t i = tid0; i < (size_t)NUM_EXP * D_MODEL * HIDDEN / 4; i += nthr) {
        float4 v = ((const float4*)W1)[i];
        v.x = tf32r(v.x); v.y = tf32r(v.y); v.z = tf32r(v.z); v.w = tf32r(v.w);
        ((float4*)g_W1R)[i] = v;
    }
    for (size_t i = tid0; i < (size_t)NUM_EXP * HIDDEN * N2PAD; i += nthr) {
        size_t r = i / N2PAD; int n = (int)(i % N2PAD);
        g_W2R[i] = (n < NUM_CLS) ? tf32r(W2[r * NUM_CLS + n]) : 0.f;
    }
}

// ---------------- L2: router (+ last-block scan) -----------------------------
__global__ void router_kernel(const float* __restrict__ x,
                              const float* __restrict__ Wg,
                              const float* __restrict__ bg) {
    int gwarp = (blockIdx.x * blockDim.x + threadIdx.x) >> 5;
    int lane  = threadIdx.x & 31;
    if (gwarp < BATCH) {
        const float* xr = x + (size_t)gwarp * D_MODEL;
        float acc[NUM_EXP];
#pragma unroll
        for (int e = 0; e < NUM_EXP; e++) acc[e] = 0.f;
        for (int k0 = lane * 4; k0 < D_MODEL; k0 += 128) {
            float4 xv = *(const float4*)(xr + k0);
            const float* xs = (const float*)&xv;
#pragma unroll
            for (int kk = 0; kk < 4; kk++) {
                const float4* wg = (const float4*)(Wg + (size_t)(k0 + kk) * NUM_EXP);
                float4 w0 = wg[0], w1 = wg[1];
                float xk = xs[kk];
                acc[0] += xk * w0.x; acc[1] += xk * w0.y;
                acc[2] += xk * w0.z; acc[3] += xk * w0.w;
                acc[4] += xk * w1.x; acc[5] += xk * w1.y;
                acc[6] += xk * w1.z; acc[7] += xk * w1.w;
            }
        }
#pragma unroll
        for (int off = 16; off; off >>= 1)
#pragma unroll
            for (int e = 0; e < NUM_EXP; e++)
                acc[e] += __shfl_xor_sync(0xFFFFFFFFu, acc[e], off);
        if (lane == 0) {
            float v[NUM_EXP];
#pragma unroll
            for (int e = 0; e < NUM_EXP; e++) v[e] = acc[e] + bg[e];
            int i1 = 0;
#pragma unroll
            for (int e = 1; e < NUM_EXP; e++) if (v[e] > v[i1]) i1 = e;
            int i2 = -1;
#pragma unroll
            for (int e = 0; e < NUM_EXP; e++)
                if (e != i1 && (i2 < 0 || v[e] > v[i2])) i2 = e;
            float e2 = expf(v[i2] - v[i1]);
            float g1 = 1.f / (1.f + e2), g2 = e2 / (1.f + e2);
#pragma unroll
            for (int e = 0; e < NUM_EXP; e++) g_gates[gwarp * NUM_EXP + e] = 0.f;
            g_gates[gwarp * NUM_EXP + i1] = g1;
            g_gates[gwarp * NUM_EXP + i2] = g2;
            g_topi[gwarp * TOPK + 0] = i1;
            g_topi[gwarp * TOPK + 1] = i2;
            g_pairExpert[gwarp * TOPK + 0] = i1;
            g_pairExpert[gwarp * TOPK + 1] = i2;
            g_pairGate[gwarp * TOPK + 0] = g1;
            g_pairGate[gwarp * TOPK + 1] = g2;
            atomicAdd(&g_counts[i1], 1);
            atomicAdd(&g_counts[i2], 1);
        }
    }
    // last block performs the 128-aligned segment scan
    __syncthreads();
    if (threadIdx.x == 0) {
        __threadfence();
        unsigned ticket = atomicAdd(&g_done, 1u);
        if (ticket == gridDim.x - 1) {
            int base = 0;
#pragma unroll
            for (int e = 0; e < NUM_EXP; e++) {
                g_segbase[e] = base;
                g_cursor[e]  = base;
                base += ((g_counts[e] + 127) >> 7) << 7;
            }
            g_segbase[NUM_EXP] = base;
            __threadfence();
        }
    }
}

// ---------------- L3: scatter ------------------------------------------------
__global__ void scatter_kernel() {
    int p = blockIdx.x * blockDim.x + threadIdx.x;
    if (p >= NPAIR) return;
    int e = g_pairExpert[p];
    int pos = atomicAdd(&g_cursor[e], 1);
    g_permToken[pos] = p >> 1;
    g_permPair[pos]  = p;
    g_permGate[pos]  = g_pairGate[p];
}

// ---------------- tf32 mma GEMMs (R3-proven 2-stage) -------------------------
#define AS_STRIDE 36
#define BS_STRIDE 136
#define AS_BYTES  (128 * AS_STRIDE * 4)            // 18432
#define BS_BYTES  (32 * BS_STRIDE * 4)             // 17408
#define STAGE_B   (AS_BYTES + BS_BYTES)            // 35840
#define SMEM_TOT  (2 * STAGE_B)                    // 71680

__device__ __forceinline__ void issue_chunk(uint32_t aDst, uint32_t bDst,
                                            const float* aSrc, const float* bSrc,
                                            int bStrideN, uint32_t aSz, int kt) {
#pragma unroll
    for (int j = 0; j < 4; j++)
        CPA16_SZ(aDst + j * 16, aSrc + kt + j * 4, aSz);
#pragma unroll
    for (int j = 0; j < 4; j++)
        CPA16(bDst + j * 16, bSrc + (size_t)kt * bStrideN + j * 4);
    CPA_COMMIT();
}

__device__ __forceinline__ void mma_tile(const float* As, const float* Bs,
                                         int wr, int wc, int gid, int tig,
                                         float c[4][4][4]) {
#pragma unroll
    for (int ks = 0; ks < 4; ks++) {
        uint32_t b[4][2];
#pragma unroll
        for (int ni = 0; ni < 4; ni++) {
            int col = wc + ni * 8 + gid;
            b[ni][0] = __float_as_uint(Bs[(ks * 8 + tig) * BS_STRIDE + col]);
            b[ni][1] = __float_as_uint(Bs[(ks * 8 + tig + 4) * BS_STRIDE + col]);
        }
#pragma unroll
        for (int mi = 0; mi < 4; mi++) {
            int r0 = wr + mi * 16 + gid;
            uint32_t a[4];
            a[0] = __float_as_uint(As[r0 * AS_STRIDE + ks * 8 + tig]);
            a[1] = __float_as_uint(As[(r0 + 8) * AS_STRIDE + ks * 8 + tig]);
            a[2] = __float_as_uint(As[r0 * AS_STRIDE + ks * 8 + tig + 4]);
            a[3] = __float_as_uint(As[(r0 + 8) * AS_STRIDE + ks * 8 + tig + 4]);
#pragma unroll
            for (int ni = 0; ni < 4; ni++) mma_tf32(c[mi][ni], a, b[ni]);
        }
    }
}

__device__ __forceinline__ void gemm_mainloop(uint32_t aDst0, uint32_t bDst0,
                                              const float* aSrc, const float* bSrc,
                                              int bStrideN, uint32_t aSz,
                                              char* smem, int NIT,
                                              int wr, int wc, int gid, int tig,
                                              float c[4][4][4]) {
    issue_chunk(aDst0, bDst0, aSrc, bSrc, bStrideN, aSz, 0);
    for (int it = 0; it < NIT; ++it) {
        if (it + 1 < NIT) {
            int nb = (it + 1) & 1;
            issue_chunk(aDst0 + nb * STAGE_B, bDst0 + nb * STAGE_B,
                        aSrc, bSrc, bStrideN, aSz, (it + 1) * 32);
            CPA_WAIT1();
        } else {
            CPA_WAIT0();
        }
        __syncthreads();
        int buf = it & 1;
        mma_tile((const float*)(smem + buf * STAGE_B),
                 (const float*)(smem + buf * STAGE_B + AS_BYTES),
                 wr, wc, gid, tig, c);
        __syncthreads();
    }
}

__global__ __launch_bounds__(256, 2)
void gemm1_mma(const float* __restrict__ b1) {
    extern __shared__ __align__(16) char smem[];
    const int tid = threadIdx.x, wid = tid >> 5, lane = tid & 31;
    const int rowBase = blockIdx.x * 128, nBase = blockIdx.y * 128;
    if (rowBase >= g_segbase[NUM_EXP]) return;
    int expert = 0;
#pragma unroll
    for (int i = 1; i < NUM_EXP; i++) if (g_segbase[i] <= rowBase) expert = i;

    uint32_t sb = smem_u32(smem);
    const int am = tid >> 1, ak = (tid & 1) * 16;
    const int bk = tid >> 3, bn = (tid & 7) * 16;
    uint32_t aDst0 = sb + (am * AS_STRIDE + ak) * 4;
    uint32_t bDst0 = sb + AS_BYTES + (bk * BS_STRIDE + bn) * 4;

    const int tok = g_permToken[rowBase + am];
    const float* aSrc = g_xR + (size_t)(tok < 0 ? 0 : tok) * D_MODEL + ak;
    uint32_t aSz = tok < 0 ? 0u : 16u;
    const float* bSrc = g_W1R + (size_t)expert * D_MODEL * HIDDEN + (size_t)bk * HIDDEN + nBase + bn;

    const int gid = lane >> 2, tig = lane & 3;
    const int wr = (wid >> 2) * 64, wc = (wid & 3) * 32;
    float c[4][4][4];
#pragma unroll
    for (int mi = 0; mi < 4; mi++)
#pragma unroll
        for (int ni = 0; ni < 4; ni++)
#pragma unroll
            for (int q = 0; q < 4; q++) c[mi][ni][q] = 0.f;

    gemm_mainloop(aDst0, bDst0, aSrc, bSrc, HIDDEN, aSz, smem, D_MODEL / 32,
                  wr, wc, gid, tig, c);

    const float* bb = b1 + (size_t)expert * HIDDEN + nBase;
#pragma unroll
    for (int mi = 0; mi < 4; mi++) {
        int r0 = rowBase + wr + mi * 16 + gid;
#pragma unroll
        for (int ni = 0; ni < 4; ni++) {
            int col = wc + ni * 8 + tig * 2;
            float bias0 = __ldg(bb + col), bias1 = __ldg(bb + col + 1);
            float2 v0, v1;
            v0.x = tf32r(gelu_exact(c[mi][ni][0] + bias0));
            v0.y = tf32r(gelu_exact(c[mi][ni][1] + bias1));
            v1.x = tf32r(gelu_exact(c[mi][ni][2] + bias0));
            v1.y = tf32r(gelu_exact(c[mi][ni][3] + bias1));
            *(float2*)(g_h + (size_t)r0 * HIDDEN + nBase + col) = v0;
            *(float2*)(g_h + (size_t)(r0 + 8) * HIDDEN + nBase + col) = v1;
        }
    }
}

__global__ __launch_bounds__(256, 2)
void gemm2_mma(const float* __restrict__ b2, float* __restrict__ out) {
    extern __shared__ __align__(16) char smem[];
    const int tid = threadIdx.x, wid = tid >> 5, lane = tid & 31;
    const int rowBase = blockIdx.x * 128, nBase = blockIdx.y * 128;
    if (rowBase >= g_segbase[NUM_EXP]) return;
    int expert = 0;
#pragma unroll
    for (int i = 1; i < NUM_EXP; i++) if (g_segbase[i] <= rowBase) expert = i;

    uint32_t sb = smem_u32(smem);
    const int am = tid >> 1, ak = (tid & 1) * 16;
    const int bk = tid >> 3, bn = (tid & 7) * 16;
    uint32_t aDst0 = sb + (am * AS_STRIDE + ak) * 4;
    uint32_t bDst0 = sb + AS_BYTES + (bk * BS_STRIDE + bn) * 4;

    const float* aSrc = g_h + (size_t)(rowBase + am) * HIDDEN + ak;
    const float* bSrc = g_W2R + (size_t)expert * HIDDEN * N2PAD + (size_t)bk * N2PAD + nBase + bn;

    const int gid = lane >> 2, tig = lane & 3;
    const int wr = (wid >> 2) * 64, wc = (wid & 3) * 32;
    float c[4][4][4];
#pragma unroll
    for (int mi = 0; mi < 4; mi++)
#pragma unroll
        for (int ni = 0; ni < 4; ni++)
#pragma unroll
            for (int q = 0; q < 4; q++) c[mi][ni][q] = 0.f;

    gemm_mainloop(aDst0, bDst0, aSrc, bSrc, N2PAD, 16u, smem, HIDDEN / 32,
                  wr, wc, gid, tig, c);

    const float* bb = b2 + (size_t)expert * NUM_CLS;
#pragma unroll
    for (int mi = 0; mi < 4; mi++) {
        int r0 = rowBase + wr + mi * 16 + gid;
#pragma unroll
        for (int half = 0; half < 2; half++) {
            int r = r0 + half * 8;
            int pair = g_permPair[r];
            if (pair < 0) continue;
            float gate = g_permGate[r];
            float* orow = out + (size_t)(pair >> 1) * NUM_CLS;
#pragma unroll
            for (int ni = 0; ni < 4; ni++) {
                int col = nBase + wc + ni * 8 + tig * 2;
                if (col < NUM_CLS)
                    atomicAdd(orow + col, gate * (c[mi][ni][half * 2 + 0] + __ldg(bb + col)));
                if (col + 1 < NUM_CLS)
                    atomicAdd(orow + col + 1, gate * (c[mi][ni][half * 2 + 1] + __ldg(bb + col + 1)));
            }
        }
    }
}

// ---------------- tail -------------------------------------------------------
__global__ void tail_kernel(float* __restrict__ out, int out_size) {
    int i = blockIdx.x * blockDim.x + threadIdx.x;
    const int OUT0 = BATCH * NUM_CLS;
    if (out_size >= OUT0 + BATCH * NUM_EXP) {
        if (i < BATCH * NUM_EXP)
            out[OUT0 + i] = g_gates[i];
        if (out_size >= OUT0 + BATCH * NUM_EXP + BATCH * TOPK && i < BATCH * TOPK)
            out[OUT0 + BATCH * NUM_EXP + i] = (float)g_topi[i];
    }
}

// ---------------------------------------------------------------------------
extern "C" void kernel_launch(void* const* d_in, const int* in_sizes, int n_in,
                              void* d_out, int out_size) {
    const float* x  = (const float*)d_in[0];
    const float* Wg = (const float*)d_in[1];
    const float* bg = (const float*)d_in[2];
    const float* W1 = (const float*)d_in[3];
    const float* b1 = (const float*)d_in[4];
    const float* W2 = (const float*)d_in[5];
    const float* b2 = (const float*)d_in[6];
    float* out = (float*)d_out;

    cudaFuncSetAttribute(gemm1_mma, cudaFuncAttributeMaxDynamicSharedMemorySize, SMEM_TOT);
    cudaFuncSetAttribute(gemm2_mma, cudaFuncAttributeMaxDynamicSharedMemorySize, SMEM_TOT);

    // Launch order matters: ncu profiles launch index 4 -> gemm1_mma.
    cudaMemsetAsync(d_out, 0, (size_t)out_size * sizeof(float));            // 0
    prep_kernel<<<2048, 256>>>(x, W1, W2);                                  // 1
    router_kernel<<<BATCH / 8, 256>>>(x, Wg, bg);                           // 2
    scatter_kernel<<<(NPAIR + 255) / 256, 256>>>();                         // 3
    gemm1_mma<<<dim3(MAX_TILES, HIDDEN / 128), 256, SMEM_TOT>>>(b1);        // 4 <- ncu
    gemm2_mma<<<dim3(MAX_TILES, N2PAD / 128), 256, SMEM_TOT>>>(b2, out);    // 5
    tail_kernel<<<(BATCH * NUM_EXP + 255) / 256, 256>>>(out, out_size);     // 6
}

// round 7
// speedup vs baseline: 1.2542x; 1.1055x over previous
#include <cuda_runtime.h>
#include <cuda_bf16.h>
#include <math.h>
#include <stdint.h>

// ---------------------------------------------------------------------------
// MoE top-2/8: router -> permuted expert segments -> two tf32 mma.sync GEMMs.
// 4-warp CTAs, 64x64 warp tiles (halved cross-warp LDS redundancy).
// ---------------------------------------------------------------------------

#define BATCH      8192
#define D_MODEL    1024
#define HIDDEN     4096
#define NUM_CLS    1000
#define N2PAD      1024
#define NUM_EXP    8
#define TOPK       2
#define NPAIR      (BATCH * TOPK)
#define MAX_TILES  136
#define CAP        (MAX_TILES * 128)

// ---------------- scratch ---------------------------------------------------
__device__ float g_h[(size_t)CAP * HIDDEN];
__device__ float g_xR[(size_t)BATCH * D_MODEL];
__device__ float g_W1R[(size_t)NUM_EXP * D_MODEL * HIDDEN];
__device__ float g_W2R[(size_t)NUM_EXP * HIDDEN * N2PAD];
__device__ float g_gates[BATCH * NUM_EXP];
__device__ int   g_topi[BATCH * TOPK];
__device__ int   g_pairExpert[NPAIR];
__device__ float g_pairGate[NPAIR];
__device__ int   g_counts[NUM_EXP];
__device__ int   g_segbase[NUM_EXP + 1];
__device__ int   g_cursor[NUM_EXP];
__device__ int   g_permToken[CAP];
__device__ int   g_permPair[CAP];
__device__ float g_permGate[CAP];
__device__ unsigned g_done;

__device__ __forceinline__ float tf32r(float x) {
    uint32_t o; asm("cvt.rna.tf32.f32 %0, %1;" : "=r"(o) : "f"(x));
    return __uint_as_float(o);
}
__device__ __forceinline__ float gelu_exact(float v) {
    return 0.5f * v * (1.0f + erff(v * 0.70710678118654752f));
}
__device__ __forceinline__ uint32_t smem_u32(const void* p) {
    uint32_t a;
    asm("{ .reg .u64 t; cvta.to.shared.u64 t, %1; cvt.u32.u64 %0, t; }" : "=r"(a) : "l"(p));
    return a;
}

#define CPA16(dst, src)        asm volatile("cp.async.ca.shared.global [%0], [%1], 16;" :: "r"(dst), "l"(src))
#define CPA16_SZ(dst, src, sz) asm volatile("cp.async.ca.shared.global [%0], [%1], 16, %2;" :: "r"(dst), "l"(src), "r"(sz))
#define CPA_COMMIT()           asm volatile("cp.async.commit_group;" ::: "memory")
#define CPA_WAIT1()            asm volatile("cp.async.wait_group 1;" ::: "memory")
#define CPA_WAIT0()            asm volatile("cp.async.wait_group 0;" ::: "memory")

__device__ __forceinline__ void mma_tf32(float* c, const uint32_t* a, const uint32_t* b) {
    asm volatile("mma.sync.aligned.m16n8k8.row.col.f32.tf32.tf32.f32 "
                 "{%0,%1,%2,%3}, {%4,%5,%6,%7}, {%8,%9}, {%0,%1,%2,%3};"
                 : "+f"(c[0]), "+f"(c[1]), "+f"(c[2]), "+f"(c[3])
                 : "r"(a[0]), "r"(a[1]), "r"(a[2]), "r"(a[3]), "r"(b[0]), "r"(b[1]));
}

// ---------------- L1: fused prep (init + tf32 rounding) ---------------------
__global__ void prep_kernel(const float* __restrict__ x,
                            const float* __restrict__ W1,
                            const float* __restrict__ W2) {
    size_t tid0 = blockIdx.x * blockDim.x + threadIdx.x;
    size_t nthr = (size_t)gridDim.x * blockDim.x;

    if (tid0 < CAP) { g_permToken[tid0] = -1; g_permPair[tid0] = -1; }
    if (tid0 < NUM_EXP) g_counts[tid0] = 0;
    if (tid0 == 0) g_done = 0;

    for (size_t i = tid0; i < (size_t)BATCH * D_MODEL / 4; i += nthr) {
        float4 v = ((const float4*)x)[i];
        v.x = tf32r(v.x); v.y = tf32r(v.y); v.z = tf32r(v.z); v.w = tf32r(v.w);
        ((float4*)g_xR)[i] = v;
    }
    for (size_t i = tid0; i < (size_t)NUM_EXP * D_MODEL * HIDDEN / 4; i += nthr) {
        float4 v = ((const float4*)W1)[i];
        v.x = tf32r(v.x); v.y = tf32r(v.y); v.z = tf32r(v.z); v.w = tf32r(v.w);
        ((float4*)g_W1R)[i] = v;
    }
    for (size_t i = tid0; i < (size_t)NUM_EXP * HIDDEN * N2PAD; i += nthr) {
        size_t r = i / N2PAD; int n = (int)(i % N2PAD);
        g_W2R[i] = (n < NUM_CLS) ? tf32r(W2[r * NUM_CLS + n]) : 0.f;
    }
}

// ---------------- L2: router (+ last-block scan) -----------------------------
__global__ void router_kernel(const float* __restrict__ x,
                              const float* __restrict__ Wg,
                              const float* __restrict__ bg) {
    int gwarp = (blockIdx.x * blockDim.x + threadIdx.x) >> 5;
    int lane  = threadIdx.x & 31;
    if (gwarp < BATCH) {
        const float* xr = x + (size_t)gwarp * D_MODEL;
        float acc[NUM_EXP];
#pragma unroll
        for (int e = 0; e < NUM_EXP; e++) acc[e] = 0.f;
        for (int k0 = lane * 4; k0 < D_MODEL; k0 += 128) {
            float4 xv = *(const float4*)(xr + k0);
            const float* xs = (const float*)&xv;
#pragma unroll
            for (int kk = 0; kk < 4; kk++) {
                const float4* wg = (const float4*)(Wg + (size_t)(k0 + kk) * NUM_EXP);
                float4 w0 = wg[0], w1 = wg[1];
                float xk = xs[kk];
                acc[0] += xk * w0.x; acc[1] += xk * w0.y;
                acc[2] += xk * w0.z; acc[3] += xk * w0.w;
                acc[4] += xk * w1.x; acc[5] += xk * w1.y;
                acc[6] += xk * w1.z; acc[7] += xk * w1.w;
            }
        }
#pragma unroll
        for (int off = 16; off; off >>= 1)
#pragma unroll
            for (int e = 0; e < NUM_EXP; e++)
                acc[e] += __shfl_xor_sync(0xFFFFFFFFu, acc[e], off);
        if (lane == 0) {
            float v[NUM_EXP];
#pragma unroll
            for (int e = 0; e < NUM_EXP; e++) v[e] = acc[e] + bg[e];
            int i1 = 0;
#pragma unroll
            for (int e = 1; e < NUM_EXP; e++) if (v[e] > v[i1]) i1 = e;
            int i2 = -1;
#pragma unroll
            for (int e = 0; e < NUM_EXP; e++)
                if (e != i1 && (i2 < 0 || v[e] > v[i2])) i2 = e;
            float e2 = expf(v[i2] - v[i1]);
            float g1 = 1.f / (1.f + e2), g2 = e2 / (1.f + e2);
#pragma unroll
            for (int e = 0; e < NUM_EXP; e++) g_gates[gwarp * NUM_EXP + e] = 0.f;
            g_gates[gwarp * NUM_EXP + i1] = g1;
            g_gates[gwarp * NUM_EXP + i2] = g2;
            g_topi[gwarp * TOPK + 0] = i1;
            g_topi[gwarp * TOPK + 1] = i2;
            g_pairExpert[gwarp * TOPK + 0] = i1;
            g_pairExpert[gwarp * TOPK + 1] = i2;
            g_pairGate[gwarp * TOPK + 0] = g1;
            g_pairGate[gwarp * TOPK + 1] = g2;
            atomicAdd(&g_counts[i1], 1);
            atomicAdd(&g_counts[i2], 1);
        }
    }
    __syncthreads();
    if (threadIdx.x == 0) {
        __threadfence();
        unsigned ticket = atomicAdd(&g_done, 1u);
        if (ticket == gridDim.x - 1) {
            int base = 0;
#pragma unroll
            for (int e = 0; e < NUM_EXP; e++) {
                g_segbase[e] = base;
                g_cursor[e]  = base;
                base += ((g_counts[e] + 127) >> 7) << 7;
            }
            g_segbase[NUM_EXP] = base;
            __threadfence();
        }
    }
}

// ---------------- L3: scatter ------------------------------------------------
__global__ void scatter_kernel() {
    int p = blockIdx.x * blockDim.x + threadIdx.x;
    if (p >= NPAIR) return;
    int e = g_pairExpert[p];
    int pos = atomicAdd(&g_cursor[e], 1);
    g_permToken[pos] = p >> 1;
    g_permPair[pos]  = p;
    g_permGate[pos]  = g_pairGate[p];
}

// ---------------- tf32 mma GEMMs --------------------------------------------
// 128 threads (4 warps), CTA tile 128x128, warp tile 64x64, BK=32, 2-stage.
#define AS_STRIDE 36
#define BS_STRIDE 136
#define AS_BYTES  (128 * AS_STRIDE * 4)            // 18432
#define BS_BYTES  (32 * BS_STRIDE * 4)             // 17408
#define STAGE_B   (AS_BYTES + BS_BYTES)            // 35840
#define SMEM_TOT  (2 * STAGE_B)                    // 71680

// Per-thread copy roles (128 threads):
//   A: am = tid>>1 (rows am, am+64), koff = (tid&1)*16 floats, 4 x float4 each row
//   B: bk = tid>>3 (rows bk, bk+16), bn = (tid&7)*16 floats,  4 x float4 each row
__device__ __forceinline__ void issue_chunk(
    uint32_t aDstL, uint32_t aDstH, uint32_t bDstL, uint32_t bDstH,
    const float* aSrcL, const float* aSrcH, uint32_t aSzL, uint32_t aSzH,
    const float* bSrc, int bStrideN, int kt)
{
#pragma unroll
    for (int j = 0; j < 4; j++)
        CPA16_SZ(aDstL + j * 16, aSrcL + kt + j * 4, aSzL);
#pragma unroll
    for (int j = 0; j < 4; j++)
        CPA16_SZ(aDstH + j * 16, aSrcH + kt + j * 4, aSzH);
#pragma unroll
    for (int j = 0; j < 4; j++)
        CPA16(bDstL + j * 16, bSrc + (size_t)kt * bStrideN + j * 4);
#pragma unroll
    for (int j = 0; j < 4; j++)
        CPA16(bDstH + j * 16, bSrc + (size_t)(kt + 16) * bStrideN + j * 4);
    CPA_COMMIT();
}

// 64x64 warp tile: mi 0..3 (rows), ni 0..7 (cols)
__device__ __forceinline__ void mma_tile(const float* As, const float* Bs,
                                         int wr, int wc, int gid, int tig,
                                         float c[4][8][4]) {
#pragma unroll
    for (int ks = 0; ks < 4; ks++) {
        uint32_t b[8][2];
#pragma unroll
        for (int ni = 0; ni < 8; ni++) {
            int col = wc + ni * 8 + gid;
            b[ni][0] = __float_as_uint(Bs[(ks * 8 + tig) * BS_STRIDE + col]);
            b[ni][1] = __float_as_uint(Bs[(ks * 8 + tig + 4) * BS_STRIDE + col]);
        }
#pragma unroll
        for (int mi = 0; mi < 4; mi++) {
            int r0 = wr + mi * 16 + gid;
            uint32_t a[4];
            a[0] = __float_as_uint(As[r0 * AS_STRIDE + ks * 8 + tig]);
            a[1] = __float_as_uint(As[(r0 + 8) * AS_STRIDE + ks * 8 + tig]);
            a[2] = __float_as_uint(As[r0 * AS_STRIDE + ks * 8 + tig + 4]);
            a[3] = __float_as_uint(As[(r0 + 8) * AS_STRIDE + ks * 8 + tig + 4]);
#pragma unroll
            for (int ni = 0; ni < 8; ni++) mma_tf32(c[mi][ni], a, b[ni]);
        }
    }
}

__device__ __forceinline__ void gemm_mainloop(
    uint32_t aDstL, uint32_t aDstH, uint32_t bDstL, uint32_t bDstH,
    const float* aSrcL, const float* aSrcH, uint32_t aSzL, uint32_t aSzH,
    const float* bSrc, int bStrideN, char* smem, int NIT,
    int wr, int wc, int gid, int tig, float c[4][8][4])
{
    issue_chunk(aDstL, aDstH, bDstL, bDstH, aSrcL, aSrcH, aSzL, aSzH, bSrc, bStrideN, 0);
    for (int it = 0; it < NIT; ++it) {
        if (it + 1 < NIT) {
            int nb = (it + 1) & 1;
            issue_chunk(aDstL + nb * STAGE_B, aDstH + nb * STAGE_B,
                        bDstL + nb * STAGE_B, bDstH + nb * STAGE_B,
                        aSrcL, aSrcH, aSzL, aSzH, bSrc, bStrideN, (it + 1) * 32);
            CPA_WAIT1();
        } else {
            CPA_WAIT0();
        }
        __syncthreads();
        int buf = it & 1;
        mma_tile((const float*)(smem + buf * STAGE_B),
                 (const float*)(smem + buf * STAGE_B + AS_BYTES),
                 wr, wc, gid, tig, c);
        __syncthreads();
    }
}

__global__ __launch_bounds__(128, 2)
void gemm1_mma(const float* __restrict__ b1) {
    extern __shared__ __align__(16) char smem[];
    const int tid = threadIdx.x, wid = tid >> 5, lane = tid & 31;
    const int rowBase = blockIdx.x * 128, nBase = blockIdx.y * 128;
    if (rowBase >= g_segbase[NUM_EXP]) return;
    int expert = 0;
#pragma unroll
    for (int i = 1; i < NUM_EXP; i++) if (g_segbase[i] <= rowBase) expert = i;

    uint32_t sb = smem_u32(smem);
    const int am = tid >> 1, ak = (tid & 1) * 16;
    const int bk = tid >> 3, bn = (tid & 7) * 16;
    uint32_t aDstL = sb + (am * AS_STRIDE + ak) * 4;
    uint32_t aDstH = aDstL + 64 * AS_STRIDE * 4;
    uint32_t bDstL = sb + AS_BYTES + (bk * BS_STRIDE + bn) * 4;
    uint32_t bDstH = bDstL + 16 * BS_STRIDE * 4;

    const int tokL = g_permToken[rowBase + am];
    const int tokH = g_permToken[rowBase + am + 64];
    const float* aSrcL = g_xR + (size_t)(tokL < 0 ? 0 : tokL) * D_MODEL + ak;
    const float* aSrcH = g_xR + (size_t)(tokH < 0 ? 0 : tokH) * D_MODEL + ak;
    uint32_t aSzL = tokL < 0 ? 0u : 16u;
    uint32_t aSzH = tokH < 0 ? 0u : 16u;
    const float* bSrc = g_W1R + (size_t)expert * D_MODEL * HIDDEN + (size_t)bk * HIDDEN + nBase + bn;

    const int gid = lane >> 2, tig = lane & 3;
    const int wr = (wid >> 1) * 64, wc = (wid & 1) * 64;
    float c[4][8][4];
#pragma unroll
    for (int mi = 0; mi < 4; mi++)
#pragma unroll
        for (int ni = 0; ni < 8; ni++)
#pragma unroll
            for (int q = 0; q < 4; q++) c[mi][ni][q] = 0.f;

    gemm_mainloop(aDstL, aDstH, bDstL, bDstH, aSrcL, aSrcH, aSzL, aSzH,
                  bSrc, HIDDEN, smem, D_MODEL / 32, wr, wc, gid, tig, c);

    const float* bb = b1 + (size_t)expert * HIDDEN + nBase;
#pragma unroll
    for (int mi = 0; mi < 4; mi++) {
        int r0 = rowBase + wr + mi * 16 + gid;
#pragma unroll
        for (int ni = 0; ni < 8; ni++) {
            int col = wc + ni * 8 + tig * 2;
            float bias0 = __ldg(bb + col), bias1 = __ldg(bb + col + 1);
            float2 v0, v1;
            v0.x = tf32r(gelu_exact(c[mi][ni][0] + bias0));
            v0.y = tf32r(gelu_exact(c[mi][ni][1] + bias1));
            v1.x = tf32r(gelu_exact(c[mi][ni][2] + bias0));
            v1.y = tf32r(gelu_exact(c[mi][ni][3] + bias1));
            *(float2*)(g_h + (size_t)r0 * HIDDEN + nBase + col) = v0;
            *(float2*)(g_h + (size_t)(r0 + 8) * HIDDEN + nBase + col) = v1;
        }
    }
}

__global__ __launch_bounds__(128, 2)
void gemm2_mma(const float* __restrict__ b2, float* __restrict__ out) {
    extern __shared__ __align__(16) char smem[];
    const int tid = threadIdx.x, wid = tid >> 5, lane = tid & 31;
    const int rowBase = blockIdx.x * 128, nBase = blockIdx.y * 128;
    if (rowBase >= g_segbase[NUM_EXP]) return;
    int expert = 0;
#pragma unroll
    for (int i = 1; i < NUM_EXP; i++) if (g_segbase[i] <= rowBase) expert = i;

    uint32_t sb = smem_u32(smem);
    const int am = tid >> 1, ak = (tid & 1) * 16;
    const int bk = tid >> 3, bn = (tid & 7) * 16;
    uint32_t aDstL = sb + (am * AS_STRIDE + ak) * 4;
    uint32_t aDstH = aDstL + 64 * AS_STRIDE * 4;
    uint32_t bDstL = sb + AS_BYTES + (bk * BS_STRIDE + bn) * 4;
    uint32_t bDstH = bDstL + 16 * BS_STRIDE * 4;

    const float* aSrcL = g_h + (size_t)(rowBase + am) * HIDDEN + ak;
    const float* aSrcH = g_h + (size_t)(rowBase + am + 64) * HIDDEN + ak;
    const float* bSrc = g_W2R + (size_t)expert * HIDDEN * N2PAD + (size_t)bk * N2PAD + nBase + bn;

    const int gid = lane >> 2, tig = lane & 3;
    const int wr = (wid >> 1) * 64, wc = (wid & 1) * 64;
    float c[4][8][4];
#pragma unroll
    for (int mi = 0; mi < 4; mi++)
#pragma unroll
        for (int ni = 0; ni < 8; ni++)
#pragma unroll
            for (int q = 0; q < 4; q++) c[mi][ni][q] = 0.f;

    gemm_mainloop(aDstL, aDstH, bDstL, bDstH, aSrcL, aSrcH, 16u, 16u,
                  bSrc, N2PAD, smem, HIDDEN / 32, wr, wc, gid, tig, c);

    const float* bb = b2 + (size_t)expert * NUM_CLS;
#pragma unroll
    for (int mi = 0; mi < 4; mi++) {
        int r0 = rowBase + wr + mi * 16 + gid;
#pragma unroll
        for (int half = 0; half < 2; half++) {
            int r = r0 + half * 8;
            int pair = g_permPair[r];
            if (pair < 0) continue;
            float gate = g_permGate[r];
            float* orow = out + (size_t)(pair >> 1) * NUM_CLS;
#pragma unroll
            for (int ni = 0; ni < 8; ni++) {
                int col = nBase + wc + ni * 8 + tig * 2;
                if (col < NUM_CLS)
                    atomicAdd(orow + col, gate * (c[mi][ni][half * 2 + 0] + __ldg(bb + col)));
                if (col + 1 < NUM_CLS)
                    atomicAdd(orow + col + 1, gate * (c[mi][ni][half * 2 + 1] + __ldg(bb + col + 1)));
            }
        }
    }
}

// ---------------- tail -------------------------------------------------------
__global__ void tail_kernel(float* __restrict__ out, int out_size) {
    int i = blockIdx.x * blockDim.x + threadIdx.x;
    const int OUT0 = BATCH * NUM_CLS;
    if (out_size >= OUT0 + BATCH * NUM_EXP) {
        if (i < BATCH * NUM_EXP)
            out[OUT0 + i] = g_gates[i];
        if (out_size >= OUT0 + BATCH * NUM_EXP + BATCH * TOPK && i < BATCH * TOPK)
            out[OUT0 + BATCH * NUM_EXP + i] = (float)g_topi[i];
    }
}

// ---------------------------------------------------------------------------
extern "C" void kernel_launch(void* const* d_in, const int* in_sizes, int n_in,
                              void* d_out, int out_size) {
    const float* x  = (const float*)d_in[0];
    const float* Wg = (const float*)d_in[1];
    const float* bg = (const float*)d_in[2];
    const float* W1 = (const float*)d_in[3];
    const float* b1 = (const float*)d_in[4];
    const float* W2 = (const float*)d_in[5];
    const float* b2 = (const float*)d_in[6];
    float* out = (float*)d_out;

    cudaFuncSetAttribute(gemm1_mma, cudaFuncAttributeMaxDynamicSharedMemorySize, SMEM_TOT);
    cudaFuncSetAttribute(gemm2_mma, cudaFuncAttributeMaxDynamicSharedMemorySize, SMEM_TOT);

    // ncu profiles launch index 4 -> gemm1_mma.
    cudaMemsetAsync(d_out, 0, (size_t)out_size * sizeof(float));            // 0
    prep_kernel<<<2048, 256>>>(x, W1, W2);                                  // 1
    router_kernel<<<BATCH / 8, 256>>>(x, Wg, bg);                           // 2
    scatter_kernel<<<(NPAIR + 255) / 256, 256>>>();                         // 3
    gemm1_mma<<<dim3(MAX_TILES, HIDDEN / 128), 128, SMEM_TOT>>>(b1);        // 4 <- ncu
    gemm2_mma<<<dim3(MAX_TILES, N2PAD / 128), 128, SMEM_TOT>>>(b2, out);    // 5
    tail_kernel<<<(BATCH * NUM_EXP + 255) / 256, 256>>>(out, out_size);     // 6
}

// round 8
// speedup vs baseline: 1.6972x; 1.3532x over previous
#include <cuda_runtime.h>
#include <cuda_bf16.h>
#include <math.h>
#include <stdint.h>

// ---------------------------------------------------------------------------
// MoE top-2/8: two tf32 mma.sync GEMMs, ldmatrix fragment loads (A and B),
// transposed K-contig weight scratch, 2-stage cp.async pipeline.
// ---------------------------------------------------------------------------

#define BATCH      8192
#define D_MODEL    1024
#define HIDDEN     4096
#define NUM_CLS    1000
#define N2PAD      1024
#define NUM_EXP    8
#define TOPK       2
#define NPAIR      (BATCH * TOPK)
#define MAX_TILES  136
#define CAP        (MAX_TILES * 128)

// ---------------- scratch ---------------------------------------------------
__device__ float g_h[(size_t)CAP * HIDDEN];                     // tf32-rounded
__device__ float g_xR[(size_t)BATCH * D_MODEL];                 // tf32-rounded
__device__ float g_W1T[(size_t)NUM_EXP * HIDDEN * D_MODEL];     // [e][n][k] tf32
__device__ float g_W2T[(size_t)NUM_EXP * N2PAD * HIDDEN];       // [e][n][k] tf32
__device__ float g_gates[BATCH * NUM_EXP];
__device__ int   g_topi[BATCH * TOPK];
__device__ int   g_pairExpert[NPAIR];
__device__ float g_pairGate[NPAIR];
__device__ int   g_counts[NUM_EXP];
__device__ int   g_segbase[NUM_EXP + 1];
__device__ int   g_cursor[NUM_EXP];
__device__ int   g_permToken[CAP];
__device__ int   g_permPair[CAP];
__device__ float g_permGate[CAP];
__device__ unsigned g_done;

__device__ __forceinline__ float tf32r(float x) {
    uint32_t o; asm("cvt.rna.tf32.f32 %0, %1;" : "=r"(o) : "f"(x));
    return __uint_as_float(o);
}
__device__ __forceinline__ float gelu_exact(float v) {
    return 0.5f * v * (1.0f + erff(v * 0.70710678118654752f));
}
__device__ __forceinline__ uint32_t smem_u32(const void* p) {
    uint32_t a;
    asm("{ .reg .u64 t; cvta.to.shared.u64 t, %1; cvt.u32.u64 %0, t; }" : "=r"(a) : "l"(p));
    return a;
}

#define CPA16(dst, src)        asm volatile("cp.async.ca.shared.global [%0], [%1], 16;" :: "r"(dst), "l"(src))
#define CPA16_SZ(dst, src, sz) asm volatile("cp.async.ca.shared.global [%0], [%1], 16, %2;" :: "r"(dst), "l"(src), "r"(sz))
#define CPA_COMMIT()           asm volatile("cp.async.commit_group;" ::: "memory")
#define CPA_WAIT1()            asm volatile("cp.async.wait_group 1;" ::: "memory")
#define CPA_WAIT0()            asm volatile("cp.async.wait_group 0;" ::: "memory")

__device__ __forceinline__ void mma_tf32(float* c, const uint32_t* a, uint32_t b0, uint32_t b1) {
    asm volatile("mma.sync.aligned.m16n8k8.row.col.f32.tf32.tf32.f32 "
                 "{%0,%1,%2,%3}, {%4,%5,%6,%7}, {%8,%9}, {%0,%1,%2,%3};"
                 : "+f"(c[0]), "+f"(c[1]), "+f"(c[2]), "+f"(c[3])
                 : "r"(a[0]), "r"(a[1]), "r"(a[2]), "r"(a[3]), "r"(b0), "r"(b1));
}
__device__ __forceinline__ void ldsm4(uint32_t& r0, uint32_t& r1, uint32_t& r2, uint32_t& r3,
                                      uint32_t addr) {
    asm volatile("ldmatrix.sync.aligned.m8n8.x4.shared.b16 {%0,%1,%2,%3}, [%4];"
                 : "=r"(r0), "=r"(r1), "=r"(r2), "=r"(r3) : "r"(addr));
}

// ---------------- L1: prep = init + round_x + router + scan -----------------
__global__ void prep_kernel(const float* __restrict__ x,
                            const float* __restrict__ Wg,
                            const float* __restrict__ bg) {
    size_t tid0 = blockIdx.x * blockDim.x + threadIdx.x;
    size_t nthr = (size_t)gridDim.x * blockDim.x;

    if (tid0 < CAP) { g_permToken[tid0] = -1; g_permPair[tid0] = -1; }
    if (tid0 < NUM_EXP) g_counts[tid0] = 0;

    // --- router: blocks 0..1023, one warp per token --------------------------
    if (blockIdx.x < BATCH / 8) {
        int gwarp = (blockIdx.x * blockDim.x + threadIdx.x) >> 5;
        int lane  = threadIdx.x & 31;
        const float* xr = x + (size_t)gwarp * D_MODEL;
        float acc[NUM_EXP];
#pragma unroll
        for (int e = 0; e < NUM_EXP; e++) acc[e] = 0.f;
        for (int k0 = lane * 4; k0 < D_MODEL; k0 += 128) {
            float4 xv = *(const float4*)(xr + k0);
            const float* xs = (const float*)&xv;
#pragma unroll
            for (int kk = 0; kk < 4; kk++) {
                const float4* wg = (const float4*)(Wg + (size_t)(k0 + kk) * NUM_EXP);
                float4 w0 = wg[0], w1 = wg[1];
                float xk = xs[kk];
                acc[0] += xk * w0.x; acc[1] += xk * w0.y;
                acc[2] += xk * w0.z; acc[3] += xk * w0.w;
                acc[4] += xk * w1.x; acc[5] += xk * w1.y;
                acc[6] += xk * w1.z; acc[7] += xk * w1.w;
            }
        }
#pragma unroll
        for (int off = 16; off; off >>= 1)
#pragma unroll
            for (int e = 0; e < NUM_EXP; e++)
                acc[e] += __shfl_xor_sync(0xFFFFFFFFu, acc[e], off);
        if (lane == 0) {
            float v[NUM_EXP];
#pragma unroll
            for (int e = 0; e < NUM_EXP; e++) v[e] = acc[e] + bg[e];
            int i1 = 0;
#pragma unroll
            for (int e = 1; e < NUM_EXP; e++) if (v[e] > v[i1]) i1 = e;
            int i2 = -1;
#pragma unroll
            for (int e = 0; e < NUM_EXP; e++)
                if (e != i1 && (i2 < 0 || v[e] > v[i2])) i2 = e;
            float e2 = expf(v[i2] - v[i1]);
            float g1 = 1.f / (1.f + e2), g2 = e2 / (1.f + e2);
#pragma unroll
            for (int e = 0; e < NUM_EXP; e++) g_gates[gwarp * NUM_EXP + e] = 0.f;
            g_gates[gwarp * NUM_EXP + i1] = g1;
            g_gates[gwarp * NUM_EXP + i2] = g2;
            g_topi[gwarp * TOPK + 0] = i1;
            g_topi[gwarp * TOPK + 1] = i2;
            g_pairExpert[gwarp * TOPK + 0] = i1;
            g_pairExpert[gwarp * TOPK + 1] = i2;
            g_pairGate[gwarp * TOPK + 0] = g1;
            g_pairGate[gwarp * TOPK + 1] = g2;
            atomicAdd(&g_counts[i1], 1);
            atomicAdd(&g_counts[i2], 1);
        }
        __syncthreads();
        if (threadIdx.x == 0) {
            __threadfence();
            unsigned ticket = atomicAdd(&g_done, 1u);
            if (ticket == BATCH / 8 - 1) {          // last router block: scan
                int base = 0;
#pragma unroll
                for (int e = 0; e < NUM_EXP; e++) {
                    g_segbase[e] = base;
                    g_cursor[e]  = base;
                    base += ((g_counts[e] + 127) >> 7) << 7;
                }
                g_segbase[NUM_EXP] = base;
                g_done = 0;
                __threadfence();
            }
        }
    }

    // --- round x to tf32 -----------------------------------------------------
    for (size_t i = tid0; i < (size_t)BATCH * D_MODEL / 4; i += nthr) {
        float4 v = ((const float4*)x)[i];
        v.x = tf32r(v.x); v.y = tf32r(v.y); v.z = tf32r(v.z); v.w = tf32r(v.w);
        ((float4*)g_xR)[i] = v;
    }
}

// ---------------- L2: transpose weights to [e][n][k] tf32 -------------------
__global__ void transpose_kernel(const float* __restrict__ W1,
                                 const float* __restrict__ W2) {
    __shared__ float t[32][33];
    int e = blockIdx.z;
    int tx = threadIdx.x, ty = threadIdx.y;
    if (blockIdx.y < 32) {
        // W1 [e][k=1024][n=4096] -> W1T [e][n=4096][k=1024]
        int nB = blockIdx.x * 32, kB = blockIdx.y * 32;
        const float* src = W1 + (size_t)e * D_MODEL * HIDDEN;
        float* dst = g_W1T + (size_t)e * HIDDEN * D_MODEL;
#pragma unroll
        for (int i = 0; i < 32; i += 8)
            t[ty + i][tx] = src[(size_t)(kB + ty + i) * HIDDEN + nB + tx];
        __syncthreads();
#pragma unroll
        for (int i = 0; i < 32; i += 8)
            dst[(size_t)(nB + ty + i) * D_MODEL + kB + tx] = tf32r(t[tx][ty + i]);
    } else {
        // W2 [e][k=4096][n=1000] -> W2T [e][n=1024pad][k=4096]
        int nB = blockIdx.x * 32, kB = (blockIdx.y - 32) * 32;
        if (nB >= N2PAD) return;
        const float* src = W2 + (size_t)e * HIDDEN * NUM_CLS;
        float* dst = g_W2T + (size_t)e * N2PAD * HIDDEN;
#pragma unroll
        for (int i = 0; i < 32; i += 8) {
            int n = nB + tx;
            t[ty + i][tx] = (n < NUM_CLS) ? src[(size_t)(kB + ty + i) * NUM_CLS + n] : 0.f;
        }
        __syncthreads();
#pragma unroll
        for (int i = 0; i < 32; i += 8)
            dst[(size_t)(nB + ty + i) * HIDDEN + kB + tx] = tf32r(t[tx][ty + i]);
    }
}

// ---------------- L3: scatter ------------------------------------------------
__global__ void scatter_kernel() {
    int p = blockIdx.x * blockDim.x + threadIdx.x;
    if (p >= NPAIR) return;
    int e = g_pairExpert[p];
    int pos = atomicAdd(&g_cursor[e], 1);
    g_permToken[pos] = p >> 1;
    g_permPair[pos]  = p;
    g_permGate[pos]  = g_pairGate[p];
}

// ---------------- tf32 mma GEMMs --------------------------------------------
// 128 threads (4 warps, 2x2), CTA tile 128x128, warp tile 64x64, BK=32,
// 2-stage cp.async; A smem [row][k] stride 36, B smem [n][k] stride 36.
#define TS        36
#define AS_BYTES  (128 * TS * 4)                   // 18432
#define BS_BYTES  (128 * TS * 4)                   // 18432
#define STAGE_B   (AS_BYTES + BS_BYTES)            // 36864
#define SMEM_TOT  (2 * STAGE_B)                    // 73728

// copy roles: A: am=tid>>1 rows {am, am+64}, ak=(tid&1)*16, 4 float4 each.
//             B: n = (tid>>3)+16r (r=0..7), j=tid&7 -> one float4 per (r).
__device__ __forceinline__ void issue_chunk(
    uint32_t aDstL, uint32_t aDstH, uint32_t bDst,
    const float* aSrcL, const float* aSrcH, uint32_t aSzL, uint32_t aSzH,
    const float* bSrc, int bKtot, int kt)
{
#pragma unroll
    for (int j = 0; j < 4; j++)
        CPA16_SZ(aDstL + j * 16, aSrcL + kt + j * 4, aSzL);
#pragma unroll
    for (int j = 0; j < 4; j++)
        CPA16_SZ(aDstH + j * 16, aSrcH + kt + j * 4, aSzH);
#pragma unroll
    for (int r = 0; r < 8; r++)
        CPA16(bDst + r * (16 * TS * 4), bSrc + (size_t)r * 16 * bKtot + kt);
    CPA_COMMIT();
}

// ldmatrix fragment loads; aAddr/bAddr are per-lane byte addresses (stage 0).
__device__ __forceinline__ void mma_tile(uint32_t aAddr, uint32_t bAddr,
                                         float c[4][8][4]) {
#pragma unroll
    for (int ks = 0; ks < 4; ks++) {
        uint32_t a[4][4], b[4][4];
#pragma unroll
        for (int mi = 0; mi < 4; mi++)
            ldsm4(a[mi][0], a[mi][1], a[mi][2], a[mi][3],
                  aAddr + mi * (16 * TS * 4) + ks * 32);
#pragma unroll
        for (int n2 = 0; n2 < 4; n2++)
            ldsm4(b[n2][0], b[n2][1], b[n2][2], b[n2][3],
                  bAddr + n2 * (16 * TS * 4) + ks * 32);
#pragma unroll
        for (int mi = 0; mi < 4; mi++)
#pragma unroll
            for (int n2 = 0; n2 < 4; n2++) {
                mma_tf32(c[mi][2 * n2],     a[mi], b[n2][0], b[n2][1]);
                mma_tf32(c[mi][2 * n2 + 1], a[mi], b[n2][2], b[n2][3]);
            }
    }
}

__device__ __forceinline__ void gemm_mainloop(
    uint32_t aDstL, uint32_t aDstH, uint32_t bDst,
    const float* aSrcL, const float* aSrcH, uint32_t aSzL, uint32_t aSzH,
    const float* bSrc, int bKtot, int NIT,
    uint32_t aAddr, uint32_t bAddr, float c[4][8][4])
{
    issue_chunk(aDstL, aDstH, bDst, aSrcL, aSrcH, aSzL, aSzH, bSrc, bKtot, 0);
    for (int it = 0; it < NIT; ++it) {
        if (it + 1 < NIT) {
            int nb = (it + 1) & 1;
            issue_chunk(aDstL + nb * STAGE_B, aDstH + nb * STAGE_B, bDst + nb * STAGE_B,
                        aSrcL, aSrcH, aSzL, aSzH, bSrc, bKtot, (it + 1) * 32);
            CPA_WAIT1();
        } else {
            CPA_WAIT0();
        }
        __syncthreads();
        int buf = it & 1;
        mma_tile(aAddr + buf * STAGE_B, bAddr + buf * STAGE_B, c);
        __syncthreads();
    }
}

__global__ __launch_bounds__(128, 2)
void gemm1_mma(const float* __restrict__ b1) {
    extern __shared__ __align__(16) char smem[];
    const int tid = threadIdx.x, wid = tid >> 5, lane = tid & 31;
    const int rowBase = blockIdx.x * 128, nBase = blockIdx.y * 128;
    if (rowBase >= g_segbase[NUM_EXP]) return;
    int expert = 0;
#pragma unroll
    for (int i = 1; i < NUM_EXP; i++) if (g_segbase[i] <= rowBase) expert = i;

    uint32_t sb = smem_u32(smem);
    const int am = tid >> 1, ak = (tid & 1) * 16;
    uint32_t aDstL = sb + (am * TS + ak) * 4;
    uint32_t aDstH = aDstL + 64 * TS * 4;
    uint32_t bDst  = sb + AS_BYTES + (((tid >> 3) * TS + (tid & 7) * 4)) * 4;

    const int tokL = g_permToken[rowBase + am];
    const int tokH = g_permToken[rowBase + am + 64];
    const float* aSrcL = g_xR + (size_t)(tokL < 0 ? 0 : tokL) * D_MODEL + ak;
    const float* aSrcH = g_xR + (size_t)(tokH < 0 ? 0 : tokH) * D_MODEL + ak;
    uint32_t aSzL = tokL < 0 ? 0u : 16u;
    uint32_t aSzH = tokH < 0 ? 0u : 16u;
    const float* bSrc = g_W1T + (size_t)expert * HIDDEN * D_MODEL
                      + (size_t)(nBase + (tid >> 3)) * D_MODEL + (tid & 7) * 4;

    const int gid = lane >> 2, tig = lane & 3;
    const int wr = (wid >> 1) * 64, wc = (wid & 1) * 64;
    // ldmatrix lane addressing
    const int ra = (lane & 7) + 8 * ((lane >> 3) & 1), ka = 4 * ((lane >> 4) & 1);
    const int rb = (lane & 7) + 8 * ((lane >> 4) & 1), kb = 4 * ((lane >> 3) & 1);
    uint32_t aAddr = sb + ((wr + ra) * TS + ka) * 4;
    uint32_t bAddr = sb + AS_BYTES + ((wc + rb) * TS + kb) * 4;

    float c[4][8][4];
#pragma unroll
    for (int mi = 0; mi < 4; mi++)
#pragma unroll
        for (int ni = 0; ni < 8; ni++)
#pragma unroll
            for (int q = 0; q < 4; q++) c[mi][ni][q] = 0.f;

    gemm_mainloop(aDstL, aDstH, bDst, aSrcL, aSrcH, aSzL, aSzH,
                  bSrc, D_MODEL, D_MODEL / 32, aAddr, bAddr, c);

    const float* bb = b1 + (size_t)expert * HIDDEN + nBase;
#pragma unroll
    for (int mi = 0; mi < 4; mi++) {
        int r0 = rowBase + wr + mi * 16 + gid;
#pragma unroll
        for (int ni = 0; ni < 8; ni++) {
            int col = wc + ni * 8 + tig * 2;
            float bias0 = __ldg(bb + col), bias1 = __ldg(bb + col + 1);
            float2 v0, v1;
            v0.x = tf32r(gelu_exact(c[mi][ni][0] + bias0));
            v0.y = tf32r(gelu_exact(c[mi][ni][1] + bias1));
            v1.x = tf32r(gelu_exact(c[mi][ni][2] + bias0));
            v1.y = tf32r(gelu_exact(c[mi][ni][3] + bias1));
            *(float2*)(g_h + (size_t)r0 * HIDDEN + nBase + col) = v0;
            *(float2*)(g_h + (size_t)(r0 + 8) * HIDDEN + nBase + col) = v1;
        }
    }
}

__global__ __launch_bounds__(128, 2)
void gemm2_mma(const float* __restrict__ b2, float* __restrict__ out) {
    extern __shared__ __align__(16) char smem[];
    const int tid = threadIdx.x, wid = tid >> 5, lane = tid & 31;
    const int rowBase = blockIdx.x * 128, nBase = blockIdx.y * 128;
    if (rowBase >= g_segbase[NUM_EXP]) return;
    int expert = 0;
#pragma unroll
    for (int i = 1; i < NUM_EXP; i++) if (g_segbase[i] <= rowBase) expert = i;

    uint32_t sb = smem_u32(smem);
    const int am = tid >> 1, ak = (tid & 1) * 16;
    uint32_t aDstL = sb + (am * TS + ak) * 4;
    uint32_t aDstH = aDstL + 64 * TS * 4;
    uint32_t bDst  = sb + AS_BYTES + (((tid >> 3) * TS + (tid & 7) * 4)) * 4;

    const float* aSrcL = g_h + (size_t)(rowBase + am) * HIDDEN + ak;
    const float* aSrcH = g_h + (size_t)(rowBase + am + 64) * HIDDEN + ak;
    const float* bSrc = g_W2T + (size_t)expert * N2PAD * HIDDEN
                      + (size_t)(nBase + (tid >> 3)) * HIDDEN + (tid & 7) * 4;

    const int gid = lane >> 2, tig = lane & 3;
    const int wr = (wid >> 1) * 64, wc = (wid & 1) * 64;
    const int ra = (lane & 7) + 8 * ((lane >> 3) & 1), ka = 4 * ((lane >> 4) & 1);
    const int rb = (lane & 7) + 8 * ((lane >> 4) & 1), kb = 4 * ((lane >> 3) & 1);
    uint32_t aAddr = sb + ((wr + ra) * TS + ka) * 4;
    uint32_t bAddr = sb + AS_BYTES + ((wc + rb) * TS + kb) * 4;

    float c[4][8][4];
#pragma unroll
    for (int mi = 0; mi < 4; mi++)
#pragma unroll
        for (int ni = 0; ni < 8; ni++)
#pragma unroll
            for (int q = 0; q < 4; q++) c[mi][ni][q] = 0.f;

    gemm_mainloop(aDstL, aDstH, bDst, aSrcL, aSrcH, 16u, 16u,
                  bSrc, HIDDEN, HIDDEN / 32, aAddr, bAddr, c);

    const float* bb = b2 + (size_t)expert * NUM_CLS;
#pragma unroll
    for (int mi = 0; mi < 4; mi++) {
        int r0 = rowBase + wr + mi * 16 + gid;
#pragma unroll
        for (int half = 0; half < 2; half++) {
            int r = r0 + half * 8;
            int pair = g_permPair[r];
            if (pair < 0) continue;
            float gate = g_permGate[r];
            float* orow = out + (size_t)(pair >> 1) * NUM_CLS;
#pragma unroll
            for (int ni = 0; ni < 8; ni++) {
                int col = nBase + wc + ni * 8 + tig * 2;
                if (col < NUM_CLS)
                    atomicAdd(orow + col, gate * (c[mi][ni][half * 2 + 0] + __ldg(bb + col)));
                if (col + 1 < NUM_CLS)
                    atomicAdd(orow + col + 1, gate * (c[mi][ni][half * 2 + 1] + __ldg(bb + col + 1)));
            }
        }
    }
}

// ---------------- tail -------------------------------------------------------
__global__ void tail_kernel(float* __restrict__ out, int out_size) {
    int i = blockIdx.x * blockDim.x + threadIdx.x;
    const int OUT0 = BATCH * NUM_CLS;
    if (out_size >= OUT0 + BATCH * NUM_EXP) {
        if (i < BATCH * NUM_EXP)
            out[OUT0 + i] = g_gates[i];
        if (out_size >= OUT0 + BATCH * NUM_EXP + BATCH * TOPK && i < BATCH * TOPK)
            out[OUT0 + BATCH * NUM_EXP + i] = (float)g_topi[i];
    }
}

// ---------------------------------------------------------------------------
extern "C" void kernel_launch(void* const* d_in, const int* in_sizes, int n_in,
                              void* d_out, int out_size) {
    const float* x  = (const float*)d_in[0];
    const float* Wg = (const float*)d_in[1];
    const float* bg = (const float*)d_in[2];
    const float* W1 = (const float*)d_in[3];
    const float* b1 = (const float*)d_in[4];
    const float* W2 = (const float*)d_in[5];
    const float* b2 = (const float*)d_in[6];
    float* out = (float*)d_out;

    cudaFuncSetAttribute(gemm1_mma, cudaFuncAttributeMaxDynamicSharedMemorySize, SMEM_TOT);
    cudaFuncSetAttribute(gemm2_mma, cudaFuncAttributeMaxDynamicSharedMemorySize, SMEM_TOT);

    // ncu profiles launch index 4 -> gemm1_mma.
    cudaMemsetAsync(d_out, 0, (size_t)out_size * sizeof(float));             // 0
    prep_kernel<<<2048, 256>>>(x, Wg, bg);                                   // 1
    transpose_kernel<<<dim3(128, 160, NUM_EXP), dim3(32, 8)>>>(W1, W2);      // 2
    scatter_kernel<<<(NPAIR + 255) / 256, 256>>>();                          // 3
    gemm1_mma<<<dim3(MAX_TILES, HIDDEN / 128), 128, SMEM_TOT>>>(b1);         // 4 <- ncu
    gemm2_mma<<<dim3(MAX_TILES, N2PAD / 128), 128, SMEM_TOT>>>(b2, out);     // 5
    tail_kernel<<<(BATCH * NUM_EXP + 255) / 256, 256>>>(out, out_size);      // 6
}

// round 9
// speedup vs baseline: 1.8377x; 1.0828x over previous
#include <cuda_runtime.h>
#include <cuda_fp16.h>
#include <math.h>
#include <stdint.h>

// ---------------------------------------------------------------------------
// MoE top-2/8: two fp16 mma.sync (m16n8k16, fp32 accum) GEMMs, ldmatrix
// fragment loads, transposed fp16 K-contig weight scratch, 2-stage cp.async.
// ---------------------------------------------------------------------------

#define BATCH      8192
#define D_MODEL    1024
#define HIDDEN     4096
#define NUM_CLS    1000
#define N2PAD      1024
#define NUM_EXP    8
#define TOPK       2
#define NPAIR      (BATCH * TOPK)
#define MAX_TILES  136
#define CAP        (MAX_TILES * 128)

// ---------------- scratch ---------------------------------------------------
__device__ __half g_h[(size_t)CAP * HIDDEN];                    // fp16 acts
__device__ __half g_xH[(size_t)BATCH * D_MODEL];                // fp16 x
__device__ __half g_W1T[(size_t)NUM_EXP * HIDDEN * D_MODEL];    // [e][n][k]
__device__ __half g_W2T[(size_t)NUM_EXP * N2PAD * HIDDEN];      // [e][n][k]
__device__ float g_gates[BATCH * NUM_EXP];
__device__ int   g_topi[BATCH * TOPK];
__device__ int   g_pairExpert[NPAIR];
__device__ float g_pairGate[NPAIR];
__device__ int   g_counts[NUM_EXP];
__device__ int   g_segbase[NUM_EXP + 1];
__device__ int   g_cursor[NUM_EXP];
__device__ int   g_permToken[CAP];
__device__ int   g_permPair[CAP];
__device__ float g_permGate[CAP];
__device__ unsigned g_done;

__device__ __forceinline__ float gelu_exact(float v) {
    return 0.5f * v * (1.0f + erff(v * 0.70710678118654752f));
}
__device__ __forceinline__ uint32_t smem_u32(const void* p) {
    uint32_t a;
    asm("{ .reg .u64 t; cvta.to.shared.u64 t, %1; cvt.u32.u64 %0, t; }" : "=r"(a) : "l"(p));
    return a;
}

#define CPA16(dst, src)        asm volatile("cp.async.ca.shared.global [%0], [%1], 16;" :: "r"(dst), "l"(src))
#define CPA16_SZ(dst, src, sz) asm volatile("cp.async.ca.shared.global [%0], [%1], 16, %2;" :: "r"(dst), "l"(src), "r"(sz))
#define CPA_COMMIT()           asm volatile("cp.async.commit_group;" ::: "memory")
#define CPA_WAIT1()            asm volatile("cp.async.wait_group 1;" ::: "memory")
#define CPA_WAIT0()            asm volatile("cp.async.wait_group 0;" ::: "memory")

__device__ __forceinline__ void mma_f16(float* c, const uint32_t* a, uint32_t b0, uint32_t b1) {
    asm volatile("mma.sync.aligned.m16n8k16.row.col.f32.f16.f16.f32 "
                 "{%0,%1,%2,%3}, {%4,%5,%6,%7}, {%8,%9}, {%0,%1,%2,%3};"
                 : "+f"(c[0]), "+f"(c[1]), "+f"(c[2]), "+f"(c[3])
                 : "r"(a[0]), "r"(a[1]), "r"(a[2]), "r"(a[3]), "r"(b0), "r"(b1));
}
__device__ __forceinline__ void ldsm4(uint32_t* r, uint32_t addr) {
    asm volatile("ldmatrix.sync.aligned.m8n8.x4.shared.b16 {%0,%1,%2,%3}, [%4];"
                 : "=r"(r[0]), "=r"(r[1]), "=r"(r[2]), "=r"(r[3]) : "r"(addr));
}

// ---------------- L1: prep = init + x->fp16 + router + scan -----------------
__global__ void prep_kernel(const float* __restrict__ x,
                            const float* __restrict__ Wg,
                            const float* __restrict__ bg) {
    size_t tid0 = blockIdx.x * blockDim.x + threadIdx.x;
    size_t nthr = (size_t)gridDim.x * blockDim.x;

    if (tid0 < CAP) { g_permToken[tid0] = -1; g_permPair[tid0] = -1; }
    if (tid0 < NUM_EXP) g_counts[tid0] = 0;

    if (blockIdx.x < BATCH / 8) {
        int gwarp = (blockIdx.x * blockDim.x + threadIdx.x) >> 5;
        int lane  = threadIdx.x & 31;
        const float* xr = x + (size_t)gwarp * D_MODEL;
        float acc[NUM_EXP];
#pragma unroll
        for (int e = 0; e < NUM_EXP; e++) acc[e] = 0.f;
        for (int k0 = lane * 4; k0 < D_MODEL; k0 += 128) {
            float4 xv = *(const float4*)(xr + k0);
            const float* xs = (const float*)&xv;
#pragma unroll
            for (int kk = 0; kk < 4; kk++) {
                const float4* wg = (const float4*)(Wg + (size_t)(k0 + kk) * NUM_EXP);
                float4 w0 = wg[0], w1 = wg[1];
                float xk = xs[kk];
                acc[0] += xk * w0.x; acc[1] += xk * w0.y;
                acc[2] += xk * w0.z; acc[3] += xk * w0.w;
                acc[4] += xk * w1.x; acc[5] += xk * w1.y;
                acc[6] += xk * w1.z; acc[7] += xk * w1.w;
            }
        }
#pragma unroll
        for (int off = 16; off; off >>= 1)
#pragma unroll
            for (int e = 0; e < NUM_EXP; e++)
                acc[e] += __shfl_xor_sync(0xFFFFFFFFu, acc[e], off);
        if (lane == 0) {
            float v[NUM_EXP];
#pragma unroll
            for (int e = 0; e < NUM_EXP; e++) v[e] = acc[e] + bg[e];
            int i1 = 0;
#pragma unroll
            for (int e = 1; e < NUM_EXP; e++) if (v[e] > v[i1]) i1 = e;
            int i2 = -1;
#pragma unroll
            for (int e = 0; e < NUM_EXP; e++)
                if (e != i1 && (i2 < 0 || v[e] > v[i2])) i2 = e;
            float e2 = expf(v[i2] - v[i1]);
            float g1 = 1.f / (1.f + e2), g2 = e2 / (1.f + e2);
#pragma unroll
            for (int e = 0; e < NUM_EXP; e++) g_gates[gwarp * NUM_EXP + e] = 0.f;
            g_gates[gwarp * NUM_EXP + i1] = g1;
            g_gates[gwarp * NUM_EXP + i2] = g2;
            g_topi[gwarp * TOPK + 0] = i1;
            g_topi[gwarp * TOPK + 1] = i2;
            g_pairExpert[gwarp * TOPK + 0] = i1;
            g_pairExpert[gwarp * TOPK + 1] = i2;
            g_pairGate[gwarp * TOPK + 0] = g1;
            g_pairGate[gwarp * TOPK + 1] = g2;
            atomicAdd(&g_counts[i1], 1);
            atomicAdd(&g_counts[i2], 1);
        }
        __syncthreads();
        if (threadIdx.x == 0) {
            __threadfence();
            unsigned ticket = atomicAdd(&g_done, 1u);
            if (ticket == BATCH / 8 - 1) {
                int base = 0;
#pragma unroll
                for (int e = 0; e < NUM_EXP; e++) {
                    g_segbase[e] = base;
                    g_cursor[e]  = base;
                    base += ((g_counts[e] + 127) >> 7) << 7;
                }
                g_segbase[NUM_EXP] = base;
                g_done = 0;
                __threadfence();
            }
        }
    }

    for (size_t i = tid0; i < (size_t)BATCH * D_MODEL / 4; i += nthr) {
        float4 v = ((const float4*)x)[i];
        __half2 h0 = __floats2half2_rn(v.x, v.y);
        __half2 h1 = __floats2half2_rn(v.z, v.w);
        ((__half2*)g_xH)[i * 2]     = h0;
        ((__half2*)g_xH)[i * 2 + 1] = h1;
    }
}

// ---------------- L2: transpose weights to [e][n][k] fp16 -------------------
__global__ void transpose_kernel(const float* __restrict__ W1,
                                 const float* __restrict__ W2) {
    __shared__ float t[32][33];
    int e = blockIdx.z;
    int tx = threadIdx.x, ty = threadIdx.y;
    if (blockIdx.y < 32) {
        int nB = blockIdx.x * 32, kB = blockIdx.y * 32;
        const float* src = W1 + (size_t)e * D_MODEL * HIDDEN;
        __half* dst = g_W1T + (size_t)e * HIDDEN * D_MODEL;
#pragma unroll
        for (int i = 0; i < 32; i += 8)
            t[ty + i][tx] = src[(size_t)(kB + ty + i) * HIDDEN + nB + tx];
        __syncthreads();
#pragma unroll
        for (int i = 0; i < 32; i += 8)
            dst[(size_t)(nB + ty + i) * D_MODEL + kB + tx] = __float2half_rn(t[tx][ty + i]);
    } else {
        int nB = blockIdx.x * 32, kB = (blockIdx.y - 32) * 32;
        if (nB >= N2PAD) return;
        const float* src = W2 + (size_t)e * HIDDEN * NUM_CLS;
        __half* dst = g_W2T + (size_t)e * N2PAD * HIDDEN;
#pragma unroll
        for (int i = 0; i < 32; i += 8) {
            int n = nB + tx;
            t[ty + i][tx] = (n < NUM_CLS) ? src[(size_t)(kB + ty + i) * NUM_CLS + n] : 0.f;
        }
        __syncthreads();
#pragma unroll
        for (int i = 0; i < 32; i += 8)
            dst[(size_t)(nB + ty + i) * HIDDEN + kB + tx] = __float2half_rn(t[tx][ty + i]);
    }
}

// ---------------- L3: scatter ------------------------------------------------
__global__ void scatter_kernel() {
    int p = blockIdx.x * blockDim.x + threadIdx.x;
    if (p >= NPAIR) return;
    int e = g_pairExpert[p];
    int pos = atomicAdd(&g_cursor[e], 1);
    g_permToken[pos] = p >> 1;
    g_permPair[pos]  = p;
    g_permGate[pos]  = g_pairGate[p];
}

// ---------------- fp16 mma GEMMs --------------------------------------------
// 128 threads (4 warps 2x2), CTA tile 128x128, warp tile 64x64, BK=32 fp16,
// 2-stage cp.async. SMEM rows: 32 fp16 data padded to 40 (80B), conflict-free.
#define TSH       40
#define ROWB      (TSH * 2)                        // 80 bytes/row
#define A_BYTES   (128 * ROWB)                     // 10240
#define B_BYTES   (128 * ROWB)                     // 10240
#define STAGE_B   (A_BYTES + B_BYTES)              // 20480
#define SMEM_TOT  (2 * STAGE_B)                    // 40960

// copy roles: thread t handles A row t and B n-row t (64B each = 4 x 16B).
__device__ __forceinline__ void issue_chunk(
    uint32_t aDst, uint32_t bDst,
    const __half* aSrc, uint32_t aSz, const __half* bSrc, int kt)
{
#pragma unroll
    for (int j = 0; j < 4; j++)
        CPA16_SZ(aDst + j * 16, aSrc + kt + j * 8, aSz);
#pragma unroll
    for (int j = 0; j < 4; j++)
        CPA16(bDst + j * 16, bSrc + kt + j * 8);
    CPA_COMMIT();
}

// ldmatrix fragment loads + 32 m16n8k16 MMAs per ks; 2 ks per chunk.
__device__ __forceinline__ void mma_tile(uint32_t aAddr, uint32_t bAddr,
                                         float c[4][8][4]) {
#pragma unroll
    for (int ks = 0; ks < 2; ks++) {
        uint32_t a[4][4], b[4][4];
#pragma unroll
        for (int mi = 0; mi < 4; mi++)
            ldsm4(a[mi], aAddr + mi * (16 * ROWB) + ks * 32);
#pragma unroll
        for (int n2 = 0; n2 < 4; n2++)
            ldsm4(b[n2], bAddr + n2 * (16 * ROWB) + ks * 32);
#pragma unroll
        for (int mi = 0; mi < 4; mi++)
#pragma unroll
            for (int n2 = 0; n2 < 4; n2++) {
                mma_f16(c[mi][2 * n2],     a[mi], b[n2][0], b[n2][1]);
                mma_f16(c[mi][2 * n2 + 1], a[mi], b[n2][2], b[n2][3]);
            }
    }
}

__device__ __forceinline__ void gemm_mainloop(
    uint32_t aDst, uint32_t bDst,
    const __half* aSrc, uint32_t aSz, const __half* bSrc, int NIT,
    uint32_t aAddr, uint32_t bAddr, char* smem, float c[4][8][4])
{
    issue_chunk(aDst, bDst, aSrc, aSz, bSrc, 0);
    for (int it = 0; it < NIT; ++it) {
        if (it + 1 < NIT) {
            int nb = (it + 1) & 1;
            issue_chunk(aDst + nb * STAGE_B, bDst + nb * STAGE_B,
                        aSrc, aSz, bSrc, (it + 1) * 32);
            CPA_WAIT1();
        } else {
            CPA_WAIT0();
        }
        __syncthreads();
        int buf = it & 1;
        mma_tile(aAddr + buf * STAGE_B, bAddr + buf * STAGE_B, c);
        __syncthreads();
    }
}

__global__ __launch_bounds__(128, 2)
void gemm1_mma(const float* __restrict__ b1) {
    extern __shared__ __align__(16) char smem[];
    const int tid = threadIdx.x, wid = tid >> 5, lane = tid & 31;
    const int rowBase = blockIdx.x * 128, nBase = blockIdx.y * 128;
    if (rowBase >= g_segbase[NUM_EXP]) return;
    int expert = 0;
#pragma unroll
    for (int i = 1; i < NUM_EXP; i++) if (g_segbase[i] <= rowBase) expert = i;

    uint32_t sb = smem_u32(smem);
    uint32_t aDst = sb + tid * ROWB;
    uint32_t bDst = sb + A_BYTES + tid * ROWB;

    const int tok = g_permToken[rowBase + tid];
    const __half* aSrc = g_xH + (size_t)(tok < 0 ? 0 : tok) * D_MODEL;
    uint32_t aSz = tok < 0 ? 0u : 16u;
    const __half* bSrc = g_W1T + (size_t)expert * HIDDEN * D_MODEL
                       + (size_t)(nBase + tid) * D_MODEL;

    const int gid = lane >> 2, tig = lane & 3;
    const int wr = (wid >> 1) * 64, wc = (wid & 1) * 64;
    const int g8 = lane >> 3, r8 = lane & 7;
    uint32_t aAddr = sb + (wr + (g8 & 1) * 8 + r8) * ROWB + (g8 >> 1) * 16;
    uint32_t bAddr = sb + A_BYTES + (wc + (g8 >> 1) * 8 + r8) * ROWB + (g8 & 1) * 16;

    float c[4][8][4];
#pragma unroll
    for (int mi = 0; mi < 4; mi++)
#pragma unroll
        for (int ni = 0; ni < 8; ni++)
#pragma unroll
            for (int q = 0; q < 4; q++) c[mi][ni][q] = 0.f;

    gemm_mainloop(aDst, bDst, aSrc, aSz, bSrc, D_MODEL / 32, aAddr, bAddr, smem, c);

    const float* bb = b1 + (size_t)expert * HIDDEN + nBase;
#pragma unroll
    for (int mi = 0; mi < 4; mi++) {
        int r0 = rowBase + wr + mi * 16 + gid;
#pragma unroll
        for (int ni = 0; ni < 8; ni++) {
            int col = wc + ni * 8 + tig * 2;
            float bias0 = __ldg(bb + col), bias1 = __ldg(bb + col + 1);
            __half2 v0 = __floats2half2_rn(gelu_exact(c[mi][ni][0] + bias0),
                                           gelu_exact(c[mi][ni][1] + bias1));
            __half2 v1 = __floats2half2_rn(gelu_exact(c[mi][ni][2] + bias0),
                                           gelu_exact(c[mi][ni][3] + bias1));
            *(__half2*)(g_h + (size_t)r0 * HIDDEN + nBase + col) = v0;
            *(__half2*)(g_h + (size_t)(r0 + 8) * HIDDEN + nBase + col) = v1;
        }
    }
}

__global__ __launch_bounds__(128, 2)
void gemm2_mma(const float* __restrict__ b2, float* __restrict__ out) {
    extern __shared__ __align__(16) char smem[];
    const int tid = threadIdx.x, wid = tid >> 5, lane = tid & 31;
    const int rowBase = blockIdx.x * 128, nBase = blockIdx.y * 128;
    if (rowBase >= g_segbase[NUM_EXP]) return;
    int expert = 0;
#pragma unroll
    for (int i = 1; i < NUM_EXP; i++) if (g_segbase[i] <= rowBase) expert = i;

    uint32_t sb = smem_u32(smem);
    uint32_t aDst = sb + tid * ROWB;
    uint32_t bDst = sb + A_BYTES + tid * ROWB;

    const __half* aSrc = g_h + (size_t)(rowBase + tid) * HIDDEN;
    const __half* bSrc = g_W2T + (size_t)expert * N2PAD * HIDDEN
                       + (size_t)(nBase + tid) * HIDDEN;

    const int gid = lane >> 2, tig = lane & 3;
    const int wr = (wid >> 1) * 64, wc = (wid & 1) * 64;
    const int g8 = lane >> 3, r8 = lane & 7;
    uint32_t aAddr = sb + (wr + (g8 & 1) * 8 + r8) * ROWB + (g8 >> 1) * 16;
    uint32_t bAddr = sb + A_BYTES + (wc + (g8 >> 1) * 8 + r8) * ROWB + (g8 & 1) * 16;

    float c[4][8][4];
#pragma unroll
    for (int mi = 0; mi < 4; mi++)
#pragma unroll
        for (int ni = 0; ni < 8; ni++)
#pragma unroll
            for (int q = 0; q < 4; q++) c[mi][ni][q] = 0.f;

    gemm_mainloop(aDst, bDst, aSrc, 16u, bSrc, HIDDEN / 32, aAddr, bAddr, smem, c);

    const float* bb = b2 + (size_t)expert * NUM_CLS;
#pragma unroll
    for (int mi = 0; mi < 4; mi++) {
        int r0 = rowBase + wr + mi * 16 + gid;
#pragma unroll
        for (int half = 0; half < 2; half++) {
            int r = r0 + half * 8;
            int pair = g_permPair[r];
            if (pair < 0) continue;
            float gate = g_permGate[r];
            float* orow = out + (size_t)(pair >> 1) * NUM_CLS;
#pragma unroll
            for (int ni = 0; ni < 8; ni++) {
                int col = nBase + wc + ni * 8 + tig * 2;
                if (col < NUM_CLS)
                    atomicAdd(orow + col, gate * (c[mi][ni][half * 2 + 0] + __ldg(bb + col)));
                if (col + 1 < NUM_CLS)
                    atomicAdd(orow + col + 1, gate * (c[mi][ni][half * 2 + 1] + __ldg(bb + col + 1)));
            }
        }
    }
}

// ---------------- tail -------------------------------------------------------
__global__ void tail_kernel(float* __restrict__ out, int out_size) {
    int i = blockIdx.x * blockDim.x + threadIdx.x;
    const int OUT0 = BATCH * NUM_CLS;
    if (out_size >= OUT0 + BATCH * NUM_EXP) {
        if (i < BATCH * NUM_EXP)
            out[OUT0 + i] = g_gates[i];
        if (out_size >= OUT0 + BATCH * NUM_EXP + BATCH * TOPK && i < BATCH * TOPK)
            out[OUT0 + BATCH * NUM_EXP + i] = (float)g_topi[i];
    }
}

// ---------------------------------------------------------------------------
extern "C" void kernel_launch(void* const* d_in, const int* in_sizes, int n_in,
                              void* d_out, int out_size) {
    const float* x  = (const float*)d_in[0];
    const float* Wg = (const float*)d_in[1];
    const float* bg = (const float*)d_in[2];
    const float* W1 = (const float*)d_in[3];
    const float* b1 = (const float*)d_in[4];
    const float* W2 = (const float*)d_in[5];
    const float* b2 = (const float*)d_in[6];
    float* out = (float*)d_out;

    cudaFuncSetAttribute(gemm1_mma, cudaFuncAttributeMaxDynamicSharedMemorySize, SMEM_TOT);
    cudaFuncSetAttribute(gemm2_mma, cudaFuncAttributeMaxDynamicSharedMemorySize, SMEM_TOT);

    // ncu profiles launch index 4 -> gemm1_mma.
    cudaMemsetAsync(d_out, 0, (size_t)out_size * sizeof(float));             // 0
    prep_kernel<<<2048, 256>>>(x, Wg, bg);                                   // 1
    transpose_kernel<<<dim3(128, 160, NUM_EXP), dim3(32, 8)>>>(W1, W2);      // 2
    scatter_kernel<<<(NPAIR + 255) / 256, 256>>>();                          // 3
    gemm1_mma<<<dim3(MAX_TILES, HIDDEN / 128), 128, SMEM_TOT>>>(b1);         // 4 <- ncu
    gemm2_mma<<<dim3(MAX_TILES, N2PAD / 128), 128, SMEM_TOT>>>(b2, out);     // 5
    tail_kernel<<<(BATCH * NUM_EXP + 255) / 256, 256>>>(out, out_size);      // 6
}

// round 10
// speedup vs baseline: 1.8433x; 1.0030x over previous
#include <cuda_runtime.h>
#include <cuda_fp16.h>
#include <math.h>
#include <stdint.h>

// ---------------------------------------------------------------------------
// MoE top-2/8: fp16 m16n8k16 mma.sync GEMMs (fp32 accum), ldmatrix fragments,
// BK=64, cp.async.cg (L1-bypass fill), 2-stage pipeline.
// ---------------------------------------------------------------------------

#define BATCH      8192
#define D_MODEL    1024
#define HIDDEN     4096
#define NUM_CLS    1000
#define N2PAD      1024
#define NUM_EXP    8
#define TOPK       2
#define NPAIR      (BATCH * TOPK)
#define MAX_TILES  136
#define CAP        (MAX_TILES * 128)

// ---------------- scratch ---------------------------------------------------
__device__ __half g_h[(size_t)CAP * HIDDEN];
__device__ __half g_xH[(size_t)BATCH * D_MODEL];
__device__ __half g_W1T[(size_t)NUM_EXP * HIDDEN * D_MODEL];    // [e][n][k]
__device__ __half g_W2T[(size_t)NUM_EXP * N2PAD * HIDDEN];      // [e][n][k]
__device__ float g_gates[BATCH * NUM_EXP];
__device__ int   g_topi[BATCH * TOPK];
__device__ int   g_pairExpert[NPAIR];
__device__ float g_pairGate[NPAIR];
__device__ int   g_counts[NUM_EXP];
__device__ int   g_segbase[NUM_EXP + 1];
__device__ int   g_cursor[NUM_EXP];
__device__ int   g_permToken[CAP];
__device__ int   g_permPair[CAP];
__device__ float g_permGate[CAP];
__device__ unsigned g_done;

__device__ __forceinline__ float gelu_exact(float v) {
    return 0.5f * v * (1.0f + erff(v * 0.70710678118654752f));
}
__device__ __forceinline__ uint32_t smem_u32(const void* p) {
    uint32_t a;
    asm("{ .reg .u64 t; cvta.to.shared.u64 t, %1; cvt.u32.u64 %0, t; }" : "=r"(a) : "l"(p));
    return a;
}

#define CPG16(dst, src)        asm volatile("cp.async.cg.shared.global [%0], [%1], 16;" :: "r"(dst), "l"(src))
#define CPG16_SZ(dst, src, sz) asm volatile("cp.async.cg.shared.global [%0], [%1], 16, %2;" :: "r"(dst), "l"(src), "r"(sz))
#define CPA_COMMIT()           asm volatile("cp.async.commit_group;" ::: "memory")
#define CPA_WAIT1()            asm volatile("cp.async.wait_group 1;" ::: "memory")
#define CPA_WAIT0()            asm volatile("cp.async.wait_group 0;" ::: "memory")

__device__ __forceinline__ void mma_f16(float* c, const uint32_t* a, uint32_t b0, uint32_t b1) {
    asm volatile("mma.sync.aligned.m16n8k16.row.col.f32.f16.f16.f32 "
                 "{%0,%1,%2,%3}, {%4,%5,%6,%7}, {%8,%9}, {%0,%1,%2,%3};"
                 : "+f"(c[0]), "+f"(c[1]), "+f"(c[2]), "+f"(c[3])
                 : "r"(a[0]), "r"(a[1]), "r"(a[2]), "r"(a[3]), "r"(b0), "r"(b1));
}
__device__ __forceinline__ void ldsm4(uint32_t* r, uint32_t addr) {
    asm volatile("ldmatrix.sync.aligned.m8n8.x4.shared.b16 {%0,%1,%2,%3}, [%4];"
                 : "=r"(r[0]), "=r"(r[1]), "=r"(r[2]), "=r"(r[3]) : "r"(addr));
}

// ---------------- L1: prep = init + x->fp16 + router + scan -----------------
__global__ void prep_kernel(const float* __restrict__ x,
                            const float* __restrict__ Wg,
                            const float* __restrict__ bg) {
    size_t tid0 = blockIdx.x * blockDim.x + threadIdx.x;
    size_t nthr = (size_t)gridDim.x * blockDim.x;

    if (tid0 < CAP) { g_permToken[tid0] = -1; g_permPair[tid0] = -1; }
    if (tid0 < NUM_EXP) g_counts[tid0] = 0;

    if (blockIdx.x < BATCH / 8) {
        int gwarp = (blockIdx.x * blockDim.x + threadIdx.x) >> 5;
        int lane  = threadIdx.x & 31;
        const float* xr = x + (size_t)gwarp * D_MODEL;
        float acc[NUM_EXP];
#pragma unroll
        for (int e = 0; e < NUM_EXP; e++) acc[e] = 0.f;
        for (int k0 = lane * 4; k0 < D_MODEL; k0 += 128) {
            float4 xv = *(const float4*)(xr + k0);
            const float* xs = (const float*)&xv;
#pragma unroll
            for (int kk = 0; kk < 4; kk++) {
                const float4* wg = (const float4*)(Wg + (size_t)(k0 + kk) * NUM_EXP);
                float4 w0 = wg[0], w1 = wg[1];
                float xk = xs[kk];
                acc[0] += xk * w0.x; acc[1] += xk * w0.y;
                acc[2] += xk * w0.z; acc[3] += xk * w0.w;
                acc[4] += xk * w1.x; acc[5] += xk * w1.y;
                acc[6] += xk * w1.z; acc[7] += xk * w1.w;
            }
        }
#pragma unroll
        for (int off = 16; off; off >>= 1)
#pragma unroll
            for (int e = 0; e < NUM_EXP; e++)
                acc[e] += __shfl_xor_sync(0xFFFFFFFFu, acc[e], off);
        if (lane == 0) {
            float v[NUM_EXP];
#pragma unroll
            for (int e = 0; e < NUM_EXP; e++) v[e] = acc[e] + bg[e];
            int i1 = 0;
#pragma unroll
            for (int e = 1; e < NUM_EXP; e++) if (v[e] > v[i1]) i1 = e;
            int i2 = -1;
#pragma unroll
            for (int e = 0; e < NUM_EXP; e++)
                if (e != i1 && (i2 < 0 || v[e] > v[i2])) i2 = e;
            float e2 = expf(v[i2] - v[i1]);
            float g1 = 1.f / (1.f + e2), g2 = e2 / (1.f + e2);
#pragma unroll
            for (int e = 0; e < NUM_EXP; e++) g_gates[gwarp * NUM_EXP + e] = 0.f;
            g_gates[gwarp * NUM_EXP + i1] = g1;
            g_gates[gwarp * NUM_EXP + i2] = g2;
            g_topi[gwarp * TOPK + 0] = i1;
            g_topi[gwarp * TOPK + 1] = i2;
            g_pairExpert[gwarp * TOPK + 0] = i1;
            g_pairExpert[gwarp * TOPK + 1] = i2;
            g_pairGate[gwarp * TOPK + 0] = g1;
            g_pairGate[gwarp * TOPK + 1] = g2;
            atomicAdd(&g_counts[i1], 1);
            atomicAdd(&g_counts[i2], 1);
        }
        __syncthreads();
        if (threadIdx.x == 0) {
            __threadfence();
            unsigned ticket = atomicAdd(&g_done, 1u);
            if (ticket == BATCH / 8 - 1) {
                int base = 0;
#pragma unroll
                for (int e = 0; e < NUM_EXP; e++) {
                    g_segbase[e] = base;
                    g_cursor[e]  = base;
                    base += ((g_counts[e] + 127) >> 7) << 7;
                }
                g_segbase[NUM_EXP] = base;
                g_done = 0;
                __threadfence();
            }
        }
    }

    for (size_t i = tid0; i < (size_t)BATCH * D_MODEL / 4; i += nthr) {
        float4 v = ((const float4*)x)[i];
        ((__half2*)g_xH)[i * 2]     = __floats2half2_rn(v.x, v.y);
        ((__half2*)g_xH)[i * 2 + 1] = __floats2half2_rn(v.z, v.w);
    }
}

// ---------------- L2: transpose weights to [e][n][k] fp16 -------------------
__global__ void transpose_kernel(const float* __restrict__ W1,
                                 const float* __restrict__ W2) {
    __shared__ float t[32][33];
    int e = blockIdx.z;
    int tx = threadIdx.x, ty = threadIdx.y;
    if (blockIdx.y < 32) {
        int nB = blockIdx.x * 32, kB = blockIdx.y * 32;
        const float* src = W1 + (size_t)e * D_MODEL * HIDDEN;
        __half* dst = g_W1T + (size_t)e * HIDDEN * D_MODEL;
#pragma unroll
        for (int i = 0; i < 32; i += 8)
            t[ty + i][tx] = src[(size_t)(kB + ty + i) * HIDDEN + nB + tx];
        __syncthreads();
#pragma unroll
        for (int i = 0; i < 32; i += 8)
            dst[(size_t)(nB + ty + i) * D_MODEL + kB + tx] = __float2half_rn(t[tx][ty + i]);
    } else {
        int nB = blockIdx.x * 32, kB = (blockIdx.y - 32) * 32;
        if (nB >= N2PAD) return;
        const float* src = W2 + (size_t)e * HIDDEN * NUM_CLS;
        __half* dst = g_W2T + (size_t)e * N2PAD * HIDDEN;
#pragma unroll
        for (int i = 0; i < 32; i += 8) {
            int n = nB + tx;
            t[ty + i][tx] = (n < NUM_CLS) ? src[(size_t)(kB + ty + i) * NUM_CLS + n] : 0.f;
        }
        __syncthreads();
#pragma unroll
        for (int i = 0; i < 32; i += 8)
            dst[(size_t)(nB + ty + i) * HIDDEN + kB + tx] = __float2half_rn(t[tx][ty + i]);
    }
}

// ---------------- L3: scatter ------------------------------------------------
__global__ void scatter_kernel() {
    int p = blockIdx.x * blockDim.x + threadIdx.x;
    if (p >= NPAIR) return;
    int e = g_pairExpert[p];
    int pos = atomicAdd(&g_cursor[e], 1);
    g_permToken[pos] = p >> 1;
    g_permPair[pos]  = p;
    g_permGate[pos]  = g_pairGate[p];
}

// ---------------- fp16 mma GEMMs --------------------------------------------
// 128 threads (4 warps 2x2), CTA tile 128x128, warp tile 64x64, BK=64 fp16,
// 2-stage cp.async.cg. Rows: 64 fp16 = 128B data padded to 144B (16r mod 128
// -> conflict-free ldmatrix).
#define ROWB      144
#define A_BYTES   (128 * ROWB)                     // 18432
#define B_BYTES   (128 * ROWB)                     // 18432
#define STAGE_B   (A_BYTES + B_BYTES)              // 36864
#define SMEM_TOT  (2 * STAGE_B)                    // 73728

// copy roles: thread t owns A row t and B n-row t: 128B = 8 x 16B each.
__device__ __forceinline__ void issue_chunk(
    uint32_t aDst, uint32_t bDst,
    const __half* aSrc, uint32_t aSz, const __half* bSrc, int kt)
{
#pragma unroll
    for (int j = 0; j < 8; j++)
        CPG16_SZ(aDst + j * 16, aSrc + kt + j * 8, aSz);
#pragma unroll
    for (int j = 0; j < 8; j++)
        CPG16(bDst + j * 16, bSrc + kt + j * 8);
    CPA_COMMIT();
}

// 4 ks (k16) per BK=64 chunk.
__device__ __forceinline__ void mma_tile(uint32_t aAddr, uint32_t bAddr,
                                         float c[4][8][4]) {
#pragma unroll
    for (int ks = 0; ks < 4; ks++) {
        uint32_t a[4][4], b[4][4];
#pragma unroll
        for (int mi = 0; mi < 4; mi++)
            ldsm4(a[mi], aAddr + mi * (16 * ROWB) + ks * 32);
#pragma unroll
        for (int n2 = 0; n2 < 4; n2++)
            ldsm4(b[n2], bAddr + n2 * (16 * ROWB) + ks * 32);
#pragma unroll
        for (int mi = 0; mi < 4; mi++)
#pragma unroll
            for (int n2 = 0; n2 < 4; n2++) {
                mma_f16(c[mi][2 * n2],     a[mi], b[n2][0], b[n2][1]);
                mma_f16(c[mi][2 * n2 + 1], a[mi], b[n2][2], b[n2][3]);
            }
    }
}

__device__ __forceinline__ void gemm_mainloop(
    uint32_t aDst, uint32_t bDst,
    const __half* aSrc, uint32_t aSz, const __half* bSrc, int NIT,
    uint32_t aAddr, uint32_t bAddr, float c[4][8][4])
{
    issue_chunk(aDst, bDst, aSrc, aSz, bSrc, 0);
    for (int it = 0; it < NIT; ++it) {
        if (it + 1 < NIT) {
            int nb = (it + 1) & 1;
            issue_chunk(aDst + nb * STAGE_B, bDst + nb * STAGE_B,
                        aSrc, aSz, bSrc, (it + 1) * 64);
            CPA_WAIT1();
        } else {
            CPA_WAIT0();
        }
        __syncthreads();
        int buf = it & 1;
        mma_tile(aAddr + buf * STAGE_B, bAddr + buf * STAGE_B, c);
        __syncthreads();
    }
}

__global__ __launch_bounds__(128, 2)
void gemm1_mma(const float* __restrict__ b1) {
    extern __shared__ __align__(16) char smem[];
    const int tid = threadIdx.x, wid = tid >> 5, lane = tid & 31;
    const int rowBase = blockIdx.x * 128, nBase = blockIdx.y * 128;
    if (rowBase >= g_segbase[NUM_EXP]) return;
    int expert = 0;
#pragma unroll
    for (int i = 1; i < NUM_EXP; i++) if (g_segbase[i] <= rowBase) expert = i;

    uint32_t sb = smem_u32(smem);
    uint32_t aDst = sb + tid * ROWB;
    uint32_t bDst = sb + A_BYTES + tid * ROWB;

    const int tok = g_permToken[rowBase + tid];
    const __half* aSrc = g_xH + (size_t)(tok < 0 ? 0 : tok) * D_MODEL;
    uint32_t aSz = tok < 0 ? 0u : 16u;
    const __half* bSrc = g_W1T + (size_t)expert * HIDDEN * D_MODEL
                       + (size_t)(nBase + tid) * D_MODEL;

    const int gid = lane >> 2, tig = lane & 3;
    const int wr = (wid >> 1) * 64, wc = (wid & 1) * 64;
    const int g8 = lane >> 3, r8 = lane & 7;
    uint32_t aAddr = sb + (wr + (g8 & 1) * 8 + r8) * ROWB + (g8 >> 1) * 16;
    uint32_t bAddr = sb + A_BYTES + (wc + (g8 >> 1) * 8 + r8) * ROWB + (g8 & 1) * 16;

    float c[4][8][4];
#pragma unroll
    for (int mi = 0; mi < 4; mi++)
#pragma unroll
        for (int ni = 0; ni < 8; ni++)
#pragma unroll
            for (int q = 0; q < 4; q++) c[mi][ni][q] = 0.f;

    gemm_mainloop(aDst, bDst, aSrc, aSz, bSrc, D_MODEL / 64, aAddr, bAddr, c);

    const float* bb = b1 + (size_t)expert * HIDDEN + nBase;
#pragma unroll
    for (int mi = 0; mi < 4; mi++) {
        int r0 = rowBase + wr + mi * 16 + gid;
#pragma unroll
        for (int ni = 0; ni < 8; ni++) {
            int col = wc + ni * 8 + tig * 2;
            float bias0 = __ldg(bb + col), bias1 = __ldg(bb + col + 1);
            __half2 v0 = __floats2half2_rn(gelu_exact(c[mi][ni][0] + bias0),
                                           gelu_exact(c[mi][ni][1] + bias1));
            __half2 v1 = __floats2half2_rn(gelu_exact(c[mi][ni][2] + bias0),
                                           gelu_exact(c[mi][ni][3] + bias1));
            *(__half2*)(g_h + (size_t)r0 * HIDDEN + nBase + col) = v0;
            *(__half2*)(g_h + (size_t)(r0 + 8) * HIDDEN + nBase + col) = v1;
        }
    }
}

__global__ __launch_bounds__(128, 2)
void gemm2_mma(const float* __restrict__ b2, float* __restrict__ out) {
    extern __shared__ __align__(16) char smem[];
    const int tid = threadIdx.x, wid = tid >> 5, lane = tid & 31;
    const int rowBase = blockIdx.x * 128, nBase = blockIdx.y * 128;
    if (rowBase >= g_segbase[NUM_EXP]) return;
    int expert = 0;
#pragma unroll
    for (int i = 1; i < NUM_EXP; i++) if (g_segbase[i] <= rowBase) expert = i;

    uint32_t sb = smem_u32(smem);
    uint32_t aDst = sb + tid * ROWB;
    uint32_t bDst = sb + A_BYTES + tid * ROWB;

    const __half* aSrc = g_h + (size_t)(rowBase + tid) * HIDDEN;
    const __half* bSrc = g_W2T + (size_t)expert * N2PAD * HIDDEN
                       + (size_t)(nBase + tid) * HIDDEN;

    const int gid = lane >> 2, tig = lane & 3;
    const int wr = (wid >> 1) * 64, wc = (wid & 1) * 64;
    const int g8 = lane >> 3, r8 = lane & 7;
    uint32_t aAddr = sb + (wr + (g8 & 1) * 8 + r8) * ROWB + (g8 >> 1) * 16;
    uint32_t bAddr = sb + A_BYTES + (wc + (g8 >> 1) * 8 + r8) * ROWB + (g8 & 1) * 16;

    float c[4][8][4];
#pragma unroll
    for (int mi = 0; mi < 4; mi++)
#pragma unroll
        for (int ni = 0; ni < 8; ni++)
#pragma unroll
            for (int q = 0; q < 4; q++) c[mi][ni][q] = 0.f;

    gemm_mainloop(aDst, bDst, aSrc, 16u, bSrc, HIDDEN / 64, aAddr, bAddr, c);

    const float* bb = b2 + (size_t)expert * NUM_CLS;
#pragma unroll
    for (int mi = 0; mi < 4; mi++) {
        int r0 = rowBase + wr + mi * 16 + gid;
#pragma unroll
        for (int half = 0; half < 2; half++) {
            int r = r0 + half * 8;
            int pair = g_permPair[r];
            if (pair < 0) continue;
            float gate = g_permGate[r];
            float* orow = out + (size_t)(pair >> 1) * NUM_CLS;
#pragma unroll
            for (int ni = 0; ni < 8; ni++) {
                int col = nBase + wc + ni * 8 + tig * 2;
                if (col < NUM_CLS)
                    atomicAdd(orow + col, gate * (c[mi][ni][half * 2 + 0] + __ldg(bb + col)));
                if (col + 1 < NUM_CLS)
                    atomicAdd(orow + col + 1, gate * (c[mi][ni][half * 2 + 1] + __ldg(bb + col + 1)));
            }
        }
    }
}

// ---------------- tail -------------------------------------------------------
__global__ void tail_kernel(float* __restrict__ out, int out_size) {
    int i = blockIdx.x * blockDim.x + threadIdx.x;
    const int OUT0 = BATCH * NUM_CLS;
    if (out_size >= OUT0 + BATCH * NUM_EXP) {
        if (i < BATCH * NUM_EXP)
            out[OUT0 + i] = g_gates[i];
        if (out_size >= OUT0 + BATCH * NUM_EXP + BATCH * TOPK && i < BATCH * TOPK)
            out[OUT0 + BATCH * NUM_EXP + i] = (float)g_topi[i];
    }
}

// ---------------------------------------------------------------------------
extern "C" void kernel_launch(void* const* d_in, const int* in_sizes, int n_in,
                              void* d_out, int out_size) {
    const float* x  = (const float*)d_in[0];
    const float* Wg = (const float*)d_in[1];
    const float* bg = (const float*)d_in[2];
    const float* W1 = (const float*)d_in[3];
    const float* b1 = (const float*)d_in[4];
    const float* W2 = (const float*)d_in[5];
    const float* b2 = (const float*)d_in[6];
    float* out = (float*)d_out;

    cudaFuncSetAttribute(gemm1_mma, cudaFuncAttributeMaxDynamicSharedMemorySize, SMEM_TOT);
    cudaFuncSetAttribute(gemm2_mma, cudaFuncAttributeMaxDynamicSharedMemorySize, SMEM_TOT);

    // ncu profiles launch index 4 -> gemm1_mma.
    cudaMemsetAsync(d_out, 0, (size_t)out_size * sizeof(float));             // 0
    prep_kernel<<<2048, 256>>>(x, Wg, bg);                                   // 1
    transpose_kernel<<<dim3(128, 160, NUM_EXP), dim3(32, 8)>>>(W1, W2);      // 2
    scatter_kernel<<<(NPAIR + 255) / 256, 256>>>();                          // 3
    gemm1_mma<<<dim3(MAX_TILES, HIDDEN / 128), 128, SMEM_TOT>>>(b1);         // 4 <- ncu
    gemm2_mma<<<dim3(MAX_TILES, N2PAD / 128), 128, SMEM_TOT>>>(b2, out);     // 5
    tail_kernel<<<(BATCH * NUM_EXP + 255) / 256, 256>>>(out, out_size);      // 6
}

// round 11
// speedup vs baseline: 2.1847x; 1.1852x over previous
#include <cuda_runtime.h>
#include <cuda_fp16.h>
#include <math.h>
#include <stdint.h>

// ---------------------------------------------------------------------------
// MoE top-2/8: fp16 m16n8k16 mma.sync GEMMs (fp32 accum), ldmatrix fragments,
// BK=64, cp.async.cg, 2-stage pipeline, 256-thread CTAs (8 warps x 64x32),
// 16 warps/SM for latency hiding.
// ---------------------------------------------------------------------------

#define BATCH      8192
#define D_MODEL    1024
#define HIDDEN     4096
#define NUM_CLS    1000
#define N2PAD      1024
#define NUM_EXP    8
#define TOPK       2
#define NPAIR      (BATCH * TOPK)
#define MAX_TILES  136
#define CAP        (MAX_TILES * 128)

// ---------------- scratch ---------------------------------------------------
__device__ __half g_h[(size_t)CAP * HIDDEN];
__device__ __half g_xH[(size_t)BATCH * D_MODEL];
__device__ __half g_W1T[(size_t)NUM_EXP * HIDDEN * D_MODEL];    // [e][n][k]
__device__ __half g_W2T[(size_t)NUM_EXP * N2PAD * HIDDEN];      // [e][n][k]
__device__ float g_gates[BATCH * NUM_EXP];
__device__ int   g_topi[BATCH * TOPK];
__device__ int   g_pairExpert[NPAIR];
__device__ float g_pairGate[NPAIR];
__device__ int   g_counts[NUM_EXP];
__device__ int   g_segbase[NUM_EXP + 1];
__device__ int   g_cursor[NUM_EXP];
__device__ int   g_permToken[CAP];
__device__ int   g_permPair[CAP];
__device__ float g_permGate[CAP];
__device__ unsigned g_done;

__device__ __forceinline__ float gelu_exact(float v) {
    return 0.5f * v * (1.0f + erff(v * 0.70710678118654752f));
}
__device__ __forceinline__ uint32_t smem_u32(const void* p) {
    uint32_t a;
    asm("{ .reg .u64 t; cvta.to.shared.u64 t, %1; cvt.u32.u64 %0, t; }" : "=r"(a) : "l"(p));
    return a;
}

#define CPG16(dst, src)        asm volatile("cp.async.cg.shared.global [%0], [%1], 16;" :: "r"(dst), "l"(src))
#define CPG16_SZ(dst, src, sz) asm volatile("cp.async.cg.shared.global [%0], [%1], 16, %2;" :: "r"(dst), "l"(src), "r"(sz))
#define CPA_COMMIT()           asm volatile("cp.async.commit_group;" ::: "memory")
#define CPA_WAIT1()            asm volatile("cp.async.wait_group 1;" ::: "memory")
#define CPA_WAIT0()            asm volatile("cp.async.wait_group 0;" ::: "memory")

__device__ __forceinline__ void mma_f16(float* c, const uint32_t* a, uint32_t b0, uint32_t b1) {
    asm volatile("mma.sync.aligned.m16n8k16.row.col.f32.f16.f16.f32 "
                 "{%0,%1,%2,%3}, {%4,%5,%6,%7}, {%8,%9}, {%0,%1,%2,%3};"
                 : "+f"(c[0]), "+f"(c[1]), "+f"(c[2]), "+f"(c[3])
                 : "r"(a[0]), "r"(a[1]), "r"(a[2]), "r"(a[3]), "r"(b0), "r"(b1));
}
__device__ __forceinline__ void ldsm4(uint32_t* r, uint32_t addr) {
    asm volatile("ldmatrix.sync.aligned.m8n8.x4.shared.b16 {%0,%1,%2,%3}, [%4];"
                 : "=r"(r[0]), "=r"(r[1]), "=r"(r[2]), "=r"(r[3]) : "r"(addr));
}

// ---------------- L1: prep = init + x->fp16 + router + scan -----------------
__global__ void prep_kernel(const float* __restrict__ x,
                            const float* __restrict__ Wg,
                            const float* __restrict__ bg) {
    size_t tid0 = blockIdx.x * blockDim.x + threadIdx.x;
    size_t nthr = (size_t)gridDim.x * blockDim.x;

    if (tid0 < CAP) { g_permToken[tid0] = -1; g_permPair[tid0] = -1; }
    if (tid0 < NUM_EXP) g_counts[tid0] = 0;

    if (blockIdx.x < BATCH / 8) {
        int gwarp = (blockIdx.x * blockDim.x + threadIdx.x) >> 5;
        int lane  = threadIdx.x & 31;
        const float* xr = x + (size_t)gwarp * D_MODEL;
        float acc[NUM_EXP];
#pragma unroll
        for (int e = 0; e < NUM_EXP; e++) acc[e] = 0.f;
        for (int k0 = lane * 4; k0 < D_MODEL; k0 += 128) {
            float4 xv = *(const float4*)(xr + k0);
            const float* xs = (const float*)&xv;
#pragma unroll
            for (int kk = 0; kk < 4; kk++) {
                const float4* wg = (const float4*)(Wg + (size_t)(k0 + kk) * NUM_EXP);
                float4 w0 = wg[0], w1 = wg[1];
                float xk = xs[kk];
                acc[0] += xk * w0.x; acc[1] += xk * w0.y;
                acc[2] += xk * w0.z; acc[3] += xk * w0.w;
                acc[4] += xk * w1.x; acc[5] += xk * w1.y;
                acc[6] += xk * w1.z; acc[7] += xk * w1.w;
            }
        }
#pragma unroll
        for (int off = 16; off; off >>= 1)
#pragma unroll
            for (int e = 0; e < NUM_EXP; e++)
                acc[e] += __shfl_xor_sync(0xFFFFFFFFu, acc[e], off);
        if (lane == 0) {
            float v[NUM_EXP];
#pragma unroll
            for (int e = 0; e < NUM_EXP; e++) v[e] = acc[e] + bg[e];
            int i1 = 0;
#pragma unroll
            for (int e = 1; e < NUM_EXP; e++) if (v[e] > v[i1]) i1 = e;
            int i2 = -1;
#pragma unroll
            for (int e = 0; e < NUM_EXP; e++)
                if (e != i1 && (i2 < 0 || v[e] > v[i2])) i2 = e;
            float e2 = expf(v[i2] - v[i1]);
            float g1 = 1.f / (1.f + e2), g2 = e2 / (1.f + e2);
#pragma unroll
            for (int e = 0; e < NUM_EXP; e++) g_gates[gwarp * NUM_EXP + e] = 0.f;
            g_gates[gwarp * NUM_EXP + i1] = g1;
            g_gates[gwarp * NUM_EXP + i2] = g2;
            g_topi[gwarp * TOPK + 0] = i1;
            g_topi[gwarp * TOPK + 1] = i2;
            g_pairExpert[gwarp * TOPK + 0] = i1;
            g_pairExpert[gwarp * TOPK + 1] = i2;
            g_pairGate[gwarp * TOPK + 0] = g1;
            g_pairGate[gwarp * TOPK + 1] = g2;
            atomicAdd(&g_counts[i1], 1);
            atomicAdd(&g_counts[i2], 1);
        }
        __syncthreads();
        if (threadIdx.x == 0) {
            __threadfence();
            unsigned ticket = atomicAdd(&g_done, 1u);
            if (ticket == BATCH / 8 - 1) {
                int base = 0;
#pragma unroll
                for (int e = 0; e < NUM_EXP; e++) {
                    g_segbase[e] = base;
                    g_cursor[e]  = base;
                    base += ((g_counts[e] + 127) >> 7) << 7;
                }
                g_segbase[NUM_EXP] = base;
                g_done = 0;
                __threadfence();
            }
        }
    }

    for (size_t i = tid0; i < (size_t)BATCH * D_MODEL / 4; i += nthr) {
        float4 v = ((const float4*)x)[i];
        ((__half2*)g_xH)[i * 2]     = __floats2half2_rn(v.x, v.y);
        ((__half2*)g_xH)[i * 2 + 1] = __floats2half2_rn(v.z, v.w);
    }
}

// ---------------- L2: transpose weights to [e][n][k] fp16 -------------------
__global__ void transpose_kernel(const float* __restrict__ W1,
                                 const float* __restrict__ W2) {
    __shared__ float t[32][33];
    int e = blockIdx.z;
    int tx = threadIdx.x, ty = threadIdx.y;
    if (blockIdx.y < 32) {
        int nB = blockIdx.x * 32, kB = blockIdx.y * 32;
        const float* src = W1 + (size_t)e * D_MODEL * HIDDEN;
        __half* dst = g_W1T + (size_t)e * HIDDEN * D_MODEL;
#pragma unroll
        for (int i = 0; i < 32; i += 8)
            t[ty + i][tx] = src[(size_t)(kB + ty + i) * HIDDEN + nB + tx];
        __syncthreads();
#pragma unroll
        for (int i = 0; i < 32; i += 8)
            dst[(size_t)(nB + ty + i) * D_MODEL + kB + tx] = __float2half_rn(t[tx][ty + i]);
    } else {
        int nB = blockIdx.x * 32, kB = (blockIdx.y - 32) * 32;
        if (nB >= N2PAD) return;
        const float* src = W2 + (size_t)e * HIDDEN * NUM_CLS;
        __half* dst = g_W2T + (size_t)e * N2PAD * HIDDEN;
#pragma unroll
        for (int i = 0; i < 32; i += 8) {
            int n = nB + tx;
            t[ty + i][tx] = (n < NUM_CLS) ? src[(size_t)(kB + ty + i) * NUM_CLS + n] : 0.f;
        }
        __syncthreads();
#pragma unroll
        for (int i = 0; i < 32; i += 8)
            dst[(size_t)(nB + ty + i) * HIDDEN + kB + tx] = __float2half_rn(t[tx][ty + i]);
    }
}

// ---------------- L3: scatter ------------------------------------------------
__global__ void scatter_kernel() {
    int p = blockIdx.x * blockDim.x + threadIdx.x;
    if (p >= NPAIR) return;
    int e = g_pairExpert[p];
    int pos = atomicAdd(&g_cursor[e], 1);
    g_permToken[pos] = p >> 1;
    g_permPair[pos]  = p;
    g_permGate[pos]  = g_pairGate[p];
}

// ---------------- fp16 mma GEMMs --------------------------------------------
// 256 threads (8 warps, 2x4), CTA tile 128x128, warp tile 64x32, BK=64 fp16,
// 2-stage cp.async.cg. 144B rows -> conflict-free ldmatrix.
#define ROWB      144
#define A_BYTES   (128 * ROWB)                     // 18432
#define B_BYTES   (128 * ROWB)                     // 18432
#define STAGE_B   (A_BYTES + B_BYTES)              // 36864
#define SMEM_TOT  (2 * STAGE_B)                    // 73728

// copy roles (256 thr): thread t owns row t>>1 of A and of B, 64B half-row
// selected by (t&1): 4 x 16B cp.async each.
__device__ __forceinline__ void issue_chunk(
    uint32_t aDst, uint32_t bDst,
    const __half* aSrc, uint32_t aSz, const __half* bSrc, int kt)
{
#pragma unroll
    for (int j = 0; j < 4; j++)
        CPG16_SZ(aDst + j * 16, aSrc + kt + j * 8, aSz);
#pragma unroll
    for (int j = 0; j < 4; j++)
        CPG16(bDst + j * 16, bSrc + kt + j * 8);
    CPA_COMMIT();
}

// 64x32 warp tile: 4 ks of (4 a-ldsm + 2 b-ldsm + 16 mma).
__device__ __forceinline__ void mma_tile(uint32_t aAddr, uint32_t bAddr,
                                         float c[4][4][4]) {
#pragma unroll
    for (int ks = 0; ks < 4; ks++) {
        uint32_t a[4][4], b[2][4];
#pragma unroll
        for (int mi = 0; mi < 4; mi++)
            ldsm4(a[mi], aAddr + mi * (16 * ROWB) + ks * 32);
#pragma unroll
        for (int n2 = 0; n2 < 2; n2++)
            ldsm4(b[n2], bAddr + n2 * (16 * ROWB) + ks * 32);
#pragma unroll
        for (int mi = 0; mi < 4; mi++)
#pragma unroll
            for (int n2 = 0; n2 < 2; n2++) {
                mma_f16(c[mi][2 * n2],     a[mi], b[n2][0], b[n2][1]);
                mma_f16(c[mi][2 * n2 + 1], a[mi], b[n2][2], b[n2][3]);
            }
    }
}

__device__ __forceinline__ void gemm_mainloop(
    uint32_t aDst, uint32_t bDst,
    const __half* aSrc, uint32_t aSz, const __half* bSrc, int NIT,
    uint32_t aAddr, uint32_t bAddr, float c[4][4][4])
{
    issue_chunk(aDst, bDst, aSrc, aSz, bSrc, 0);
    for (int it = 0; it < NIT; ++it) {
        if (it + 1 < NIT) {
            int nb = (it + 1) & 1;
            issue_chunk(aDst + nb * STAGE_B, bDst + nb * STAGE_B,
                        aSrc, aSz, bSrc, (it + 1) * 64);
            CPA_WAIT1();
        } else {
            CPA_WAIT0();
        }
        __syncthreads();
        int buf = it & 1;
        mma_tile(aAddr + buf * STAGE_B, bAddr + buf * STAGE_B, c);
        __syncthreads();
    }
}

__global__ __launch_bounds__(256, 2)
void gemm1_mma(const float* __restrict__ b1) {
    extern __shared__ __align__(16) char smem[];
    const int tid = threadIdx.x, wid = tid >> 5, lane = tid & 31;
    const int rowBase = blockIdx.x * 128, nBase = blockIdx.y * 128;
    if (rowBase >= g_segbase[NUM_EXP]) return;
    int expert = 0;
#pragma unroll
    for (int i = 1; i < NUM_EXP; i++) if (g_segbase[i] <= rowBase) expert = i;

    uint32_t sb = smem_u32(smem);
    const int cr = tid >> 1, co = (tid & 1) * 32;   // row, half-row (elements)
    uint32_t aDst = sb + cr * ROWB + co * 2;
    uint32_t bDst = sb + A_BYTES + cr * ROWB + co * 2;

    const int tok = g_permToken[rowBase + cr];
    const __half* aSrc = g_xH + (size_t)(tok < 0 ? 0 : tok) * D_MODEL + co;
    uint32_t aSz = tok < 0 ? 0u : 16u;
    const __half* bSrc = g_W1T + (size_t)expert * HIDDEN * D_MODEL
                       + (size_t)(nBase + cr) * D_MODEL + co;

    const int gid = lane >> 2, tig = lane & 3;
    const int wr = (wid >> 2) * 64, wc = (wid & 3) * 32;
    const int g8 = lane >> 3, r8 = lane & 7;
    uint32_t aAddr = sb + (wr + (g8 & 1) * 8 + r8) * ROWB + (g8 >> 1) * 16;
    uint32_t bAddr = sb + A_BYTES + (wc + (g8 >> 1) * 8 + r8) * ROWB + (g8 & 1) * 16;

    float c[4][4][4];
#pragma unroll
    for (int mi = 0; mi < 4; mi++)
#pragma unroll
        for (int ni = 0; ni < 4; ni++)
#pragma unroll
            for (int q = 0; q < 4; q++) c[mi][ni][q] = 0.f;

    gemm_mainloop(aDst, bDst, aSrc, aSz, bSrc, D_MODEL / 64, aAddr, bAddr, c);

    const float* bb = b1 + (size_t)expert * HIDDEN + nBase;
#pragma unroll
    for (int mi = 0; mi < 4; mi++) {
        int r0 = rowBase + wr + mi * 16 + gid;
#pragma unroll
        for (int ni = 0; ni < 4; ni++) {
            int col = wc + ni * 8 + tig * 2;
            float bias0 = __ldg(bb + col), bias1 = __ldg(bb + col + 1);
            __half2 v0 = __floats2half2_rn(gelu_exact(c[mi][ni][0] + bias0),
                                           gelu_exact(c[mi][ni][1] + bias1));
            __half2 v1 = __floats2half2_rn(gelu_exact(c[mi][ni][2] + bias0),
                                           gelu_exact(c[mi][ni][3] + bias1));
            *(__half2*)(g_h + (size_t)r0 * HIDDEN + nBase + col) = v0;
            *(__half2*)(g_h + (size_t)(r0 + 8) * HIDDEN + nBase + col) = v1;
        }
    }
}

__global__ __launch_bounds__(256, 2)
void gemm2_mma(const float* __restrict__ b2, float* __restrict__ out) {
    extern __shared__ __align__(16) char smem[];
    const int tid = threadIdx.x, wid = tid >> 5, lane = tid & 31;
    const int rowBase = blockIdx.x * 128, nBase = blockIdx.y * 128;
    if (rowBase >= g_segbase[NUM_EXP]) return;
    int expert = 0;
#pragma unroll
    for (int i = 1; i < NUM_EXP; i++) if (g_segbase[i] <= rowBase) expert = i;

    uint32_t sb = smem_u32(smem);
    const int cr = tid >> 1, co = (tid & 1) * 32;
    uint32_t aDst = sb + cr * ROWB + co * 2;
    uint32_t bDst = sb + A_BYTES + cr * ROWB + co * 2;

    const __half* aSrc = g_h + (size_t)(rowBase + cr) * HIDDEN + co;
    const __half* bSrc = g_W2T + (size_t)expert * N2PAD * HIDDEN
                       + (size_t)(nBase + cr) * HIDDEN + co;

    const int gid = lane >> 2, tig = lane & 3;
    const int wr = (wid >> 2) * 64, wc = (wid & 3) * 32;
    const int g8 = lane >> 3, r8 = lane & 7;
    uint32_t aAddr = sb + (wr + (g8 & 1) * 8 + r8) * ROWB + (g8 >> 1) * 16;
    uint32_t bAddr = sb + A_BYTES + (wc + (g8 >> 1) * 8 + r8) * ROWB + (g8 & 1) * 16;

    float c[4][4][4];
#pragma unroll
    for (int mi = 0; mi < 4; mi++)
#pragma unroll
        for (int ni = 0; ni < 4; ni++)
#pragma unroll
            for (int q = 0; q < 4; q++) c[mi][ni][q] = 0.f;

    gemm_mainloop(aDst, bDst, aSrc, 16u, bSrc, HIDDEN / 64, aAddr, bAddr, c);

    const float* bb = b2 + (size_t)expert * NUM_CLS;
#pragma unroll
    for (int mi = 0; mi < 4; mi++) {
        int r0 = rowBase + wr + mi * 16 + gid;
#pragma unroll
        for (int half = 0; half < 2; half++) {
            int r = r0 + half * 8;
            int pair = g_permPair[r];
            if (pair < 0) continue;
            float gate = g_permGate[r];
            float* orow = out + (size_t)(pair >> 1) * NUM_CLS;
#pragma unroll
            for (int ni = 0; ni < 4; ni++) {
                int col = nBase + wc + ni * 8 + tig * 2;
                if (col < NUM_CLS)
                    atomicAdd(orow + col, gate * (c[mi][ni][half * 2 + 0] + __ldg(bb + col)));
                if (col + 1 < NUM_CLS)
                    atomicAdd(orow + col + 1, gate * (c[mi][ni][half * 2 + 1] + __ldg(bb + col + 1)));
            }
        }
    }
}

// ---------------- tail -------------------------------------------------------
__global__ void tail_kernel(float* __restrict__ out, int out_size) {
    int i = blockIdx.x * blockDim.x + threadIdx.x;
    const int OUT0 = BATCH * NUM_CLS;
    if (out_size >= OUT0 + BATCH * NUM_EXP) {
        if (i < BATCH * NUM_EXP)
            out[OUT0 + i] = g_gates[i];
        if (out_size >= OUT0 + BATCH * NUM_EXP + BATCH * TOPK && i < BATCH * TOPK)
            out[OUT0 + BATCH * NUM_EXP + i] = (float)g_topi[i];
    }
}

// ---------------------------------------------------------------------------
extern "C" void kernel_launch(void* const* d_in, const int* in_sizes, int n_in,
                              void* d_out, int out_size) {
    const float* x  = (const float*)d_in[0];
    const float* Wg = (const float*)d_in[1];
    const float* bg = (const float*)d_in[2];
    const float* W1 = (const float*)d_in[3];
    const float* b1 = (const float*)d_in[4];
    const float* W2 = (const float*)d_in[5];
    const float* b2 = (const float*)d_in[6];
    float* out = (float*)d_out;

    cudaFuncSetAttribute(gemm1_mma, cudaFuncAttributeMaxDynamicSharedMemorySize, SMEM_TOT);
    cudaFuncSetAttribute(gemm2_mma, cudaFuncAttributeMaxDynamicSharedMemorySize, SMEM_TOT);

    // ncu profiles launch index 4 -> gemm1_mma.
    cudaMemsetAsync(d_out, 0, (size_t)out_size * sizeof(float));             // 0
    prep_kernel<<<2048, 256>>>(x, Wg, bg);                                   // 1
    transpose_kernel<<<dim3(128, 160, NUM_EXP), dim3(32, 8)>>>(W1, W2);      // 2
    scatter_kernel<<<(NPAIR + 255) / 256, 256>>>();                          // 3
    gemm1_mma<<<dim3(MAX_TILES, HIDDEN / 128), 256, SMEM_TOT>>>(b1);         // 4 <- ncu
    gemm2_mma<<<dim3(MAX_TILES, N2PAD / 128), 256, SMEM_TOT>>>(b2, out);     // 5
    tail_kernel<<<(BATCH * NUM_EXP + 255) / 256, 256>>>(out, out_size);      // 6
}

// round 12
// speedup vs baseline: 2.2581x; 1.0336x over previous
#include <cuda_runtime.h>
#include <cuda_fp16.h>
#include <math.h>
#include <stdint.h>

// ---------------------------------------------------------------------------
// MoE top-2/8: fp16 m16n8k16 mma.sync GEMMs (fp32 accum), ldmatrix fragments,
// BK=64, cp.async.cg, 3-stage single-sync pipeline, 256-thread CTAs (8 warps).
// ---------------------------------------------------------------------------

#define BATCH      8192
#define D_MODEL    1024
#define HIDDEN     4096
#define NUM_CLS    1000
#define N2PAD      1024
#define NUM_EXP    8
#define TOPK       2
#define NPAIR      (BATCH * TOPK)
#define MAX_TILES  136
#define CAP        (MAX_TILES * 128)

// ---------------- scratch ---------------------------------------------------
__device__ __half g_h[(size_t)CAP * HIDDEN];
__device__ __half g_xH[(size_t)BATCH * D_MODEL];
__device__ __half g_W1T[(size_t)NUM_EXP * HIDDEN * D_MODEL];    // [e][n][k]
__device__ __half g_W2T[(size_t)NUM_EXP * N2PAD * HIDDEN];      // [e][n][k]
__device__ float g_gates[BATCH * NUM_EXP];
__device__ int   g_topi[BATCH * TOPK];
__device__ int   g_pairExpert[NPAIR];
__device__ float g_pairGate[NPAIR];
__device__ int   g_counts[NUM_EXP];
__device__ int   g_segbase[NUM_EXP + 1];
__device__ int   g_cursor[NUM_EXP];
__device__ int   g_permToken[CAP];
__device__ int   g_permPair[CAP];
__device__ float g_permGate[CAP];
__device__ unsigned g_done;

__device__ __forceinline__ float gelu_exact(float v) {
    return 0.5f * v * (1.0f + erff(v * 0.70710678118654752f));
}
__device__ __forceinline__ uint32_t smem_u32(const void* p) {
    uint32_t a;
    asm("{ .reg .u64 t; cvta.to.shared.u64 t, %1; cvt.u32.u64 %0, t; }" : "=r"(a) : "l"(p));
    return a;
}

#define CPG16(dst, src)        asm volatile("cp.async.cg.shared.global [%0], [%1], 16;" :: "r"(dst), "l"(src))
#define CPG16_SZ(dst, src, sz) asm volatile("cp.async.cg.shared.global [%0], [%1], 16, %2;" :: "r"(dst), "l"(src), "r"(sz))
#define CPA_COMMIT()           asm volatile("cp.async.commit_group;" ::: "memory")
#define CPA_WAIT1()            asm volatile("cp.async.wait_group 1;" ::: "memory")
#define CPA_WAIT0()            asm volatile("cp.async.wait_group 0;" ::: "memory")

__device__ __forceinline__ void mma_f16(float* c, const uint32_t* a, uint32_t b0, uint32_t b1) {
    asm volatile("mma.sync.aligned.m16n8k16.row.col.f32.f16.f16.f32 "
                 "{%0,%1,%2,%3}, {%4,%5,%6,%7}, {%8,%9}, {%0,%1,%2,%3};"
                 : "+f"(c[0]), "+f"(c[1]), "+f"(c[2]), "+f"(c[3])
                 : "r"(a[0]), "r"(a[1]), "r"(a[2]), "r"(a[3]), "r"(b0), "r"(b1));
}
__device__ __forceinline__ void ldsm4(uint32_t* r, uint32_t addr) {
    asm volatile("ldmatrix.sync.aligned.m8n8.x4.shared.b16 {%0,%1,%2,%3}, [%4];"
                 : "=r"(r[0]), "=r"(r[1]), "=r"(r[2]), "=r"(r[3]) : "r"(addr));
}

// ---------------- L1: prep = init + x->fp16 + router + scan -----------------
__global__ void prep_kernel(const float* __restrict__ x,
                            const float* __restrict__ Wg,
                            const float* __restrict__ bg) {
    size_t tid0 = blockIdx.x * blockDim.x + threadIdx.x;
    size_t nthr = (size_t)gridDim.x * blockDim.x;

    if (tid0 < CAP) { g_permToken[tid0] = -1; g_permPair[tid0] = -1; }
    if (tid0 < NUM_EXP) g_counts[tid0] = 0;

    if (blockIdx.x < BATCH / 8) {
        int gwarp = (blockIdx.x * blockDim.x + threadIdx.x) >> 5;
        int lane  = threadIdx.x & 31;
        const float* xr = x + (size_t)gwarp * D_MODEL;
        float acc[NUM_EXP];
#pragma unroll
        for (int e = 0; e < NUM_EXP; e++) acc[e] = 0.f;
        for (int k0 = lane * 4; k0 < D_MODEL; k0 += 128) {
            float4 xv = *(const float4*)(xr + k0);
            const float* xs = (const float*)&xv;
#pragma unroll
            for (int kk = 0; kk < 4; kk++) {
                const float4* wg = (const float4*)(Wg + (size_t)(k0 + kk) * NUM_EXP);
                float4 w0 = wg[0], w1 = wg[1];
                float xk = xs[kk];
                acc[0] += xk * w0.x; acc[1] += xk * w0.y;
                acc[2] += xk * w0.z; acc[3] += xk * w0.w;
                acc[4] += xk * w1.x; acc[5] += xk * w1.y;
                acc[6] += xk * w1.z; acc[7] += xk * w1.w;
            }
        }
#pragma unroll
        for (int off = 16; off; off >>= 1)
#pragma unroll
            for (int e = 0; e < NUM_EXP; e++)
                acc[e] += __shfl_xor_sync(0xFFFFFFFFu, acc[e], off);
        if (lane == 0) {
            float v[NUM_EXP];
#pragma unroll
            for (int e = 0; e < NUM_EXP; e++) v[e] = acc[e] + bg[e];
            int i1 = 0;
#pragma unroll
            for (int e = 1; e < NUM_EXP; e++) if (v[e] > v[i1]) i1 = e;
            int i2 = -1;
#pragma unroll
            for (int e = 0; e < NUM_EXP; e++)
                if (e != i1 && (i2 < 0 || v[e] > v[i2])) i2 = e;
            float e2 = expf(v[i2] - v[i1]);
            float g1 = 1.f / (1.f + e2), g2 = e2 / (1.f + e2);
#pragma unroll
            for (int e = 0; e < NUM_EXP; e++) g_gates[gwarp * NUM_EXP + e] = 0.f;
            g_gates[gwarp * NUM_EXP + i1] = g1;
            g_gates[gwarp * NUM_EXP + i2] = g2;
            g_topi[gwarp * TOPK + 0] = i1;
            g_topi[gwarp * TOPK + 1] = i2;
            g_pairExpert[gwarp * TOPK + 0] = i1;
            g_pairExpert[gwarp * TOPK + 1] = i2;
            g_pairGate[gwarp * TOPK + 0] = g1;
            g_pairGate[gwarp * TOPK + 1] = g2;
            atomicAdd(&g_counts[i1], 1);
            atomicAdd(&g_counts[i2], 1);
        }
        __syncthreads();
        if (threadIdx.x == 0) {
            __threadfence();
            unsigned ticket = atomicAdd(&g_done, 1u);
            if (ticket == BATCH / 8 - 1) {
                int base = 0;
#pragma unroll
                for (int e = 0; e < NUM_EXP; e++) {
                    g_segbase[e] = base;
                    g_cursor[e]  = base;
                    base += ((g_counts[e] + 127) >> 7) << 7;
                }
                g_segbase[NUM_EXP] = base;
                g_done = 0;
                __threadfence();
            }
        }
    }

    for (size_t i = tid0; i < (size_t)BATCH * D_MODEL / 4; i += nthr) {
        float4 v = ((const float4*)x)[i];
        ((__half2*)g_xH)[i * 2]     = __floats2half2_rn(v.x, v.y);
        ((__half2*)g_xH)[i * 2 + 1] = __floats2half2_rn(v.z, v.w);
    }
}

// ---------------- L2: transpose weights to [e][n][k] fp16 -------------------
__global__ void transpose_kernel(const float* __restrict__ W1,
                                 const float* __restrict__ W2) {
    __shared__ float t[32][33];
    int e = blockIdx.z;
    int tx = threadIdx.x, ty = threadIdx.y;
    if (blockIdx.y < 32) {
        int nB = blockIdx.x * 32, kB = blockIdx.y * 32;
        const float* src = W1 + (size_t)e * D_MODEL * HIDDEN;
        __half* dst = g_W1T + (size_t)e * HIDDEN * D_MODEL;
#pragma unroll
        for (int i = 0; i < 32; i += 8)
            t[ty + i][tx] = src[(size_t)(kB + ty + i) * HIDDEN + nB + tx];
        __syncthreads();
#pragma unroll
        for (int i = 0; i < 32; i += 8)
            dst[(size_t)(nB + ty + i) * D_MODEL + kB + tx] = __float2half_rn(t[tx][ty + i]);
    } else {
        int nB = blockIdx.x * 32, kB = (blockIdx.y - 32) * 32;
        if (nB >= N2PAD) return;
        const float* src = W2 + (size_t)e * HIDDEN * NUM_CLS;
        __half* dst = g_W2T + (size_t)e * N2PAD * HIDDEN;
#pragma unroll
        for (int i = 0; i < 32; i += 8) {
            int n = nB + tx;
            t[ty + i][tx] = (n < NUM_CLS) ? src[(size_t)(kB + ty + i) * NUM_CLS + n] : 0.f;
        }
        __syncthreads();
#pragma unroll
        for (int i = 0; i < 32; i += 8)
            dst[(size_t)(nB + ty + i) * HIDDEN + kB + tx] = __float2half_rn(t[tx][ty + i]);
    }
}

// ---------------- L3: scatter ------------------------------------------------
__global__ void scatter_kernel() {
    int p = blockIdx.x * blockDim.x + threadIdx.x;
    if (p >= NPAIR) return;
    int e = g_pairExpert[p];
    int pos = atomicAdd(&g_cursor[e], 1);
    g_permToken[pos] = p >> 1;
    g_permPair[pos]  = p;
    g_permGate[pos]  = g_pairGate[p];
}

// ---------------- fp16 mma GEMMs --------------------------------------------
// 256 threads (8 warps, 2x4), CTA tile 128x128, warp tile 64x32, BK=64 fp16,
// 3-stage cp.async.cg pipeline with ONE __syncthreads per chunk.
#define ROWB      144
#define A_BYTES   (128 * ROWB)                     // 18432
#define B_BYTES   (128 * ROWB)                     // 18432
#define STAGE_B   (A_BYTES + B_BYTES)              // 36864
#define NSTAGE    3
#define SMEM_TOT  (NSTAGE * STAGE_B)               // 110592

__device__ __forceinline__ void issue_chunk(
    uint32_t aDst, uint32_t bDst,
    const __half* aSrc, uint32_t aSz, const __half* bSrc, int kt)
{
#pragma unroll
    for (int j = 0; j < 4; j++)
        CPG16_SZ(aDst + j * 16, aSrc + kt + j * 8, aSz);
#pragma unroll
    for (int j = 0; j < 4; j++)
        CPG16(bDst + j * 16, bSrc + kt + j * 8);
    CPA_COMMIT();
}

// 64x32 warp tile: 4 ks of (4 a-ldsm + 2 b-ldsm + 16 mma).
__device__ __forceinline__ void mma_tile(uint32_t aAddr, uint32_t bAddr,
                                         float c[4][4][4]) {
#pragma unroll
    for (int ks = 0; ks < 4; ks++) {
        uint32_t a[4][4], b[2][4];
#pragma unroll
        for (int mi = 0; mi < 4; mi++)
            ldsm4(a[mi], aAddr + mi * (16 * ROWB) + ks * 32);
#pragma unroll
        for (int n2 = 0; n2 < 2; n2++)
            ldsm4(b[n2], bAddr + n2 * (16 * ROWB) + ks * 32);
#pragma unroll
        for (int mi = 0; mi < 4; mi++)
#pragma unroll
            for (int n2 = 0; n2 < 2; n2++) {
                mma_f16(c[mi][2 * n2],     a[mi], b[n2][0], b[n2][1]);
                mma_f16(c[mi][2 * n2 + 1], a[mi], b[n2][2], b[n2][3]);
            }
    }
}

// 3-stage, ONE sync per chunk:
//   wait(oldest done) -> sync -> prefetch it+2 -> mma(it)
// Safety: sync at iter it proves all warps finished mma(it-1) — the last
// reader of buffer (it-1)%3 == (it+2)%3 — before the prefetch overwrites it.
__device__ __forceinline__ void gemm_mainloop(
    uint32_t aDst, uint32_t bDst,
    const __half* aSrc, uint32_t aSz, const __half* bSrc, int NIT,
    uint32_t aAddr, uint32_t bAddr, float c[4][4][4])
{
    issue_chunk(aDst, bDst, aSrc, aSz, bSrc, 0);
    issue_chunk(aDst + STAGE_B, bDst + STAGE_B, aSrc, aSz, bSrc, 64);
    int buf = 0, nxt = 2;
    for (int it = 0; it < NIT; ++it) {
        if (it + 1 < NIT) CPA_WAIT1(); else CPA_WAIT0();
        __syncthreads();
        if (it + 2 < NIT)
            issue_chunk(aDst + nxt * STAGE_B, bDst + nxt * STAGE_B,
                        aSrc, aSz, bSrc, (it + 2) * 64);
        mma_tile(aAddr + buf * STAGE_B, bAddr + buf * STAGE_B, c);
        buf = (buf == NSTAGE - 1) ? 0 : buf + 1;
        nxt = (nxt == NSTAGE - 1) ? 0 : nxt + 1;
    }
}

__global__ __launch_bounds__(256, 2)
void gemm1_mma(const float* __restrict__ b1) {
    extern __shared__ __align__(16) char smem[];
    const int tid = threadIdx.x, wid = tid >> 5, lane = tid & 31;
    const int rowBase = blockIdx.x * 128, nBase = blockIdx.y * 128;
    if (rowBase >= g_segbase[NUM_EXP]) return;
    int expert = 0;
#pragma unroll
    for (int i = 1; i < NUM_EXP; i++) if (g_segbase[i] <= rowBase) expert = i;

    uint32_t sb = smem_u32(smem);
    const int cr = tid >> 1, co = (tid & 1) * 32;   // row, half-row (elements)
    uint32_t aDst = sb + cr * ROWB + co * 2;
    uint32_t bDst = sb + A_BYTES + cr * ROWB + co * 2;

    const int tok = g_permToken[rowBase + cr];
    const __half* aSrc = g_xH + (size_t)(tok < 0 ? 0 : tok) * D_MODEL + co;
    uint32_t aSz = tok < 0 ? 0u : 16u;
    const __half* bSrc = g_W1T + (size_t)expert * HIDDEN * D_MODEL
                       + (size_t)(nBase + cr) * D_MODEL + co;

    const int gid = lane >> 2, tig = lane & 3;
    const int wr = (wid >> 2) * 64, wc = (wid & 3) * 32;
    const int g8 = lane >> 3, r8 = lane & 7;
    uint32_t aAddr = sb + (wr + (g8 & 1) * 8 + r8) * ROWB + (g8 >> 1) * 16;
    uint32_t bAddr = sb + A_BYTES + (wc + (g8 >> 1) * 8 + r8) * ROWB + (g8 & 1) * 16;

    float c[4][4][4];
#pragma unroll
    for (int mi = 0; mi < 4; mi++)
#pragma unroll
        for (int ni = 0; ni < 4; ni++)
#pragma unroll
            for (int q = 0; q < 4; q++) c[mi][ni][q] = 0.f;

    gemm_mainloop(aDst, bDst, aSrc, aSz, bSrc, D_MODEL / 64, aAddr, bAddr, c);

    const float* bb = b1 + (size_t)expert * HIDDEN + nBase;
#pragma unroll
    for (int mi = 0; mi < 4; mi++) {
        int r0 = rowBase + wr + mi * 16 + gid;
#pragma unroll
        for (int ni = 0; ni < 4; ni++) {
            int col = wc + ni * 8 + tig * 2;
            float bias0 = __ldg(bb + col), bias1 = __ldg(bb + col + 1);
            __half2 v0 = __floats2half2_rn(gelu_exact(c[mi][ni][0] + bias0),
                                           gelu_exact(c[mi][ni][1] + bias1));
            __half2 v1 = __floats2half2_rn(gelu_exact(c[mi][ni][2] + bias0),
                                           gelu_exact(c[mi][ni][3] + bias1));
            *(__half2*)(g_h + (size_t)r0 * HIDDEN + nBase + col) = v0;
            *(__half2*)(g_h + (size_t)(r0 + 8) * HIDDEN + nBase + col) = v1;
        }
    }
}

__global__ __launch_bounds__(256, 2)
void gemm2_mma(const float* __restrict__ b2, float* __restrict__ out) {
    extern __shared__ __align__(16) char smem[];
    const int tid = threadIdx.x, wid = tid >> 5, lane = tid & 31;
    const int rowBase = blockIdx.x * 128, nBase = blockIdx.y * 128;
    if (rowBase >= g_segbase[NUM_EXP]) return;
    int expert = 0;
#pragma unroll
    for (int i = 1; i < NUM_EXP; i++) if (g_segbase[i] <= rowBase) expert = i;

    uint32_t sb = smem_u32(smem);
    const int cr = tid >> 1, co = (tid & 1) * 32;
    uint32_t aDst = sb + cr * ROWB + co * 2;
    uint32_t bDst = sb + A_BYTES + cr * ROWB + co * 2;

    const __half* aSrc = g_h + (size_t)(rowBase + cr) * HIDDEN + co;
    const __half* bSrc = g_W2T + (size_t)expert * N2PAD * HIDDEN
                       + (size_t)(nBase + cr) * HIDDEN + co;

    const int gid = lane >> 2, tig = lane & 3;
    const int wr = (wid >> 2) * 64, wc = (wid & 3) * 32;
    const int g8 = lane >> 3, r8 = lane & 7;
    uint32_t aAddr = sb + (wr + (g8 & 1) * 8 + r8) * ROWB + (g8 >> 1) * 16;
    uint32_t bAddr = sb + A_BYTES + (wc + (g8 >> 1) * 8 + r8) * ROWB + (g8 & 1) * 16;

    float c[4][4][4];
#pragma unroll
    for (int mi = 0; mi < 4; mi++)
#pragma unroll
        for (int ni = 0; ni < 4; ni++)
#pragma unroll
            for (int q = 0; q < 4; q++) c[mi][ni][q] = 0.f;

    gemm_mainloop(aDst, bDst, aSrc, 16u, bSrc, HIDDEN / 64, aAddr, bAddr, c);

    const float* bb = b2 + (size_t)expert * NUM_CLS;
#pragma unroll
    for (int mi = 0; mi < 4; mi++) {
        int r0 = rowBase + wr + mi * 16 + gid;
#pragma unroll
        for (int half = 0; half < 2; half++) {
            int r = r0 + half * 8;
            int pair = g_permPair[r];
            if (pair < 0) continue;
            float gate = g_permGate[r];
            float* orow = out + (size_t)(pair >> 1) * NUM_CLS;
#pragma unroll
            for (int ni = 0; ni < 4; ni++) {
                int col = nBase + wc + ni * 8 + tig * 2;
                if (col < NUM_CLS)
                    atomicAdd(orow + col, gate * (c[mi][ni][half * 2 + 0] + __ldg(bb + col)));
                if (col + 1 < NUM_CLS)
                    atomicAdd(orow + col + 1, gate * (c[mi][ni][half * 2 + 1] + __ldg(bb + col + 1)));
            }
        }
    }
}

// ---------------- tail -------------------------------------------------------
__global__ void tail_kernel(float* __restrict__ out, int out_size) {
    int i = blockIdx.x * blockDim.x + threadIdx.x;
    const int OUT0 = BATCH * NUM_CLS;
    if (out_size >= OUT0 + BATCH * NUM_EXP) {
        if (i < BATCH * NUM_EXP)
            out[OUT0 + i] = g_gates[i];
        if (out_size >= OUT0 + BATCH * NUM_EXP + BATCH * TOPK && i < BATCH * TOPK)
            out[OUT0 + BATCH * NUM_EXP + i] = (float)g_topi[i];
    }
}

// ---------------------------------------------------------------------------
extern "C" void kernel_launch(void* const* d_in, const int* in_sizes, int n_in,
                              void* d_out, int out_size) {
    const float* x  = (const float*)d_in[0];
    const float* Wg = (const float*)d_in[1];
    const float* bg = (const float*)d_in[2];
    const float* W1 = (const float*)d_in[3];
    const float* b1 = (const float*)d_in[4];
    const float* W2 = (const float*)d_in[5];
    const float* b2 = (const float*)d_in[6];
    float* out = (float*)d_out;

    cudaFuncSetAttribute(gemm1_mma, cudaFuncAttributeMaxDynamicSharedMemorySize, SMEM_TOT);
    cudaFuncSetAttribute(gemm2_mma, cudaFuncAttributeMaxDynamicSharedMemorySize, SMEM_TOT);

    // ncu profiles launch index 4 -> gemm1_mma.
    cudaMemsetAsync(d_out, 0, (size_t)out_size * sizeof(float));             // 0
    prep_kernel<<<2048, 256>>>(x, Wg, bg);                                   // 1
    transpose_kernel<<<dim3(128, 160, NUM_EXP), dim3(32, 8)>>>(W1, W2);      // 2
    scatter_kernel<<<(NPAIR + 255) / 256, 256>>>();                          // 3
    gemm1_mma<<<dim3(MAX_TILES, HIDDEN / 128), 256, SMEM_TOT>>>(b1);         // 4 <- ncu
    gemm2_mma<<<dim3(MAX_TILES, N2PAD / 128), 256, SMEM_TOT>>>(b2, out);     // 5
    tail_kernel<<<(BATCH * NUM_EXP + 255) / 256, 256>>>(out, out_size);      // 6
}

// round 13
// speedup vs baseline: 2.3482x; 1.0399x over previous
#include <cuda_runtime.h>
#include <cuda_fp16.h>
#include <math.h>
#include <stdint.h>

// ---------------------------------------------------------------------------
// MoE top-2/8: fp16 m16n8k16 mma.sync GEMMs (fp32 accum), ldmatrix fragments,
// BK=64, cp.async.cg, 3-stage single-sync pipeline, 256-thread CTAs (8 warps).
// Preamble fused: router || weight transposes in one kernel.
// ---------------------------------------------------------------------------

#define BATCH      8192
#define D_MODEL    1024
#define HIDDEN     4096
#define NUM_CLS    1000
#define N2PAD      1024
#define NUM_EXP    8
#define TOPK       2
#define NPAIR      (BATCH * TOPK)
#define MAX_TILES  136
#define CAP        (MAX_TILES * 128)

#define RTR_BLOCKS (BATCH / 8)                  // 1024 router blocks
#define T1_BLOCKS  (NUM_EXP * (D_MODEL/64) * (HIDDEN/64))   // 8*16*64 = 8192
#define T2_BLOCKS  (NUM_EXP * (HIDDEN/64) * (N2PAD/64))     // 8*64*16 = 8192
#define PREP_BLOCKS (RTR_BLOCKS + T1_BLOCKS + T2_BLOCKS)    // 17408

// ---------------- scratch ---------------------------------------------------
__device__ __half g_h[(size_t)CAP * HIDDEN];
__device__ __half g_xH[(size_t)BATCH * D_MODEL];
__device__ __half g_W1T[(size_t)NUM_EXP * HIDDEN * D_MODEL];    // [e][n][k]
__device__ __half g_W2T[(size_t)NUM_EXP * N2PAD * HIDDEN];      // [e][n][k]
__device__ float g_gates[BATCH * NUM_EXP];
__device__ int   g_topi[BATCH * TOPK];
__device__ int   g_pairExpert[NPAIR];
__device__ float g_pairGate[NPAIR];
__device__ int   g_counts[NUM_EXP];
__device__ int   g_segbase[NUM_EXP + 1];
__device__ int   g_cursor[NUM_EXP];
__device__ int   g_permToken[CAP];
__device__ int   g_permPair[CAP];
__device__ float g_permGate[CAP];
__device__ unsigned g_done;

__device__ __forceinline__ float gelu_exact(float v) {
    return 0.5f * v * (1.0f + erff(v * 0.70710678118654752f));
}
__device__ __forceinline__ uint32_t smem_u32(const void* p) {
    uint32_t a;
    asm("{ .reg .u64 t; cvta.to.shared.u64 t, %1; cvt.u32.u64 %0, t; }" : "=r"(a) : "l"(p));
    return a;
}

#define CPG16(dst, src)        asm volatile("cp.async.cg.shared.global [%0], [%1], 16;" :: "r"(dst), "l"(src))
#define CPG16_SZ(dst, src, sz) asm volatile("cp.async.cg.shared.global [%0], [%1], 16, %2;" :: "r"(dst), "l"(src), "r"(sz))
#define CPA_COMMIT()           asm volatile("cp.async.commit_group;" ::: "memory")
#define CPA_WAIT1()            asm volatile("cp.async.wait_group 1;" ::: "memory")
#define CPA_WAIT0()            asm volatile("cp.async.wait_group 0;" ::: "memory")

__device__ __forceinline__ void mma_f16(float* c, const uint32_t* a, uint32_t b0, uint32_t b1) {
    asm volatile("mma.sync.aligned.m16n8k16.row.col.f32.f16.f16.f32 "
                 "{%0,%1,%2,%3}, {%4,%5,%6,%7}, {%8,%9}, {%0,%1,%2,%3};"
                 : "+f"(c[0]), "+f"(c[1]), "+f"(c[2]), "+f"(c[3])
                 : "r"(a[0]), "r"(a[1]), "r"(a[2]), "r"(a[3]), "r"(b0), "r"(b1));
}
__device__ __forceinline__ void ldsm4(uint32_t* r, uint32_t addr) {
    asm volatile("ldmatrix.sync.aligned.m8n8.x4.shared.b16 {%0,%1,%2,%3}, [%4];"
                 : "=r"(r[0]), "=r"(r[1]), "=r"(r[2]), "=r"(r[3]) : "r"(addr));
}

// ---------------- L1: fused prep --------------------------------------------
// Blocks [0, RTR_BLOCKS): router (8 warps/block, 1 token/warp) + perm-init +
//   x->fp16 convert + last-block ticket scan.
// Blocks [RTR_BLOCKS, +T1_BLOCKS): W1 64x64 transpose tiles -> g_W1T fp16.
// Blocks [.., +T2_BLOCKS): W2 64x64 transpose tiles (N zero-padded) -> g_W2T.
__global__ void prep_all(const float* __restrict__ x,
                         const float* __restrict__ Wg,
                         const float* __restrict__ bg,
                         const float* __restrict__ W1,
                         const float* __restrict__ W2) {
    __shared__ float t[64][65];
    const int bid = blockIdx.x, tid = threadIdx.x;

    if (bid < RTR_BLOCKS) {
        size_t tid0 = (size_t)bid * blockDim.x + tid;
        size_t nthr = (size_t)RTR_BLOCKS * blockDim.x;
        if (tid0 < CAP) { g_permToken[tid0] = -1; g_permPair[tid0] = -1; }
        if (tid0 < NUM_EXP) g_counts[tid0] = 0;

        int gwarp = (int)(tid0 >> 5);
        int lane  = tid & 31;
        const float* xr = x + (size_t)gwarp * D_MODEL;
        float acc[NUM_EXP];
#pragma unroll
        for (int e = 0; e < NUM_EXP; e++) acc[e] = 0.f;
        for (int k0 = lane * 4; k0 < D_MODEL; k0 += 128) {
            float4 xv = *(const float4*)(xr + k0);
            const float* xs = (const float*)&xv;
#pragma unroll
            for (int kk = 0; kk < 4; kk++) {
                const float4* wg = (const float4*)(Wg + (size_t)(k0 + kk) * NUM_EXP);
                float4 w0 = wg[0], w1 = wg[1];
                float xk = xs[kk];
                acc[0] += xk * w0.x; acc[1] += xk * w0.y;
                acc[2] += xk * w0.z; acc[3] += xk * w0.w;
                acc[4] += xk * w1.x; acc[5] += xk * w1.y;
                acc[6] += xk * w1.z; acc[7] += xk * w1.w;
            }
        }
#pragma unroll
        for (int off = 16; off; off >>= 1)
#pragma unroll
            for (int e = 0; e < NUM_EXP; e++)
                acc[e] += __shfl_xor_sync(0xFFFFFFFFu, acc[e], off);
        if (lane == 0) {
            float v[NUM_EXP];
#pragma unroll
            for (int e = 0; e < NUM_EXP; e++) v[e] = acc[e] + bg[e];
            int i1 = 0;
#pragma unroll
            for (int e = 1; e < NUM_EXP; e++) if (v[e] > v[i1]) i1 = e;
            int i2 = -1;
#pragma unroll
            for (int e = 0; e < NUM_EXP; e++)
                if (e != i1 && (i2 < 0 || v[e] > v[i2])) i2 = e;
            float e2 = expf(v[i2] - v[i1]);
            float g1 = 1.f / (1.f + e2), g2 = e2 / (1.f + e2);
#pragma unroll
            for (int e = 0; e < NUM_EXP; e++) g_gates[gwarp * NUM_EXP + e] = 0.f;
            g_gates[gwarp * NUM_EXP + i1] = g1;
            g_gates[gwarp * NUM_EXP + i2] = g2;
            g_topi[gwarp * TOPK + 0] = i1;
            g_topi[gwarp * TOPK + 1] = i2;
            g_pairExpert[gwarp * TOPK + 0] = i1;
            g_pairExpert[gwarp * TOPK + 1] = i2;
            g_pairGate[gwarp * TOPK + 0] = g1;
            g_pairGate[gwarp * TOPK + 1] = g2;
            atomicAdd(&g_counts[i1], 1);
            atomicAdd(&g_counts[i2], 1);
        }

        // x -> fp16
        for (size_t i = tid0; i < (size_t)BATCH * D_MODEL / 4; i += nthr) {
            float4 v = ((const float4*)x)[i];
            ((__half2*)g_xH)[i * 2]     = __floats2half2_rn(v.x, v.y);
            ((__half2*)g_xH)[i * 2 + 1] = __floats2half2_rn(v.z, v.w);
        }

        __syncthreads();
        if (tid == 0) {
            __threadfence();
            unsigned ticket = atomicAdd(&g_done, 1u);
            if (ticket == RTR_BLOCKS - 1) {
                int base = 0;
#pragma unroll
                for (int e = 0; e < NUM_EXP; e++) {
                    g_segbase[e] = base;
                    g_cursor[e]  = base;
                    base += ((g_counts[e] + 127) >> 7) << 7;
                }
                g_segbase[NUM_EXP] = base;
                g_done = 0;
                __threadfence();
            }
        }
        return;
    }

    // ---- transpose tiles (64x64, 256 threads: tx=col, ty=row/4) ------------
    const int tx = tid & 63, ty4 = tid >> 6;           // ty4 = 0..3
    int idx = bid - RTR_BLOCKS;
    if (idx < T1_BLOCKS) {
        // W1 [e][k=1024][n=4096] -> W1T [e][n][k]
        int e  = idx >> 10;                 // /1024
        int tt = idx & 1023;
        int kB = (tt & 15) * 64;            // 16 k-tiles
        int nB = (tt >> 4) * 64;            // 64 n-tiles
        const float* src = W1 + (size_t)e * D_MODEL * HIDDEN;
        __half* dst = g_W1T + (size_t)e * HIDDEN * D_MODEL;
#pragma unroll
        for (int i = 0; i < 16; i++) {
            int r = ty4 + i * 4;
            t[r][tx] = src[(size_t)(kB + r) * HIDDEN + nB + tx];
        }
        __syncthreads();
#pragma unroll
        for (int i = 0; i < 16; i++) {
            int r = ty4 + i * 4;
            dst[(size_t)(nB + r) * D_MODEL + kB + tx] = __float2half_rn(t[tx][r]);
        }
    } else {
        // W2 [e][k=4096][n=1000] -> W2T [e][n=1024pad][k]
        idx -= T1_BLOCKS;
        int e  = idx >> 10;
        int tt = idx & 1023;
        int kB = (tt & 63) * 64;            // 64 k-tiles
        int nB = (tt >> 6) * 64;            // 16 n-tiles
        const float* src = W2 + (size_t)e * HIDDEN * NUM_CLS;
        __half* dst = g_W2T + (size_t)e * N2PAD * HIDDEN;
        int n = nB + tx;
#pragma unroll
        for (int i = 0; i < 16; i++) {
            int r = ty4 + i * 4;
            t[r][tx] = (n < NUM_CLS) ? src[(size_t)(kB + r) * NUM_CLS + n] : 0.f;
        }
        __syncthreads();
#pragma unroll
        for (int i = 0; i < 16; i++) {
            int r = ty4 + i * 4;
            dst[(size_t)(nB + r) * HIDDEN + kB + tx] = __float2half_rn(t[tx][r]);
        }
    }
}

// ---------------- L2: scatter ------------------------------------------------
__global__ void scatter_kernel() {
    int p = blockIdx.x * blockDim.x + threadIdx.x;
    if (p >= NPAIR) return;
    int e = g_pairExpert[p];
    int pos = atomicAdd(&g_cursor[e], 1);
    g_permToken[pos] = p >> 1;
    g_permPair[pos]  = p;
    g_permGate[pos]  = g_pairGate[p];
}

// ---------------- fp16 mma GEMMs --------------------------------------------
// 256 threads (8 warps, 2x4), CTA tile 128x128, warp tile 64x32, BK=64 fp16,
// 3-stage cp.async.cg pipeline with ONE __syncthreads per chunk.
#define ROWB      144
#define A_BYTES   (128 * ROWB)                     // 18432
#define B_BYTES   (128 * ROWB)                     // 18432
#define STAGE_B   (A_BYTES + B_BYTES)              // 36864
#define NSTAGE    3
#define SMEM_TOT  (NSTAGE * STAGE_B)               // 110592

__device__ __forceinline__ void issue_chunk(
    uint32_t aDst, uint32_t bDst,
    const __half* aSrc, uint32_t aSz, const __half* bSrc, int kt)
{
#pragma unroll
    for (int j = 0; j < 4; j++)
        CPG16_SZ(aDst + j * 16, aSrc + kt + j * 8, aSz);
#pragma unroll
    for (int j = 0; j < 4; j++)
        CPG16(bDst + j * 16, bSrc + kt + j * 8);
    CPA_COMMIT();
}

__device__ __forceinline__ void mma_tile(uint32_t aAddr, uint32_t bAddr,
                                         float c[4][4][4]) {
#pragma unroll
    for (int ks = 0; ks < 4; ks++) {
        uint32_t a[4][4], b[2][4];
#pragma unroll
        for (int mi = 0; mi < 4; mi++)
            ldsm4(a[mi], aAddr + mi * (16 * ROWB) + ks * 32);
#pragma unroll
        for (int n2 = 0; n2 < 2; n2++)
            ldsm4(b[n2], bAddr + n2 * (16 * ROWB) + ks * 32);
#pragma unroll
        for (int mi = 0; mi < 4; mi++)
#pragma unroll
            for (int n2 = 0; n2 < 2; n2++) {
                mma_f16(c[mi][2 * n2],     a[mi], b[n2][0], b[n2][1]);
                mma_f16(c[mi][2 * n2 + 1], a[mi], b[n2][2], b[n2][3]);
            }
    }
}

__device__ __forceinline__ void gemm_mainloop(
    uint32_t aDst, uint32_t bDst,
    const __half* aSrc, uint32_t aSz, const __half* bSrc, int NIT,
    uint32_t aAddr, uint32_t bAddr, float c[4][4][4])
{
    issue_chunk(aDst, bDst, aSrc, aSz, bSrc, 0);
    issue_chunk(aDst + STAGE_B, bDst + STAGE_B, aSrc, aSz, bSrc, 64);
    int buf = 0, nxt = 2;
    for (int it = 0; it < NIT; ++it) {
        if (it + 1 < NIT) CPA_WAIT1(); else CPA_WAIT0();
        __syncthreads();
        if (it + 2 < NIT)
            issue_chunk(aDst + nxt * STAGE_B, bDst + nxt * STAGE_B,
                        aSrc, aSz, bSrc, (it + 2) * 64);
        mma_tile(aAddr + buf * STAGE_B, bAddr + buf * STAGE_B, c);
        buf = (buf == NSTAGE - 1) ? 0 : buf + 1;
        nxt = (nxt == NSTAGE - 1) ? 0 : nxt + 1;
    }
}

__global__ __launch_bounds__(256, 2)
void gemm1_mma(const float* __restrict__ b1) {
    extern __shared__ __align__(16) char smem[];
    const int tid = threadIdx.x, wid = tid >> 5, lane = tid & 31;
    const int rowBase = blockIdx.x * 128, nBase = blockIdx.y * 128;
    if (rowBase >= g_segbase[NUM_EXP]) return;
    int expert = 0;
#pragma unroll
    for (int i = 1; i < NUM_EXP; i++) if (g_segbase[i] <= rowBase) expert = i;

    uint32_t sb = smem_u32(smem);
    const int cr = tid >> 1, co = (tid & 1) * 32;
    uint32_t aDst = sb + cr * ROWB + co * 2;
    uint32_t bDst = sb + A_BYTES + cr * ROWB + co * 2;

    const int tok = g_permToken[rowBase + cr];
    const __half* aSrc = g_xH + (size_t)(tok < 0 ? 0 : tok) * D_MODEL + co;
    uint32_t aSz = tok < 0 ? 0u : 16u;
    const __half* bSrc = g_W1T + (size_t)expert * HIDDEN * D_MODEL
                       + (size_t)(nBase + cr) * D_MODEL + co;

    const int gid = lane >> 2, tig = lane & 3;
    const int wr = (wid >> 2) * 64, wc = (wid & 3) * 32;
    const int g8 = lane >> 3, r8 = lane & 7;
    uint32_t aAddr = sb + (wr + (g8 & 1) * 8 + r8) * ROWB + (g8 >> 1) * 16;
    uint32_t bAddr = sb + A_BYTES + (wc + (g8 >> 1) * 8 + r8) * ROWB + (g8 & 1) * 16;

    float c[4][4][4];
#pragma unroll
    for (int mi = 0; mi < 4; mi++)
#pragma unroll
        for (int ni = 0; ni < 4; ni++)
#pragma unroll
            for (int q = 0; q < 4; q++) c[mi][ni][q] = 0.f;

    gemm_mainloop(aDst, bDst, aSrc, aSz, bSrc, D_MODEL / 64, aAddr, bAddr, c);

    const float* bb = b1 + (size_t)expert * HIDDEN + nBase;
#pragma unroll
    for (int mi = 0; mi < 4; mi++) {
        int r0 = rowBase + wr + mi * 16 + gid;
#pragma unroll
        for (int ni = 0; ni < 4; ni++) {
            int col = wc + ni * 8 + tig * 2;
            float bias0 = __ldg(bb + col), bias1 = __ldg(bb + col + 1);
            __half2 v0 = __floats2half2_rn(gelu_exact(c[mi][ni][0] + bias0),
                                           gelu_exact(c[mi][ni][1] + bias1));
            __half2 v1 = __floats2half2_rn(gelu_exact(c[mi][ni][2] + bias0),
                                           gelu_exact(c[mi][ni][3] + bias1));
            *(__half2*)(g_h + (size_t)r0 * HIDDEN + nBase + col) = v0;
            *(__half2*)(g_h + (size_t)(r0 + 8) * HIDDEN + nBase + col) = v1;
        }
    }
}

__global__ __launch_bounds__(256, 2)
void gemm2_mma(const float* __restrict__ b2, float* __restrict__ out) {
    extern __shared__ __align__(16) char smem[];
    const int tid = threadIdx.x, wid = tid >> 5, lane = tid & 31;
    const int rowBase = blockIdx.x * 128, nBase = blockIdx.y * 128;
    if (rowBase >= g_segbase[NUM_EXP]) return;
    int expert = 0;
#pragma unroll
    for (int i = 1; i < NUM_EXP; i++) if (g_segbase[i] <= rowBase) expert = i;

    uint32_t sb = smem_u32(smem);
    const int cr = tid >> 1, co = (tid & 1) * 32;
    uint32_t aDst = sb + cr * ROWB + co * 2;
    uint32_t bDst = sb + A_BYTES + cr * ROWB + co * 2;

    const __half* aSrc = g_h + (size_t)(rowBase + cr) * HIDDEN + co;
    const __half* bSrc = g_W2T + (size_t)expert * N2PAD * HIDDEN
                       + (size_t)(nBase + cr) * HIDDEN + co;

    const int gid = lane >> 2, tig = lane & 3;
    const int wr = (wid >> 2) * 64, wc = (wid & 3) * 32;
    const int g8 = lane >> 3, r8 = lane & 7;
    uint32_t aAddr = sb + (wr + (g8 & 1) * 8 + r8) * ROWB + (g8 >> 1) * 16;
    uint32_t bAddr = sb + A_BYTES + (wc + (g8 >> 1) * 8 + r8) * ROWB + (g8 & 1) * 16;

    float c[4][4][4];
#pragma unroll
    for (int mi = 0; mi < 4; mi++)
#pragma unroll
        for (int ni = 0; ni < 4; ni++)
#pragma unroll
            for (int q = 0; q < 4; q++) c[mi][ni][q] = 0.f;

    gemm_mainloop(aDst, bDst, aSrc, 16u, bSrc, HIDDEN / 64, aAddr, bAddr, c);

    const float* bb = b2 + (size_t)expert * NUM_CLS;
#pragma unroll
    for (int mi = 0; mi < 4; mi++) {
        int r0 = rowBase + wr + mi * 16 + gid;
#pragma unroll
        for (int half = 0; half < 2; half++) {
            int r = r0 + half * 8;
            int pair = g_permPair[r];
            if (pair < 0) continue;
            float gate = g_permGate[r];
            float* orow = out + (size_t)(pair >> 1) * NUM_CLS;
#pragma unroll
            for (int ni = 0; ni < 4; ni++) {
                int col = nBase + wc + ni * 8 + tig * 2;
                if (col < NUM_CLS)
                    atomicAdd(orow + col, gate * (c[mi][ni][half * 2 + 0] + __ldg(bb + col)));
                if (col + 1 < NUM_CLS)
                    atomicAdd(orow + col + 1, gate * (c[mi][ni][half * 2 + 1] + __ldg(bb + col + 1)));
            }
        }
    }
}

// ---------------- tail -------------------------------------------------------
__global__ void tail_kernel(float* __restrict__ out, int out_size) {
    int i = blockIdx.x * blockDim.x + threadIdx.x;
    const int OUT0 = BATCH * NUM_CLS;
    if (out_size >= OUT0 + BATCH * NUM_EXP) {
        if (i < BATCH * NUM_EXP)
            out[OUT0 + i] = g_gates[i];
        if (out_size >= OUT0 + BATCH * NUM_EXP + BATCH * TOPK && i < BATCH * TOPK)
            out[OUT0 + BATCH * NUM_EXP + i] = (float)g_topi[i];
    }
}

// ---------------------------------------------------------------------------
extern "C" void kernel_launch(void* const* d_in, const int* in_sizes, int n_in,
                              void* d_out, int out_size) {
    const float* x  = (const float*)d_in[0];
    const float* Wg = (const float*)d_in[1];
    const float* bg = (const float*)d_in[2];
    const float* W1 = (const float*)d_in[3];
    const float* b1 = (const float*)d_in[4];
    const float* W2 = (const float*)d_in[5];
    const float* b2 = (const float*)d_in[6];
    float* out = (float*)d_out;

    cudaFuncSetAttribute(gemm1_mma, cudaFuncAttributeMaxDynamicSharedMemorySize, SMEM_TOT);
    cudaFuncSetAttribute(gemm2_mma, cudaFuncAttributeMaxDynamicSharedMemorySize, SMEM_TOT);

    // ncu profiles launch index 4 -> gemm2_mma this round.
    cudaMemsetAsync(d_out, 0, (size_t)out_size * sizeof(float));             // 0
    prep_all<<<PREP_BLOCKS, 256>>>(x, Wg, bg, W1, W2);                       // 1
    scatter_kernel<<<(NPAIR + 255) / 256, 256>>>();                          // 2
    gemm1_mma<<<dim3(MAX_TILES, HIDDEN / 128), 256, SMEM_TOT>>>(b1);         // 3
    gemm2_mma<<<dim3(MAX_TILES, N2PAD / 128), 256, SMEM_TOT>>>(b2, out);     // 4 <- ncu
    tail_kernel<<<(BATCH * NUM_EXP + 255) / 256, 256>>>(out, out_size);      // 5
}

// round 14
// speedup vs baseline: 2.3488x; 1.0002x over previous
#include <cuda_runtime.h>
#include <cuda_fp16.h>
#include <math.h>
#include <stdint.h>

// ---------------------------------------------------------------------------
// MoE top-2/8: fp16 m16n8k16 mma.sync GEMMs (fp32 accum), ldmatrix fragments,
// BK=64, cp.async.cg, 3-stage single-sync pipeline, 256-thread CTAs (8 warps).
// gemm2 grid ordered nTile-fast so g_h tiles are L2-reused across nTiles.
// ---------------------------------------------------------------------------

#define BATCH      8192
#define D_MODEL    1024
#define HIDDEN     4096
#define NUM_CLS    1000
#define N2PAD      1024
#define NUM_EXP    8
#define TOPK       2
#define NPAIR      (BATCH * TOPK)
#define MAX_TILES  136
#define CAP        (MAX_TILES * 128)

#define RTR_BLOCKS (BATCH / 8)
#define T1_BLOCKS  (NUM_EXP * (D_MODEL/64) * (HIDDEN/64))   // 8192
#define T2_BLOCKS  (NUM_EXP * (HIDDEN/64) * (N2PAD/64))     // 8192
#define PREP_BLOCKS (RTR_BLOCKS + T1_BLOCKS + T2_BLOCKS)    // 17408

// ---------------- scratch ---------------------------------------------------
__device__ __half g_h[(size_t)CAP * HIDDEN];
__device__ __half g_xH[(size_t)BATCH * D_MODEL];
__device__ __half g_W1T[(size_t)NUM_EXP * HIDDEN * D_MODEL];    // [e][n][k]
__device__ __half g_W2T[(size_t)NUM_EXP * N2PAD * HIDDEN];      // [e][n][k]
__device__ float g_gates[BATCH * NUM_EXP];
__device__ int   g_topi[BATCH * TOPK];
__device__ int   g_pairExpert[NPAIR];
__device__ float g_pairGate[NPAIR];
__device__ int   g_counts[NUM_EXP];
__device__ int   g_segbase[NUM_EXP + 1];
__device__ int   g_cursor[NUM_EXP];
__device__ int   g_permToken[CAP];
__device__ int   g_permPair[CAP];
__device__ float g_permGate[CAP];
__device__ unsigned g_done;

__device__ __forceinline__ float gelu_exact(float v) {
    return 0.5f * v * (1.0f + erff(v * 0.70710678118654752f));
}
__device__ __forceinline__ uint32_t smem_u32(const void* p) {
    uint32_t a;
    asm("{ .reg .u64 t; cvta.to.shared.u64 t, %1; cvt.u32.u64 %0, t; }" : "=r"(a) : "l"(p));
    return a;
}

#define CPG16(dst, src)        asm volatile("cp.async.cg.shared.global [%0], [%1], 16;" :: "r"(dst), "l"(src))
#define CPG16_SZ(dst, src, sz) asm volatile("cp.async.cg.shared.global [%0], [%1], 16, %2;" :: "r"(dst), "l"(src), "r"(sz))
#define CPA_COMMIT()           asm volatile("cp.async.commit_group;" ::: "memory")
#define CPA_WAIT1()            asm volatile("cp.async.wait_group 1;" ::: "memory")
#define CPA_WAIT0()            asm volatile("cp.async.wait_group 0;" ::: "memory")

__device__ __forceinline__ void mma_f16(float* c, const uint32_t* a, uint32_t b0, uint32_t b1) {
    asm volatile("mma.sync.aligned.m16n8k16.row.col.f32.f16.f16.f32 "
                 "{%0,%1,%2,%3}, {%4,%5,%6,%7}, {%8,%9}, {%0,%1,%2,%3};"
                 : "+f"(c[0]), "+f"(c[1]), "+f"(c[2]), "+f"(c[3])
                 : "r"(a[0]), "r"(a[1]), "r"(a[2]), "r"(a[3]), "r"(b0), "r"(b1));
}
__device__ __forceinline__ void ldsm4(uint32_t* r, uint32_t addr) {
    asm volatile("ldmatrix.sync.aligned.m8n8.x4.shared.b16 {%0,%1,%2,%3}, [%4];"
                 : "=r"(r[0]), "=r"(r[1]), "=r"(r[2]), "=r"(r[3]) : "r"(addr));
}

// ---------------- L1: fused prep (router || transposes) ---------------------
__global__ void prep_all(const float* __restrict__ x,
                         const float* __restrict__ Wg,
                         const float* __restrict__ bg,
                         const float* __restrict__ W1,
                         const float* __restrict__ W2) {
    __shared__ float t[64][65];
    const int bid = blockIdx.x, tid = threadIdx.x;

    if (bid < RTR_BLOCKS) {
        size_t tid0 = (size_t)bid * blockDim.x + tid;
        size_t nthr = (size_t)RTR_BLOCKS * blockDim.x;
        if (tid0 < CAP) { g_permToken[tid0] = -1; g_permPair[tid0] = -1; }
        if (tid0 < NUM_EXP) g_counts[tid0] = 0;

        int gwarp = (int)(tid0 >> 5);
        int lane  = tid & 31;
        const float* xr = x + (size_t)gwarp * D_MODEL;
        float acc[NUM_EXP];
#pragma unroll
        for (int e = 0; e < NUM_EXP; e++) acc[e] = 0.f;
        for (int k0 = lane * 4; k0 < D_MODEL; k0 += 128) {
            float4 xv = *(const float4*)(xr + k0);
            const float* xs = (const float*)&xv;
#pragma unroll
            for (int kk = 0; kk < 4; kk++) {
                const float4* wg = (const float4*)(Wg + (size_t)(k0 + kk) * NUM_EXP);
                float4 w0 = wg[0], w1 = wg[1];
                float xk = xs[kk];
                acc[0] += xk * w0.x; acc[1] += xk * w0.y;
                acc[2] += xk * w0.z; acc[3] += xk * w0.w;
                acc[4] += xk * w1.x; acc[5] += xk * w1.y;
                acc[6] += xk * w1.z; acc[7] += xk * w1.w;
            }
        }
#pragma unroll
        for (int off = 16; off; off >>= 1)
#pragma unroll
            for (int e = 0; e < NUM_EXP; e++)
                acc[e] += __shfl_xor_sync(0xFFFFFFFFu, acc[e], off);
        if (lane == 0) {
            float v[NUM_EXP];
#pragma unroll
            for (int e = 0; e < NUM_EXP; e++) v[e] = acc[e] + bg[e];
            int i1 = 0;
#pragma unroll
            for (int e = 1; e < NUM_EXP; e++) if (v[e] > v[i1]) i1 = e;
            int i2 = -1;
#pragma unroll
            for (int e = 0; e < NUM_EXP; e++)
                if (e != i1 && (i2 < 0 || v[e] > v[i2])) i2 = e;
            float e2 = expf(v[i2] - v[i1]);
            float g1 = 1.f / (1.f + e2), g2 = e2 / (1.f + e2);
#pragma unroll
            for (int e = 0; e < NUM_EXP; e++) g_gates[gwarp * NUM_EXP + e] = 0.f;
            g_gates[gwarp * NUM_EXP + i1] = g1;
            g_gates[gwarp * NUM_EXP + i2] = g2;
            g_topi[gwarp * TOPK + 0] = i1;
            g_topi[gwarp * TOPK + 1] = i2;
            g_pairExpert[gwarp * TOPK + 0] = i1;
            g_pairExpert[gwarp * TOPK + 1] = i2;
            g_pairGate[gwarp * TOPK + 0] = g1;
            g_pairGate[gwarp * TOPK + 1] = g2;
            atomicAdd(&g_counts[i1], 1);
            atomicAdd(&g_counts[i2], 1);
        }

        for (size_t i = tid0; i < (size_t)BATCH * D_MODEL / 4; i += nthr) {
            float4 v = ((const float4*)x)[i];
            ((__half2*)g_xH)[i * 2]     = __floats2half2_rn(v.x, v.y);
            ((__half2*)g_xH)[i * 2 + 1] = __floats2half2_rn(v.z, v.w);
        }

        __syncthreads();
        if (tid == 0) {
            __threadfence();
            unsigned ticket = atomicAdd(&g_done, 1u);
            if (ticket == RTR_BLOCKS - 1) {
                int base = 0;
#pragma unroll
                for (int e = 0; e < NUM_EXP; e++) {
                    g_segbase[e] = base;
                    g_cursor[e]  = base;
                    base += ((g_counts[e] + 127) >> 7) << 7;
                }
                g_segbase[NUM_EXP] = base;
                g_done = 0;
                __threadfence();
            }
        }
        return;
    }

    const int tx = tid & 63, ty4 = tid >> 6;
    int idx = bid - RTR_BLOCKS;
    if (idx < T1_BLOCKS) {
        int e  = idx >> 10;
        int tt = idx & 1023;
        int kB = (tt & 15) * 64;
        int nB = (tt >> 4) * 64;
        const float* src = W1 + (size_t)e * D_MODEL * HIDDEN;
        __half* dst = g_W1T + (size_t)e * HIDDEN * D_MODEL;
#pragma unroll
        for (int i = 0; i < 16; i++) {
            int r = ty4 + i * 4;
            t[r][tx] = src[(size_t)(kB + r) * HIDDEN + nB + tx];
        }
        __syncthreads();
#pragma unroll
        for (int i = 0; i < 16; i++) {
            int r = ty4 + i * 4;
            dst[(size_t)(nB + r) * D_MODEL + kB + tx] = __float2half_rn(t[tx][r]);
        }
    } else {
        idx -= T1_BLOCKS;
        int e  = idx >> 10;
        int tt = idx & 1023;
        int kB = (tt & 63) * 64;
        int nB = (tt >> 6) * 64;
        const float* src = W2 + (size_t)e * HIDDEN * NUM_CLS;
        __half* dst = g_W2T + (size_t)e * N2PAD * HIDDEN;
        int n = nB + tx;
#pragma unroll
        for (int i = 0; i < 16; i++) {
            int r = ty4 + i * 4;
            t[r][tx] = (n < NUM_CLS) ? src[(size_t)(kB + r) * NUM_CLS + n] : 0.f;
        }
        __syncthreads();
#pragma unroll
        for (int i = 0; i < 16; i++) {
            int r = ty4 + i * 4;
            dst[(size_t)(nB + r) * HIDDEN + kB + tx] = __float2half_rn(t[tx][r]);
        }
    }
}

// ---------------- L2: scatter ------------------------------------------------
__global__ void scatter_kernel() {
    int p = blockIdx.x * blockDim.x + threadIdx.x;
    if (p >= NPAIR) return;
    int e = g_pairExpert[p];
    int pos = atomicAdd(&g_cursor[e], 1);
    g_permToken[pos] = p >> 1;
    g_permPair[pos]  = p;
    g_permGate[pos]  = g_pairGate[p];
}

// ---------------- fp16 mma GEMMs --------------------------------------------
#define ROWB      144
#define A_BYTES   (128 * ROWB)
#define B_BYTES   (128 * ROWB)
#define STAGE_B   (A_BYTES + B_BYTES)
#define NSTAGE    3
#define SMEM_TOT  (NSTAGE * STAGE_B)               // 110592

__device__ __forceinline__ void issue_chunk(
    uint32_t aDst, uint32_t bDst,
    const __half* aSrc, uint32_t aSz, const __half* bSrc, int kt)
{
#pragma unroll
    for (int j = 0; j < 4; j++)
        CPG16_SZ(aDst + j * 16, aSrc + kt + j * 8, aSz);
#pragma unroll
    for (int j = 0; j < 4; j++)
        CPG16(bDst + j * 16, bSrc + kt + j * 8);
    CPA_COMMIT();
}

__device__ __forceinline__ void mma_tile(uint32_t aAddr, uint32_t bAddr,
                                         float c[4][4][4]) {
#pragma unroll
    for (int ks = 0; ks < 4; ks++) {
        uint32_t a[4][4], b[2][4];
#pragma unroll
        for (int mi = 0; mi < 4; mi++)
            ldsm4(a[mi], aAddr + mi * (16 * ROWB) + ks * 32);
#pragma unroll
        for (int n2 = 0; n2 < 2; n2++)
            ldsm4(b[n2], bAddr + n2 * (16 * ROWB) + ks * 32);
#pragma unroll
        for (int mi = 0; mi < 4; mi++)
#pragma unroll
            for (int n2 = 0; n2 < 2; n2++) {
                mma_f16(c[mi][2 * n2],     a[mi], b[n2][0], b[n2][1]);
                mma_f16(c[mi][2 * n2 + 1], a[mi], b[n2][2], b[n2][3]);
            }
    }
}

__device__ __forceinline__ void gemm_mainloop(
    uint32_t aDst, uint32_t bDst,
    const __half* aSrc, uint32_t aSz, const __half* bSrc, int NIT,
    uint32_t aAddr, uint32_t bAddr, float c[4][4][4])
{
    issue_chunk(aDst, bDst, aSrc, aSz, bSrc, 0);
    issue_chunk(aDst + STAGE_B, bDst + STAGE_B, aSrc, aSz, bSrc, 64);
    int buf = 0, nxt = 2;
    for (int it = 0; it < NIT; ++it) {
        if (it + 1 < NIT) CPA_WAIT1(); else CPA_WAIT0();
        __syncthreads();
        if (it + 2 < NIT)
            issue_chunk(aDst + nxt * STAGE_B, bDst + nxt * STAGE_B,
                        aSrc, aSz, bSrc, (it + 2) * 64);
        mma_tile(aAddr + buf * STAGE_B, bAddr + buf * STAGE_B, c);
        buf = (buf == NSTAGE - 1) ? 0 : buf + 1;
        nxt = (nxt == NSTAGE - 1) ? 0 : nxt + 1;
    }
}

__global__ __launch_bounds__(256, 2)
void gemm1_mma(const float* __restrict__ b1) {
    extern __shared__ __align__(16) char smem[];
    const int tid = threadIdx.x, wid = tid >> 5, lane = tid & 31;
    const int rowBase = blockIdx.x * 128, nBase = blockIdx.y * 128;
    if (rowBase >= g_segbase[NUM_EXP]) return;
    int expert = 0;
#pragma unroll
    for (int i = 1; i < NUM_EXP; i++) if (g_segbase[i] <= rowBase) expert = i;

    uint32_t sb = smem_u32(smem);
    const int cr = tid >> 1, co = (tid & 1) * 32;
    uint32_t aDst = sb + cr * ROWB + co * 2;
    uint32_t bDst = sb + A_BYTES + cr * ROWB + co * 2;

    const int tok = g_permToken[rowBase + cr];
    const __half* aSrc = g_xH + (size_t)(tok < 0 ? 0 : tok) * D_MODEL + co;
    uint32_t aSz = tok < 0 ? 0u : 16u;
    const __half* bSrc = g_W1T + (size_t)expert * HIDDEN * D_MODEL
                       + (size_t)(nBase + cr) * D_MODEL + co;

    const int gid = lane >> 2, tig = lane & 3;
    const int wr = (wid >> 2) * 64, wc = (wid & 3) * 32;
    const int g8 = lane >> 3, r8 = lane & 7;
    uint32_t aAddr = sb + (wr + (g8 & 1) * 8 + r8) * ROWB + (g8 >> 1) * 16;
    uint32_t bAddr = sb + A_BYTES + (wc + (g8 >> 1) * 8 + r8) * ROWB + (g8 & 1) * 16;

    float c[4][4][4];
#pragma unroll
    for (int mi = 0; mi < 4; mi++)
#pragma unroll
        for (int ni = 0; ni < 4; ni++)
#pragma unroll
            for (int q = 0; q < 4; q++) c[mi][ni][q] = 0.f;

    gemm_mainloop(aDst, bDst, aSrc, aSz, bSrc, D_MODEL / 64, aAddr, bAddr, c);

    const float* bb = b1 + (size_t)expert * HIDDEN + nBase;
#pragma unroll
    for (int mi = 0; mi < 4; mi++) {
        int r0 = rowBase + wr + mi * 16 + gid;
#pragma unroll
        for (int ni = 0; ni < 4; ni++) {
            int col = wc + ni * 8 + tig * 2;
            float bias0 = __ldg(bb + col), bias1 = __ldg(bb + col + 1);
            __half2 v0 = __floats2half2_rn(gelu_exact(c[mi][ni][0] + bias0),
                                           gelu_exact(c[mi][ni][1] + bias1));
            __half2 v1 = __floats2half2_rn(gelu_exact(c[mi][ni][2] + bias0),
                                           gelu_exact(c[mi][ni][3] + bias1));
            *(__half2*)(g_h + (size_t)r0 * HIDDEN + nBase + col) = v0;
            *(__half2*)(g_h + (size_t)(r0 + 8) * HIDDEN + nBase + col) = v1;
        }
    }
}

// grid = (nTiles fast, rowTiles): CTAs sharing rowBase are adjacent so the
// g_h A-tile is fetched from DRAM once and L2-served for the other 7 nTiles.
__global__ __launch_bounds__(256, 2)
void gemm2_mma(const float* __restrict__ b2, float* __restrict__ out) {
    extern __shared__ __align__(16) char smem[];
    const int tid = threadIdx.x, wid = tid >> 5, lane = tid & 31;
    const int rowBase = blockIdx.y * 128, nBase = blockIdx.x * 128;
    if (rowBase >= g_segbase[NUM_EXP]) return;
    int expert = 0;
#pragma unroll
    for (int i = 1; i < NUM_EXP; i++) if (g_segbase[i] <= rowBase) expert = i;

    uint32_t sb = smem_u32(smem);
    const int cr = tid >> 1, co = (tid & 1) * 32;
    uint32_t aDst = sb + cr * ROWB + co * 2;
    uint32_t bDst = sb + A_BYTES + cr * ROWB + co * 2;

    const __half* aSrc = g_h + (size_t)(rowBase + cr) * HIDDEN + co;
    const __half* bSrc = g_W2T + (size_t)expert * N2PAD * HIDDEN
                       + (size_t)(nBase + cr) * HIDDEN + co;

    const int gid = lane >> 2, tig = lane & 3;
    const int wr = (wid >> 2) * 64, wc = (wid & 3) * 32;
    const int g8 = lane >> 3, r8 = lane & 7;
    uint32_t aAddr = sb + (wr + (g8 & 1) * 8 + r8) * ROWB + (g8 >> 1) * 16;
    uint32_t bAddr = sb + A_BYTES + (wc + (g8 >> 1) * 8 + r8) * ROWB + (g8 & 1) * 16;

    float c[4][4][4];
#pragma unroll
    for (int mi = 0; mi < 4; mi++)
#pragma unroll
        for (int ni = 0; ni < 4; ni++)
#pragma unroll
            for (int q = 0; q < 4; q++) c[mi][ni][q] = 0.f;

    gemm_mainloop(aDst, bDst, aSrc, 16u, bSrc, HIDDEN / 64, aAddr, bAddr, c);

    const float* bb = b2 + (size_t)expert * NUM_CLS;
#pragma unroll
    for (int mi = 0; mi < 4; mi++) {
        int r0 = rowBase + wr + mi * 16 + gid;
#pragma unroll
        for (int half = 0; half < 2; half++) {
            int r = r0 + half * 8;
            int pair = g_permPair[r];
            if (pair < 0) continue;
            float gate = g_permGate[r];
            float* orow = out + (size_t)(pair >> 1) * NUM_CLS;
#pragma unroll
            for (int ni = 0; ni < 4; ni++) {
                int col = nBase + wc + ni * 8 + tig * 2;
                if (col < NUM_CLS)
                    atomicAdd(orow + col, gate * (c[mi][ni][half * 2 + 0] + __ldg(bb + col)));
                if (col + 1 < NUM_CLS)
                    atomicAdd(orow + col + 1, gate * (c[mi][ni][half * 2 + 1] + __ldg(bb + col + 1)));
            }
        }
    }
}

// ---------------- tail -------------------------------------------------------
__global__ void tail_kernel(float* __restrict__ out, int out_size) {
    int i = blockIdx.x * blockDim.x + threadIdx.x;
    const int OUT0 = BATCH * NUM_CLS;
    if (out_size >= OUT0 + BATCH * NUM_EXP) {
        if (i < BATCH * NUM_EXP)
            out[OUT0 + i] = g_gates[i];
        if (out_size >= OUT0 + BATCH * NUM_EXP + BATCH * TOPK && i < BATCH * TOPK)
            out[OUT0 + BATCH * NUM_EXP + i] = (float)g_topi[i];
    }
}

// ---------------------------------------------------------------------------
extern "C" void kernel_launch(void* const* d_in, const int* in_sizes, int n_in,
                              void* d_out, int out_size) {
    const float* x  = (const float*)d_in[0];
    const float* Wg = (const float*)d_in[1];
    const float* bg = (const float*)d_in[2];
    const float* W1 = (const float*)d_in[3];
    const float* b1 = (const float*)d_in[4];
    const float* W2 = (const float*)d_in[5];
    const float* b2 = (const float*)d_in[6];
    float* out = (float*)d_out;

    cudaFuncSetAttribute(gemm1_mma, cudaFuncAttributeMaxDynamicSharedMemorySize, SMEM_TOT);
    cudaFuncSetAttribute(gemm2_mma, cudaFuncAttributeMaxDynamicSharedMemorySize, SMEM_TOT);

    // ncu profiles launch index 4 -> gemm2_mma.
    cudaMemsetAsync(d_out, 0, (size_t)out_size * sizeof(float));             // 0
    prep_all<<<PREP_BLOCKS, 256>>>(x, Wg, bg, W1, W2);                       // 1
    scatter_kernel<<<(NPAIR + 255) / 256, 256>>>();                          // 2
    gemm1_mma<<<dim3(MAX_TILES, HIDDEN / 128), 256, SMEM_TOT>>>(b1);         // 3
    gemm2_mma<<<dim3(N2PAD / 128, MAX_TILES), 256, SMEM_TOT>>>(b2, out);     // 4 <- ncu
    tail_kernel<<<(BATCH * NUM_EXP + 255) / 256, 256>>>(out, out_size);      // 5
}